// round 3
// baseline (speedup 1.0000x reference)
#include <cuda_runtime.h>

#define Sn 512
#define Bn 64
#define En 256
#define Hn 128
#define G4H 512
#define Tn 128
#define Cv 32000

// ---------------- scratch (static device globals; no allocation) ----------------
__device__ float g_xpre[2][Sn][Bn][G4H];     // precomputed x@Wih^T + biases (134MB)
__device__ float g_hs[Sn][Bn][2*Hn];         // encoder outputs (concat fwd|bwd)
__device__ float g_wahs[Sn][Bn][Hn];         // w_a @ h_s precompute
__device__ float g_e[Bn][Sn];                // attention scores per step
__device__ float g_vas[Bn][Hn];              // v_a @ s
__device__ float g_s[Bn][Hn];                // decoder hidden
__device__ float g_y[Bn][Hn];                // decoder cell
__device__ float g_ctx_part[4][Bn][2*Hn];    // partial ctx (S split in 4)
__device__ float g_ctx[Bn][2*Hn];            // full ctx (for final logits)
__device__ float g_gates[Bn][G4H];           // decoder gates scratch
__device__ float g_rowstat[Bn][2];           // softmax max, 1/sum

__device__ __forceinline__ float sigf(float x) { return 1.f / (1.f + __expf(-x)); }
__device__ __forceinline__ float tanh_fast(float x) {
    float y; asm("tanh.approx.f32 %0, %1;" : "=f"(y) : "f"(x)); return y;
}

// ---------------- generic fp32 GEMM: C[M,N] = A[M,K] @ B[N,K]^T (+bias1+bias2) (+=C) ----
// BM=BN=64, BK=16, 256 threads, 4x4 microtile. All dims are exact multiples here.
__global__ void gemm_nt(const float* __restrict__ A, const float* __restrict__ B,
                        float* __restrict__ C, int M, int N, int K,
                        const float* __restrict__ bias1, const float* __restrict__ bias2,
                        int accumulate)
{
    __shared__ __align__(16) float As[16][64];
    __shared__ __align__(16) float Bs[16][64];
    int tid = threadIdx.x;
    int tx = tid & 15, ty = tid >> 4;
    int n0 = blockIdx.x * 64, m0 = blockIdx.y * 64;
    float acc[4][4] = {};

    for (int k0 = 0; k0 < K; k0 += 16) {
#pragma unroll
        for (int q = 0; q < 4; q++) {
            int idx = tid + q * 256;
            int kk = idx & 15, m = idx >> 4;
            As[kk][m] = A[(m0 + m) * K + k0 + kk];
            Bs[kk][m] = B[(n0 + m) * K + k0 + kk];
        }
        __syncthreads();
#pragma unroll
        for (int kk = 0; kk < 16; kk++) {
            float4 a4 = *reinterpret_cast<const float4*>(&As[kk][ty * 4]);
            float4 b4 = *reinterpret_cast<const float4*>(&Bs[kk][tx * 4]);
            float av[4] = {a4.x, a4.y, a4.z, a4.w};
            float bv[4] = {b4.x, b4.y, b4.z, b4.w};
#pragma unroll
            for (int i = 0; i < 4; i++)
#pragma unroll
                for (int j = 0; j < 4; j++)
                    acc[i][j] += av[i] * bv[j];
        }
        __syncthreads();
    }
#pragma unroll
    for (int i = 0; i < 4; i++) {
        int row = m0 + ty * 4 + i;
#pragma unroll
        for (int j = 0; j < 4; j++) {
            int col = n0 + tx * 4 + j;
            float v = acc[i][j];
            if (bias1) v += bias1[col];
            if (bias2) v += bias2[col];
            if (accumulate) v += C[row * N + col];
            C[row * N + col] = v;
        }
    }
}

// ---------------- encoder recurrence: one CTA per (batch, direction), 512 steps ------
__global__ void encoder_rec(const float* __restrict__ Whh_f, const float* __restrict__ Whh_b)
{
    int b = blockIdx.x, dir = blockIdx.y;
    const float* Whh = dir ? Whh_b : Whh_f;
    __shared__ __align__(16) float h_sm[Hn];
    __shared__ float c_sm[Hn];
    __shared__ float gate_sm[G4H];
    int tid = threadIdx.x;  // 512
    if (tid < Hn) { h_sm[tid] = 0.f; c_sm[tid] = 0.f; }
    __syncthreads();

    const float4* __restrict__ w4 = reinterpret_cast<const float4*>(Whh + tid * Hn);
    const float4* h4 = reinterpret_cast<const float4*>(h_sm);

    for (int step = 0; step < Sn; step++) {
        int t = dir ? (Sn - 1 - step) : step;
        float a0 = 0.f, a1 = 0.f, a2 = 0.f, a3 = 0.f;
#pragma unroll
        for (int k = 0; k < 32; k += 4) {
            float4 w0 = __ldg(&w4[k + 0]); float4 h0 = h4[k + 0];
            float4 w1 = __ldg(&w4[k + 1]); float4 h1 = h4[k + 1];
            float4 w2 = __ldg(&w4[k + 2]); float4 h2 = h4[k + 2];
            float4 w3 = __ldg(&w4[k + 3]); float4 h3 = h4[k + 3];
            a0 += w0.x * h0.x + w0.y * h0.y + w0.z * h0.z + w0.w * h0.w;
            a1 += w1.x * h1.x + w1.y * h1.y + w1.z * h1.z + w1.w * h1.w;
            a2 += w2.x * h2.x + w2.y * h2.y + w2.z * h2.z + w2.w * h2.w;
            a3 += w3.x * h3.x + w3.y * h3.y + w3.z * h3.z + w3.w * h3.w;
        }
        float acc = g_xpre[dir][t][b][tid] + ((a0 + a1) + (a2 + a3));
        gate_sm[tid] = acc;
        __syncthreads();
        if (tid < Hn) {
            float gi = gate_sm[tid], gf = gate_sm[tid + 128];
            float gg = gate_sm[tid + 256], go = gate_sm[tid + 384];
            float c = sigf(gf) * c_sm[tid] + sigf(gi) * tanhf(gg);
            float h = sigf(go) * tanhf(c);
            c_sm[tid] = c; h_sm[tid] = h;
            g_hs[t][b][dir * Hn + tid] = h;
        }
        __syncthreads();
    }
}

// ---------------- decoder init -------------------------------------------------------
__global__ void dec_init()
{
    int i = blockIdx.x * 256 + threadIdx.x;
    if (i < Bn * Hn) {
        (&g_s[0][0])[i] = 0.f;
        (&g_y[0][0])[i] = 0.f;
        (&g_vas[0][0])[i] = 0.f;
    }
}

// ---------------- decoder: attention scores e[b][s] ----------------------------------
// 512 blocks x 256 threads; one warp per (s,b) pair, 8 pairs per warp.
__global__ void dec_scores(const float* __restrict__ ua, const float* __restrict__ mask)
{
    int warp = threadIdx.x >> 5, lane = threadIdx.x & 31;
    float4 u = reinterpret_cast<const float4*>(ua)[lane];
#pragma unroll
    for (int rep = 0; rep < 8; rep++) {
        int p = rep * 4096 + blockIdx.x * 8 + warp;      // 0..32767
        int s = p >> 6, b = p & 63;
        float4 a = reinterpret_cast<const float4*>(&g_wahs[s][b][0])[lane];
        float4 v = reinterpret_cast<const float4*>(&g_vas[b][0])[lane];
        float e = tanh_fast(a.x + v.x) * u.x + tanh_fast(a.y + v.y) * u.y +
                  tanh_fast(a.z + v.z) * u.z + tanh_fast(a.w + v.w) * u.w;
#pragma unroll
        for (int off = 16; off; off >>= 1) e += __shfl_xor_sync(0xFFFFFFFFu, e, off);
        if (lane == 0) g_e[b][s] = e * mask[s * Bn + b];
    }
}

// ---------------- decoder: softmax over S + partial ctx ------------------------------
// grid (4 s-chunks, 64 b), 256 threads
__global__ void dec_softctx()
{
    int chunk = blockIdx.x, b = blockIdx.y;
    int tid = threadIdx.x;
    __shared__ float w[Sn];
    __shared__ float red[256];

    float v0 = g_e[b][tid], v1 = g_e[b][tid + 256];
    red[tid] = fmaxf(v0, v1);
    __syncthreads();
#pragma unroll
    for (int st = 128; st; st >>= 1) {
        if (tid < st) red[tid] = fmaxf(red[tid], red[tid + st]);
        __syncthreads();
    }
    float m = red[0];
    __syncthreads();
    float e0 = __expf(v0 - m), e1 = __expf(v1 - m);
    w[tid] = e0; w[tid + 256] = e1;
    red[tid] = e0 + e1;
    __syncthreads();
#pragma unroll
    for (int st = 128; st; st >>= 1) {
        if (tid < st) red[tid] += red[tid + st];
        __syncthreads();
    }
    float inv = 1.f / red[0];

    float acc = 0.f;
    int s0 = chunk * 128;
    const float* hp = &g_hs[s0][b][tid];   // stride between s: 64*256 floats
#pragma unroll 4
    for (int s = 0; s < 128; s++)
        acc += w[s0 + s] * hp[s * (Bn * 2 * Hn)];
    g_ctx_part[chunk][b][tid] = acc * inv;
}

// ---------------- decoder: gates = ctx@Wih^T + s@Whh^T + biases ----------------------
// grid (8 gate-slices, 8 batch-groups), 512 threads
__global__ void dec_gates(const float* __restrict__ Wih, const float* __restrict__ Whh,
                          const float* __restrict__ bih, const float* __restrict__ bhh)
{
    __shared__ float sc[8][388];    // [batch][ s(128) | ctx(256) ], padded
    int bx = blockIdx.x, by = blockIdx.y;
    int tid = threadIdx.x;
    int b0 = by * 8;
    for (int idx = tid; idx < 8 * 384; idx += 512) {
        int bb = idx / 384, kk = idx - bb * 384;
        int b = b0 + bb;
        float v;
        if (kk < 128) v = g_s[b][kk];
        else {
            int k2 = kk - 128;
            v = g_ctx_part[0][b][k2] + g_ctx_part[1][b][k2] +
                g_ctx_part[2][b][k2] + g_ctx_part[3][b][k2];
            if (bx == 0) g_ctx[b][k2] = v;
        }
        sc[bb][kk] = v;
    }
    __syncthreads();

    int gi = tid >> 3, bb = tid & 7;
    int gg = bx * 64 + gi, b = b0 + bb;
    float acc = bih[gg] + bhh[gg];
    const float* ws = Whh + gg * Hn;
    const float* wc = Wih + gg * 2 * Hn;
#pragma unroll 4
    for (int k = 0; k < 128; k++) acc += ws[k] * sc[bb][k];
#pragma unroll 4
    for (int k = 0; k < 256; k++) acc += wc[k] * sc[bb][128 + k];
    g_gates[b][gg] = acc;
}

// ---------------- decoder: LSTM cell + v_a @ s_new for next step ---------------------
__global__ void dec_cell(const float* __restrict__ va)
{
    int b = blockIdx.x, j = threadIdx.x;   // 64 blocks x 128 threads
    __shared__ float s_sm[Hn];
    float gi = g_gates[b][j],       gf = g_gates[b][j + 128];
    float gg = g_gates[b][j + 256], go = g_gates[b][j + 384];
    float y = sigf(gf) * g_y[b][j] + sigf(gi) * tanhf(gg);
    float s = sigf(go) * tanhf(y);
    g_y[b][j] = y; g_s[b][j] = s; s_sm[j] = s;
    __syncthreads();
    float acc = 0.f;
    const float* vr = va + j * Hn;
#pragma unroll 4
    for (int k = 0; k < 128; k++) acc += vr[k] * s_sm[k];
    g_vas[b][j] = acc;
}

// ---------------- final softmax over C=32000 -----------------------------------------
__global__ void softmax_stat(const float* __restrict__ out)
{
    int b = blockIdx.x, tid = threadIdx.x;
    __shared__ float red[256];
    const float* row = out + b * Cv;
    float m = -1e30f;
    for (int i = tid; i < Cv; i += 256) m = fmaxf(m, row[i]);
    red[tid] = m; __syncthreads();
#pragma unroll
    for (int st = 128; st; st >>= 1) {
        if (tid < st) red[tid] = fmaxf(red[tid], red[tid + st]);
        __syncthreads();
    }
    m = red[0]; __syncthreads();
    float s = 0.f;
    for (int i = tid; i < Cv; i += 256) s += __expf(row[i] - m);
    red[tid] = s; __syncthreads();
#pragma unroll
    for (int st = 128; st; st >>= 1) {
        if (tid < st) red[tid] += red[tid + st];
        __syncthreads();
    }
    if (tid == 0) { g_rowstat[b][0] = m; g_rowstat[b][1] = 1.f / red[0]; }
}

__global__ void softmax_norm(float* out)
{
    int idx = blockIdx.x * 256 + threadIdx.x;   // < 64*32000 exactly
    int b = idx / Cv;
    out[idx] = __expf(out[idx] - g_rowstat[b][0]) * g_rowstat[b][1];
}

// ---------------- launch -------------------------------------------------------------
extern "C" void kernel_launch(void* const* d_in, const int* in_sizes, int n_in,
                              void* d_out, int out_size)
{
    (void)in_sizes; (void)n_in; (void)out_size;
    const float* x      = (const float*)d_in[0];
    const float* mask   = (const float*)d_in[1];
    const float* eWih_f = (const float*)d_in[2];
    const float* eWhh_f = (const float*)d_in[3];
    const float* ebih_f = (const float*)d_in[4];
    const float* ebhh_f = (const float*)d_in[5];
    const float* eWih_b = (const float*)d_in[6];
    const float* eWhh_b = (const float*)d_in[7];
    const float* ebih_b = (const float*)d_in[8];
    const float* ebhh_b = (const float*)d_in[9];
    const float* dWih   = (const float*)d_in[10];
    const float* dWhh   = (const float*)d_in[11];
    const float* dbih   = (const float*)d_in[12];
    const float* dbhh   = (const float*)d_in[13];
    const float* w_a    = (const float*)d_in[14];
    const float* v_a    = (const float*)d_in[15];
    const float* u_a    = (const float*)d_in[16];
    const float* w_b    = (const float*)d_in[17];
    const float* v_b    = (const float*)d_in[18];
    float* out = (float*)d_out;

    float *p_xpre, *p_hs, *p_wahs, *p_s, *p_ctx;
    cudaGetSymbolAddress((void**)&p_xpre, g_xpre);
    cudaGetSymbolAddress((void**)&p_hs,   g_hs);
    cudaGetSymbolAddress((void**)&p_wahs, g_wahs);
    cudaGetSymbolAddress((void**)&p_s,    g_s);
    cudaGetSymbolAddress((void**)&p_ctx,  g_ctx);

    // 1) precompute x @ Wih^T + biases for both directions  (M=32768, N=512, K=256)
    gemm_nt<<<dim3(8, 512), 256>>>(x, eWih_f, p_xpre,                 Sn * Bn, G4H, En, ebih_f, ebhh_f, 0);
    gemm_nt<<<dim3(8, 512), 256>>>(x, eWih_b, p_xpre + Sn * Bn * G4H, Sn * Bn, G4H, En, ebih_b, ebhh_b, 0);

    // 2) encoder recurrence (128 independent CTAs)
    encoder_rec<<<dim3(Bn, 2), 512>>>(eWhh_f, eWhh_b);

    // 3) wa_hs = h_s @ w_a^T  (M=32768, N=128, K=256)
    gemm_nt<<<dim3(2, 512), 256>>>(p_hs, w_a, p_wahs, Sn * Bn, Hn, 2 * Hn, nullptr, nullptr, 0);

    // 4) decoder loop
    dec_init<<<32, 256>>>();
    for (int t = 0; t < Tn; t++) {
        dec_scores<<<512, 256>>>(u_a, mask);
        dec_softctx<<<dim3(4, Bn), 256>>>();
        dec_gates<<<dim3(8, 8), 512>>>(dWih, dWhh, dbih, dbhh);
        dec_cell<<<Bn, Hn>>>(v_a);
    }

    // 5) logits = s @ w_b^T + ctx @ v_b^T  into d_out, then softmax
    gemm_nt<<<dim3(Cv / 64, 1), 256>>>(p_s,   w_b, out, Bn, Cv, Hn,     nullptr, nullptr, 0);
    gemm_nt<<<dim3(Cv / 64, 1), 256>>>(p_ctx, v_b, out, Bn, Cv, 2 * Hn, nullptr, nullptr, 1);
    softmax_stat<<<Bn, 256>>>(out);
    softmax_norm<<<(Bn * Cv) / 256, 256>>>(out);
}

// round 4
// speedup vs baseline: 1.3195x; 1.3195x over previous
#include <cuda_runtime.h>

#define Sn 512
#define Bn 64
#define En 256
#define Hn 128
#define G4H 512
#define Tn 128
#define Cv 32000
#define NCTA 64

// ---------------- scratch (static device globals; no allocation) ----------------
__device__ float g_xpre[2][Sn][Bn][G4H];     // precomputed x@Wih^T + biases
__device__ float g_hs[Sn][Bn][2*Hn];         // encoder outputs (concat fwd|bwd)
__device__ float g_hsT[Bn][2*Hn][Sn];        // transposed: per-b, j-major, s-contiguous
__device__ float g_wahs[Sn][Bn][Hn];         // w_a @ h_s precompute
__device__ float g_sbuf[2][Bn][Hn];          // decoder hidden, double-buffered
__device__ float g_ctx[Bn][2*Hn];            // ctx per step (and final)
__device__ float g_rowstat[Bn][2];           // softmax max, 1/sum
__device__ unsigned g_bar_cnt;
__device__ unsigned g_bar_gen;

__device__ __forceinline__ float sigf(float x) { return 1.f / (1.f + __expf(-x)); }
__device__ __forceinline__ float tanh_fast(float x) {
    float y; asm("tanh.approx.f32 %0, %1;" : "=f"(y) : "f"(x)); return y;
}
__device__ __forceinline__ float wred(float v) {
#pragma unroll
    for (int o = 16; o; o >>= 1) v += __shfl_xor_sync(0xFFFFFFFFu, v, o);
    return v;
}

// ---------------- generic fp32 GEMM: C[M,N] = A[M,K] @ B[N,K]^T (+bias1+bias2) (+=C) ----
__global__ void gemm_nt(const float* __restrict__ A, const float* __restrict__ B,
                        float* __restrict__ C, int M, int N, int K,
                        const float* __restrict__ bias1, const float* __restrict__ bias2,
                        int accumulate)
{
    __shared__ __align__(16) float As[16][64];
    __shared__ __align__(16) float Bs[16][64];
    int tid = threadIdx.x;
    int tx = tid & 15, ty = tid >> 4;
    int n0 = blockIdx.x * 64, m0 = blockIdx.y * 64;
    float acc[4][4] = {};

    for (int k0 = 0; k0 < K; k0 += 16) {
#pragma unroll
        for (int q = 0; q < 4; q++) {
            int idx = tid + q * 256;
            int kk = idx & 15, m = idx >> 4;
            As[kk][m] = A[(m0 + m) * K + k0 + kk];
            Bs[kk][m] = B[(n0 + m) * K + k0 + kk];
        }
        __syncthreads();
#pragma unroll
        for (int kk = 0; kk < 16; kk++) {
            float4 a4 = *reinterpret_cast<const float4*>(&As[kk][ty * 4]);
            float4 b4 = *reinterpret_cast<const float4*>(&Bs[kk][tx * 4]);
            float av[4] = {a4.x, a4.y, a4.z, a4.w};
            float bv[4] = {b4.x, b4.y, b4.z, b4.w};
#pragma unroll
            for (int i = 0; i < 4; i++)
#pragma unroll
                for (int j = 0; j < 4; j++)
                    acc[i][j] += av[i] * bv[j];
        }
        __syncthreads();
    }
#pragma unroll
    for (int i = 0; i < 4; i++) {
        int row = m0 + ty * 4 + i;
#pragma unroll
        for (int j = 0; j < 4; j++) {
            int col = n0 + tx * 4 + j;
            float v = acc[i][j];
            if (bias1) v += bias1[col];
            if (bias2) v += bias2[col];
            if (accumulate) v += C[row * N + col];
            C[row * N + col] = v;
        }
    }
}

// ---------------- encoder recurrence: one CTA per (batch, direction) -----------------
__global__ void encoder_rec(const float* __restrict__ Whh_f, const float* __restrict__ Whh_b)
{
    int b = blockIdx.x, dir = blockIdx.y;
    const float* Whh = dir ? Whh_b : Whh_f;
    __shared__ __align__(16) float h_sm[Hn];
    __shared__ float c_sm[Hn];
    __shared__ float gate_sm[G4H];
    int tid = threadIdx.x;  // 512
    if (tid < Hn) { h_sm[tid] = 0.f; c_sm[tid] = 0.f; }
    __syncthreads();

    const float4* __restrict__ w4 = reinterpret_cast<const float4*>(Whh + tid * Hn);
    const float4* h4 = reinterpret_cast<const float4*>(h_sm);

    for (int step = 0; step < Sn; step++) {
        int t = dir ? (Sn - 1 - step) : step;
        float a0 = 0.f, a1 = 0.f, a2 = 0.f, a3 = 0.f;
#pragma unroll
        for (int k = 0; k < 32; k += 4) {
            float4 w0 = __ldg(&w4[k + 0]); float4 h0 = h4[k + 0];
            float4 w1 = __ldg(&w4[k + 1]); float4 h1 = h4[k + 1];
            float4 w2 = __ldg(&w4[k + 2]); float4 h2 = h4[k + 2];
            float4 w3 = __ldg(&w4[k + 3]); float4 h3 = h4[k + 3];
            a0 += w0.x * h0.x + w0.y * h0.y + w0.z * h0.z + w0.w * h0.w;
            a1 += w1.x * h1.x + w1.y * h1.y + w1.z * h1.z + w1.w * h1.w;
            a2 += w2.x * h2.x + w2.y * h2.y + w2.z * h2.z + w2.w * h2.w;
            a3 += w3.x * h3.x + w3.y * h3.y + w3.z * h3.z + w3.w * h3.w;
        }
        float acc = g_xpre[dir][t][b][tid] + ((a0 + a1) + (a2 + a3));
        gate_sm[tid] = acc;
        __syncthreads();
        if (tid < Hn) {
            float gi = gate_sm[tid], gf = gate_sm[tid + 128];
            float gg = gate_sm[tid + 256], go = gate_sm[tid + 384];
            float c = sigf(gf) * c_sm[tid] + sigf(gi) * tanhf(gg);
            float h = sigf(go) * tanhf(c);
            c_sm[tid] = c; h_sm[tid] = h;
            g_hs[t][b][dir * Hn + tid] = h;
        }
        __syncthreads();
    }
}

// ---------------- transpose h_s -> h_sT[b][j][s] ------------------------------------
__global__ void transpose_hs()
{
    __shared__ float t[32][33];
    int b = blockIdx.z, s0 = blockIdx.x * 32, j0 = blockIdx.y * 32;
    int x = threadIdx.x, y = threadIdx.y;   // 32 x 8
#pragma unroll
    for (int i = 0; i < 32; i += 8) t[y + i][x] = g_hs[s0 + y + i][b][j0 + x];
    __syncthreads();
#pragma unroll
    for (int i = 0; i < 32; i += 8) g_hsT[b][j0 + y + i][s0 + x] = t[x][y + i];
}

// ---------------- decoder init (zero s buffer 0) -------------------------------------
__global__ void dec_init()
{
    int i = blockIdx.x * 256 + threadIdx.x;
    if (i < Bn * Hn) g_sbuf[0][0][i] = 0.f;
}

// ---------------- software grid barrier ----------------------------------------------
__device__ __forceinline__ void gridbar()
{
    __syncthreads();
    if (threadIdx.x == 0) {
        unsigned gen = *(volatile unsigned*)&g_bar_gen;
        __threadfence();
        unsigned t = atomicAdd(&g_bar_cnt, 1u);
        if (t == NCTA - 1) {
            g_bar_cnt = 0;
            __threadfence();
            *(volatile unsigned*)&g_bar_gen = gen + 1;
        } else {
            while (*(volatile unsigned*)&g_bar_gen == gen) __nanosleep(32);
        }
        __threadfence();
    }
    __syncthreads();
}

// ---------------- persistent fused decoder: 64 CTAs x 1024 threads, T=128 steps ------
__global__ void __launch_bounds__(1024, 1)
decoder_persist(const float* __restrict__ mask, const float* __restrict__ va,
                const float* __restrict__ ua,
                const float* __restrict__ Wih, const float* __restrict__ Whh,
                const float* __restrict__ bih, const float* __restrict__ bhh)
{
    __shared__ __align__(16) float s_sm[Hn];
    __shared__ __align__(16) float vas_sm[Hn];
    __shared__ __align__(16) float u_sm[Hn];
    __shared__ float e_sm[Sn];              // scores, then alpha
    __shared__ float red[32];
    __shared__ float red2[2];
    __shared__ float gate_sm[8][68];
    __shared__ float y_sm[128];

    int b = blockIdx.x;
    int tid = threadIdx.x;
    int w = tid >> 5, l = tid & 31;

    if (tid < Hn) { u_sm[tid] = ua[tid]; y_sm[tid] = 0.f; }
    __syncthreads();

    const float4* va4  = reinterpret_cast<const float4*>(va);
    const float4* u4p  = reinterpret_cast<const float4*>(u_sm);
    const float4* Whh4 = reinterpret_cast<const float4*>(Whh);
    const float4* Wih4 = reinterpret_cast<const float4*>(Wih);
    const float4* ctx4 = reinterpret_cast<const float4*>(&g_ctx[0][0]);
    const float4* s_sm4 = reinterpret_cast<const float4*>(s_sm);
    const float4* vas4  = reinterpret_cast<const float4*>(vas_sm);

    for (int t = 0; t < Tn; t++) {
        int par = t & 1, nxt = par ^ 1;

        // ---- phase A: per-b attention ------------------------------------
        if (tid < Hn) s_sm[tid] = g_sbuf[par][b][tid];
        __syncthreads();

        // vas[j] = v_a[j] . s   (warp per 4 j)
        {
            float4 s4 = s_sm4[l];
#pragma unroll
            for (int jj = 0; jj < 4; jj++) {
                int j = w * 4 + jj;
                float4 v4 = __ldg(&va4[j * 32 + l]);
                float p = v4.x * s4.x + v4.y * s4.y + v4.z * s4.z + v4.w * s4.w;
                p = wred(p);
                if (l == 0) vas_sm[j] = p;
            }
        }
        __syncthreads();

        // scores e[s] = u . tanh(wahs[s] + vas), * mask  (warp per 16 s)
        {
            float4 v4 = vas4[l];
            float4 u4 = u4p[l];
#pragma unroll 4
            for (int tt = 0; tt < 16; tt++) {
                int s = w * 16 + tt;
                float4 a4 = *reinterpret_cast<const float4*>(&g_wahs[s][b][l * 4]);
                float p = tanh_fast(a4.x + v4.x) * u4.x + tanh_fast(a4.y + v4.y) * u4.y +
                          tanh_fast(a4.z + v4.z) * u4.z + tanh_fast(a4.w + v4.w) * u4.w;
                p = wred(p);
                if (l == 0) e_sm[s] = p * mask[s * Bn + b];
            }
        }
        __syncthreads();

        // softmax over 512
        {
            float e = (tid < Sn) ? e_sm[tid] : -1e30f;
            float m = e;
#pragma unroll
            for (int o = 16; o; o >>= 1) m = fmaxf(m, __shfl_xor_sync(0xFFFFFFFFu, m, o));
            if (l == 0) red[w] = m;
            __syncthreads();
            if (tid == 0) {
                float mm = red[0];
#pragma unroll
                for (int i = 1; i < 32; i++) mm = fmaxf(mm, red[i]);
                red2[0] = mm;
            }
            __syncthreads();
            m = red2[0];
            float ex = (tid < Sn) ? __expf(e - m) : 0.f;
            float sum = wred(ex);
            if (l == 0) red[w] = sum;
            __syncthreads();
            if (tid == 0) {
                float ss = red[0];
#pragma unroll
                for (int i = 1; i < 32; i++) ss += red[i];
                red2[1] = 1.f / ss;
            }
            __syncthreads();
            if (tid < Sn) e_sm[tid] = ex * red2[1];   // alpha
        }
        __syncthreads();

        // ctx[j] = sum_s alpha[s] * hsT[b][j][s]   (warp per 8 j, s-contiguous)
        {
#pragma unroll
            for (int jj = 0; jj < 8; jj++) {
                int j = w * 8 + jj;
                const float4* hp = reinterpret_cast<const float4*>(&g_hsT[b][j][0]);
                float acc = 0.f;
#pragma unroll
                for (int c = 0; c < 4; c++) {
                    float4 h = __ldg(&hp[c * 32 + l]);
                    int s0 = c * 128 + l * 4;
                    acc += h.x * e_sm[s0] + h.y * e_sm[s0 + 1] +
                           h.z * e_sm[s0 + 2] + h.w * e_sm[s0 + 3];
                }
                acc = wred(acc);
                if (l == 0) g_ctx[b][j] = acc;
            }
        }

        gridbar();

        // ---- phase B: batched gates + cell (CTA owns j = b*2, b*2+1) -----
        {
            int rl = w >> 2;               // 0..7 local gate row
            int bg = w & 3;                // 16-batch group
            int q = rl & 3, jl = rl >> 2;
            int gr = q * 128 + blockIdx.x * 2 + jl;
            float4 W0 = __ldg(&Whh4[gr * 32 + l]);
            float4 W1 = __ldg(&Wih4[gr * 64 + l]);
            float4 W2 = __ldg(&Wih4[gr * 64 + 32 + l]);
            float bias = bih[gr] + bhh[gr];
            const float4* sb4 = reinterpret_cast<const float4*>(&g_sbuf[par][0][0]);
#pragma unroll 4
            for (int bb = 0; bb < 16; bb++) {
                int bq = bg * 16 + bb;
                float4 S0 = __ldg(&sb4[bq * 32 + l]);
                float4 C1 = __ldg(&ctx4[bq * 64 + l]);
                float4 C2 = __ldg(&ctx4[bq * 64 + 32 + l]);
                float acc = W0.x * S0.x + W0.y * S0.y + W0.z * S0.z + W0.w * S0.w
                          + W1.x * C1.x + W1.y * C1.y + W1.z * C1.z + W1.w * C1.w
                          + W2.x * C2.x + W2.y * C2.y + W2.z * C2.z + W2.w * C2.w;
                acc = wred(acc);
                if (l == 0) gate_sm[rl][bq] = acc + bias;
            }
        }
        __syncthreads();
        if (tid < 128) {
            int jl = tid & 1, bb = tid >> 1;
            float gi = gate_sm[jl * 4 + 0][bb];
            float gf = gate_sm[jl * 4 + 1][bb];
            float gg = gate_sm[jl * 4 + 2][bb];
            float go = gate_sm[jl * 4 + 3][bb];
            float y = sigf(gf) * y_sm[tid] + sigf(gi) * tanhf(gg);
            float s = sigf(go) * tanhf(y);
            y_sm[tid] = y;
            g_sbuf[nxt][bb][blockIdx.x * 2 + jl] = s;
        }

        gridbar();
    }
}

// ---------------- final softmax over C=32000 -----------------------------------------
__global__ void softmax_stat(const float* __restrict__ out)
{
    int b = blockIdx.x, tid = threadIdx.x;
    __shared__ float red[256];
    const float* row = out + b * Cv;
    float m = -1e30f;
    for (int i = tid; i < Cv; i += 256) m = fmaxf(m, row[i]);
    red[tid] = m; __syncthreads();
#pragma unroll
    for (int st = 128; st; st >>= 1) {
        if (tid < st) red[tid] = fmaxf(red[tid], red[tid + st]);
        __syncthreads();
    }
    m = red[0]; __syncthreads();
    float s = 0.f;
    for (int i = tid; i < Cv; i += 256) s += __expf(row[i] - m);
    red[tid] = s; __syncthreads();
#pragma unroll
    for (int st = 128; st; st >>= 1) {
        if (tid < st) red[tid] += red[tid + st];
        __syncthreads();
    }
    if (tid == 0) { g_rowstat[b][0] = m; g_rowstat[b][1] = 1.f / red[0]; }
}

__global__ void softmax_norm(float* out)
{
    int idx = blockIdx.x * 256 + threadIdx.x;
    int b = idx / Cv;
    out[idx] = __expf(out[idx] - g_rowstat[b][0]) * g_rowstat[b][1];
}

// ---------------- launch -------------------------------------------------------------
extern "C" void kernel_launch(void* const* d_in, const int* in_sizes, int n_in,
                              void* d_out, int out_size)
{
    (void)in_sizes; (void)n_in; (void)out_size;
    const float* x      = (const float*)d_in[0];
    const float* mask   = (const float*)d_in[1];
    const float* eWih_f = (const float*)d_in[2];
    const float* eWhh_f = (const float*)d_in[3];
    const float* ebih_f = (const float*)d_in[4];
    const float* ebhh_f = (const float*)d_in[5];
    const float* eWih_b = (const float*)d_in[6];
    const float* eWhh_b = (const float*)d_in[7];
    const float* ebih_b = (const float*)d_in[8];
    const float* ebhh_b = (const float*)d_in[9];
    const float* dWih   = (const float*)d_in[10];
    const float* dWhh   = (const float*)d_in[11];
    const float* dbih   = (const float*)d_in[12];
    const float* dbhh   = (const float*)d_in[13];
    const float* w_a    = (const float*)d_in[14];
    const float* v_a    = (const float*)d_in[15];
    const float* u_a    = (const float*)d_in[16];
    const float* w_b    = (const float*)d_in[17];
    const float* v_b    = (const float*)d_in[18];
    float* out = (float*)d_out;

    float *p_xpre, *p_hs, *p_wahs, *p_s, *p_ctx;
    cudaGetSymbolAddress((void**)&p_xpre, g_xpre);
    cudaGetSymbolAddress((void**)&p_hs,   g_hs);
    cudaGetSymbolAddress((void**)&p_wahs, g_wahs);
    cudaGetSymbolAddress((void**)&p_s,    g_sbuf);   // final s lives in buffer 0
    cudaGetSymbolAddress((void**)&p_ctx,  g_ctx);

    // 1) precompute x @ Wih^T + biases for both directions
    gemm_nt<<<dim3(8, 512), 256>>>(x, eWih_f, p_xpre,                 Sn * Bn, G4H, En, ebih_f, ebhh_f, 0);
    gemm_nt<<<dim3(8, 512), 256>>>(x, eWih_b, p_xpre + Sn * Bn * G4H, Sn * Bn, G4H, En, ebih_b, ebhh_b, 0);

    // 2) encoder recurrence
    encoder_rec<<<dim3(Bn, 2), 512>>>(eWhh_f, eWhh_b);

    // 3) wa_hs = h_s @ w_a^T ; transpose h_s for s-contiguous ctx reduction
    gemm_nt<<<dim3(2, 512), 256>>>(p_hs, w_a, p_wahs, Sn * Bn, Hn, 2 * Hn, nullptr, nullptr, 0);
    transpose_hs<<<dim3(16, 8, Bn), dim3(32, 8)>>>();

    // 4) fused persistent decoder (T=128 steps, 2 grid barriers/step)
    dec_init<<<32, 256>>>();
    decoder_persist<<<NCTA, 1024>>>(mask, v_a, u_a, dWih, dWhh, dbih, dbhh);

    // 5) logits = s @ w_b^T + ctx @ v_b^T  into d_out, then softmax
    gemm_nt<<<dim3(Cv / 64, 1), 256>>>(p_s,   w_b, out, Bn, Cv, Hn,     nullptr, nullptr, 0);
    gemm_nt<<<dim3(Cv / 64, 1), 256>>>(p_ctx, v_b, out, Bn, Cv, 2 * Hn, nullptr, nullptr, 1);
    softmax_stat<<<Bn, 256>>>(out);
    softmax_norm<<<(Bn * Cv) / 256, 256>>>(out);
}

// round 5
// speedup vs baseline: 1.7357x; 1.3155x over previous
#include <cuda_runtime.h>

#define Sn 512
#define Bn 64
#define En 256
#define Hn 128
#define G4H 512
#define Tn 128
#define Cv 32000

// ---------------- scratch (static device globals; no allocation) ----------------
__device__ float g_xpre[2][Sn][Bn][G4H];     // precomputed x@Wih^T + biases
__device__ float g_hs[Sn][Bn][2*Hn];         // encoder outputs (concat fwd|bwd)
__device__ float g_hsT[Bn][2*Hn][Sn];        // transposed: per-b, j-major, s-contiguous
__device__ float g_wahs[Sn][Bn][Hn];         // w_a @ h_s precompute
__device__ float g_sfin[Bn][Hn];             // final decoder hidden
__device__ float g_ctx[Bn][2*Hn];            // final ctx
__device__ float g_rowstat[Bn][2];           // softmax max, 1/sum

__device__ __forceinline__ float sigf(float x) { return 1.f / (1.f + __expf(-x)); }
__device__ __forceinline__ float tanh_fast(float x) {
    float y; asm("tanh.approx.f32 %0, %1;" : "=f"(y) : "f"(x)); return y;
}
// reduce across 8-lane group (lanes differing in bits 0..2)
__device__ __forceinline__ float gred8(float v) {
    v += __shfl_xor_sync(0xFFFFFFFFu, v, 1);
    v += __shfl_xor_sync(0xFFFFFFFFu, v, 2);
    v += __shfl_xor_sync(0xFFFFFFFFu, v, 4);
    return v;
}

// ---------------- fused xpre GEMM: both directions via blockIdx.z --------------------
__global__ void gemm_xpre(const float* __restrict__ A,
                          const float* __restrict__ B0, const float* __restrict__ B1,
                          const float* __restrict__ bi0, const float* __restrict__ bh0,
                          const float* __restrict__ bi1, const float* __restrict__ bh1,
                          float* __restrict__ C)
{
    int dir = blockIdx.z;
    const float* B = dir ? B1 : B0;
    const float* bi = dir ? bi1 : bi0;
    const float* bh = dir ? bh1 : bh0;
    float* Cd = C + (size_t)dir * Sn * Bn * G4H;

    __shared__ __align__(16) float As[16][64];
    __shared__ __align__(16) float Bs[16][64];
    int tid = threadIdx.x;
    int tx = tid & 15, ty = tid >> 4;
    int n0 = blockIdx.x * 64, m0 = blockIdx.y * 64;
    float acc[4][4] = {};

    for (int k0 = 0; k0 < En; k0 += 16) {
#pragma unroll
        for (int qq = 0; qq < 4; qq++) {
            int idx = tid + qq * 256;
            int kk = idx & 15, m = idx >> 4;
            As[kk][m] = A[(m0 + m) * En + k0 + kk];
            Bs[kk][m] = B[(n0 + m) * En + k0 + kk];
        }
        __syncthreads();
#pragma unroll
        for (int kk = 0; kk < 16; kk++) {
            float4 a4 = *reinterpret_cast<const float4*>(&As[kk][ty * 4]);
            float4 b4 = *reinterpret_cast<const float4*>(&Bs[kk][tx * 4]);
            float av[4] = {a4.x, a4.y, a4.z, a4.w};
            float bv[4] = {b4.x, b4.y, b4.z, b4.w};
#pragma unroll
            for (int i = 0; i < 4; i++)
#pragma unroll
                for (int j = 0; j < 4; j++)
                    acc[i][j] += av[i] * bv[j];
        }
        __syncthreads();
    }
#pragma unroll
    for (int i = 0; i < 4; i++) {
        int row = m0 + ty * 4 + i;
#pragma unroll
        for (int j = 0; j < 4; j++) {
            int col = n0 + tx * 4 + j;
            Cd[row * G4H + col] = acc[i][j] + bi[col] + bh[col];
        }
    }
}

// ---------------- generic fp32 GEMM (wahs + logits) ----------------------------------
__global__ void gemm_nt(const float* __restrict__ A, const float* __restrict__ B,
                        float* __restrict__ C, int M, int N, int K,
                        int accumulate)
{
    __shared__ __align__(16) float As[16][64];
    __shared__ __align__(16) float Bs[16][64];
    int tid = threadIdx.x;
    int tx = tid & 15, ty = tid >> 4;
    int n0 = blockIdx.x * 64, m0 = blockIdx.y * 64;
    float acc[4][4] = {};

    for (int k0 = 0; k0 < K; k0 += 16) {
#pragma unroll
        for (int qq = 0; qq < 4; qq++) {
            int idx = tid + qq * 256;
            int kk = idx & 15, m = idx >> 4;
            As[kk][m] = A[(m0 + m) * K + k0 + kk];
            Bs[kk][m] = B[(n0 + m) * K + k0 + kk];
        }
        __syncthreads();
#pragma unroll
        for (int kk = 0; kk < 16; kk++) {
            float4 a4 = *reinterpret_cast<const float4*>(&As[kk][ty * 4]);
            float4 b4 = *reinterpret_cast<const float4*>(&Bs[kk][tx * 4]);
            float av[4] = {a4.x, a4.y, a4.z, a4.w};
            float bv[4] = {b4.x, b4.y, b4.z, b4.w};
#pragma unroll
            for (int i = 0; i < 4; i++)
#pragma unroll
                for (int j = 0; j < 4; j++)
                    acc[i][j] += av[i] * bv[j];
        }
        __syncthreads();
    }
#pragma unroll
    for (int i = 0; i < 4; i++) {
        int row = m0 + ty * 4 + i;
#pragma unroll
        for (int j = 0; j < 4; j++) {
            int col = n0 + tx * 4 + j;
            float v = acc[i][j];
            if (accumulate) v += C[row * N + col];
            C[row * N + col] = v;
        }
    }
}

// ---------------- encoder recurrence: smem-cached half of Whh, writes hs + hsT -------
// dynamic smem: 256 rows x 132 floats = 135168 B
__global__ void encoder_rec(const float* __restrict__ Whh_f, const float* __restrict__ Whh_b)
{
    extern __shared__ __align__(16) float ws[];
    __shared__ __align__(16) float h_sm[Hn];
    __shared__ float c_sm[Hn];
    __shared__ float gate_sm[G4H];
    int b = blockIdx.x, dir = blockIdx.y;
    const float* __restrict__ Whh = dir ? Whh_b : Whh_f;
    int tid = threadIdx.x;  // 512

    for (int idx = tid; idx < 256 * 128; idx += 512) {
        int r = idx >> 7, c = idx & 127;
        ws[r * 132 + c] = Whh[idx];
    }
    if (tid < Hn) { h_sm[tid] = 0.f; c_sm[tid] = 0.f; }
    __syncthreads();

    const float4* __restrict__ wS = reinterpret_cast<const float4*>(ws + tid * 132);
    const float4* __restrict__ wG = reinterpret_cast<const float4*>(Whh + tid * Hn);
    const float4* h4 = reinterpret_cast<const float4*>(h_sm);
    bool use_smem = (tid < 256);

    for (int step = 0; step < Sn; step++) {
        int t = dir ? (Sn - 1 - step) : step;
        float a0 = 0.f, a1 = 0.f, a2 = 0.f, a3 = 0.f;
        if (use_smem) {
#pragma unroll
            for (int k = 0; k < 32; k += 4) {
                float4 w0 = wS[k + 0]; float4 h0 = h4[k + 0];
                float4 w1 = wS[k + 1]; float4 h1 = h4[k + 1];
                float4 w2 = wS[k + 2]; float4 h2 = h4[k + 2];
                float4 w3 = wS[k + 3]; float4 h3 = h4[k + 3];
                a0 += w0.x * h0.x + w0.y * h0.y + w0.z * h0.z + w0.w * h0.w;
                a1 += w1.x * h1.x + w1.y * h1.y + w1.z * h1.z + w1.w * h1.w;
                a2 += w2.x * h2.x + w2.y * h2.y + w2.z * h2.z + w2.w * h2.w;
                a3 += w3.x * h3.x + w3.y * h3.y + w3.z * h3.z + w3.w * h3.w;
            }
        } else {
#pragma unroll
            for (int k = 0; k < 32; k += 4) {
                float4 w0 = __ldg(&wG[k + 0]); float4 h0 = h4[k + 0];
                float4 w1 = __ldg(&wG[k + 1]); float4 h1 = h4[k + 1];
                float4 w2 = __ldg(&wG[k + 2]); float4 h2 = h4[k + 2];
                float4 w3 = __ldg(&wG[k + 3]); float4 h3 = h4[k + 3];
                a0 += w0.x * h0.x + w0.y * h0.y + w0.z * h0.z + w0.w * h0.w;
                a1 += w1.x * h1.x + w1.y * h1.y + w1.z * h1.z + w1.w * h1.w;
                a2 += w2.x * h2.x + w2.y * h2.y + w2.z * h2.z + w2.w * h2.w;
                a3 += w3.x * h3.x + w3.y * h3.y + w3.z * h3.z + w3.w * h3.w;
            }
        }
        gate_sm[tid] = g_xpre[dir][t][b][tid] + ((a0 + a1) + (a2 + a3));
        __syncthreads();
        if (tid < Hn) {
            float gi = gate_sm[tid], gf = gate_sm[tid + 128];
            float gg = gate_sm[tid + 256], go = gate_sm[tid + 384];
            float c = sigf(gf) * c_sm[tid] + sigf(gi) * tanhf(gg);
            float h = sigf(go) * tanhf(c);
            c_sm[tid] = c; h_sm[tid] = h;
            int j = dir * Hn + tid;
            g_hs[t][b][j] = h;
            g_hsT[b][j][t] = h;
        }
        __syncthreads();
    }
}

// ---------------- persistent per-batch decoder: 64 independent CTAs, no barriers -----
// dynamic smem: 128 gate rows x 388 floats = 198656 B (Whh|Wih rows 0..127)
__global__ void __launch_bounds__(1024, 1)
decoder_persist(const float* __restrict__ mask, const float* __restrict__ va,
                const float* __restrict__ ua,
                const float* __restrict__ Wih, const float* __restrict__ Whh,
                const float* __restrict__ bih, const float* __restrict__ bhh)
{
    extern __shared__ __align__(16) float wc[];         // [128][388]
    __shared__ __align__(16) float xin_sm[384];         // [s(128) | ctx(256)]
    __shared__ __align__(16) float e_sm[Sn];            // scores -> alpha
    __shared__ __align__(16) float s_sm[Hn];
    __shared__ __align__(16) float y_sm[Hn];
    __shared__ __align__(16) float vas_sm[Hn];
    __shared__ __align__(16) float u_sm[Hn];
    __shared__ __align__(16) float ctx_sm[2*Hn];
    __shared__ __align__(16) float mask_sm[Sn];
    __shared__ __align__(16) float bias_sm[G4H];
    __shared__ __align__(16) float gates_sm[G4H];
    __shared__ float red[32];
    __shared__ float red2[2];

    int b = blockIdx.x;
    int tid = threadIdx.x;
    int w = tid >> 5, l = tid & 31;
    int gq = l >> 3, q = l & 7;     // 8-lane group id / lane-in-group

    // one-time init
    for (int idx = tid; idx < 128 * 384; idx += 1024) {
        int r = idx / 384, c = idx - r * 384;
        wc[r * 388 + c] = (c < 128) ? Whh[r * 128 + c] : Wih[r * 256 + (c - 128)];
    }
    if (tid < G4H) { bias_sm[tid] = bih[tid] + bhh[tid]; mask_sm[tid] = mask[tid * Bn + b]; }
    if (tid < Hn)  { u_sm[tid] = ua[tid]; s_sm[tid] = 0.f; y_sm[tid] = 0.f; }
    __syncthreads();

    const float4* va4   = reinterpret_cast<const float4*>(va);
    const float4* Whh4  = reinterpret_cast<const float4*>(Whh);
    const float4* Wih4  = reinterpret_cast<const float4*>(Wih);
    const float4* wahs4 = reinterpret_cast<const float4*>(&g_wahs[0][0][0]);
    const float4* hsT4  = reinterpret_cast<const float4*>(&g_hsT[0][0][0]);
    const float4* s4    = reinterpret_cast<const float4*>(s_sm);
    const float4* u4    = reinterpret_cast<const float4*>(u_sm);
    const float4* vas4  = reinterpret_cast<const float4*>(vas_sm);
    const float4* e4p   = reinterpret_cast<const float4*>(e_sm);
    const float4* xin4  = reinterpret_cast<const float4*>(xin_sm);

    for (int t = 0; t < Tn; t++) {
        // ---- vas[j] = v_a[j] . s  (8-lane groups, 4 j per warp) ----
        {
            int j = w * 4 + gq;
            float acc = 0.f;
#pragma unroll
            for (int k = 0; k < 4; k++) {
                int f = q + k * 8;
                float4 W = __ldg(&va4[j * 32 + f]);
                float4 X = s4[f];
                acc += W.x * X.x + W.y * X.y + W.z * X.z + W.w * X.w;
            }
            acc = gred8(acc);
            if (q == 0) vas_sm[j] = acc;
        }
        __syncthreads();

        // ---- scores e[s] = u . tanh(wahs[s,b] + vas), * mask  (16 s per warp) ----
#pragma unroll
        for (int p = 0; p < 4; p++) {
            int s = w * 16 + p * 4 + gq;
            float acc = 0.f;
#pragma unroll
            for (int k = 0; k < 4; k++) {
                int f = q + k * 8;
                float4 A = __ldg(&wahs4[(s * Bn + b) * 32 + f]);
                float4 V = vas4[f];
                float4 U = u4[f];
                acc += tanh_fast(A.x + V.x) * U.x + tanh_fast(A.y + V.y) * U.y +
                       tanh_fast(A.z + V.z) * U.z + tanh_fast(A.w + V.w) * U.w;
            }
            acc = gred8(acc);
            if (q == 0) e_sm[s] = acc * mask_sm[s];
        }
        __syncthreads();

        // ---- softmax over 512 ----
        {
            float v = (tid < Sn) ? e_sm[tid] : -1e30f;
            float m = v;
#pragma unroll
            for (int o = 16; o; o >>= 1) m = fmaxf(m, __shfl_xor_sync(0xFFFFFFFFu, m, o));
            if (l == 0) red[w] = m;
            __syncthreads();
            if (tid == 0) {
                float mm = red[0];
#pragma unroll
                for (int i = 1; i < 16; i++) mm = fmaxf(mm, red[i]);
                red2[0] = mm;
            }
            __syncthreads();
            float ex = (tid < Sn) ? __expf(v - red2[0]) : 0.f;
            float sm = ex;
#pragma unroll
            for (int o = 16; o; o >>= 1) sm += __shfl_xor_sync(0xFFFFFFFFu, sm, o);
            if (l == 0) red[w] = sm;
            __syncthreads();
            if (tid == 0) {
                float ss = red[0];
#pragma unroll
                for (int i = 1; i < 16; i++) ss += red[i];
                red2[1] = 1.f / ss;
            }
            __syncthreads();
            if (tid < Sn) e_sm[tid] = ex * red2[1];   // alpha
        }
        __syncthreads();

        // ---- ctx[j] = sum_s alpha[s] * hsT[b][j][s]  (8 j per warp) ----
#pragma unroll
        for (int p = 0; p < 2; p++) {
            int j = w * 8 + p * 4 + gq;
            const float4* hp = &hsT4[(b * 2 * Hn + j) * 128];
            float acc = 0.f;
#pragma unroll
            for (int k = 0; k < 16; k++) {
                int f = q + k * 8;
                float4 H = __ldg(&hp[f]);
                float4 A = e4p[f];
                acc += H.x * A.x + H.y * A.y + H.z * A.z + H.w * A.w;
            }
            acc = gred8(acc);
            if (q == 0) {
                ctx_sm[j] = acc;
                if (t == Tn - 1) g_ctx[b][j] = acc;
            }
        }
        __syncthreads();

        // ---- build xin = [s ; ctx] ----
        if (tid < 128) xin_sm[tid] = s_sm[tid];
        else if (tid < 384) xin_sm[tid] = ctx_sm[tid - 128];
        __syncthreads();

        // ---- gates[r] = W[r] . xin + bias  (16 rows per warp; rows<128 from smem) ----
#pragma unroll
        for (int p = 0; p < 4; p++) {
            int r = w * 16 + p * 4 + gq;
            float acc = 0.f;
            if (r < 128) {
                const float4* wr = reinterpret_cast<const float4*>(wc + r * 388);
#pragma unroll
                for (int k = 0; k < 12; k++) {
                    int f = q + k * 8;
                    float4 W = wr[f];
                    float4 X = xin4[f];
                    acc += W.x * X.x + W.y * X.y + W.z * X.z + W.w * X.w;
                }
            } else {
#pragma unroll
                for (int k = 0; k < 4; k++) {
                    int f = q + k * 8;
                    float4 W = __ldg(&Whh4[r * 32 + f]);
                    float4 X = xin4[f];
                    acc += W.x * X.x + W.y * X.y + W.z * X.z + W.w * X.w;
                }
#pragma unroll
                for (int k = 4; k < 12; k++) {
                    int f = q + k * 8;
                    float4 W = __ldg(&Wih4[r * 64 + f - 32]);
                    float4 X = xin4[f];
                    acc += W.x * X.x + W.y * X.y + W.z * X.z + W.w * X.w;
                }
            }
            acc = gred8(acc);
            if (q == 0) gates_sm[r] = acc + bias_sm[r];
        }
        __syncthreads();

        // ---- LSTM cell ----
        if (tid < Hn) {
            float gi = gates_sm[tid],       gf = gates_sm[tid + 128];
            float gg = gates_sm[tid + 256], go = gates_sm[tid + 384];
            float y = sigf(gf) * y_sm[tid] + sigf(gi) * tanhf(gg);
            float s = sigf(go) * tanhf(y);
            y_sm[tid] = y; s_sm[tid] = s;
            if (t == Tn - 1) g_sfin[b][tid] = s;
        }
        __syncthreads();
    }
}

// ---------------- final softmax over C=32000 -----------------------------------------
__global__ void softmax_stat(const float* __restrict__ out)
{
    int b = blockIdx.x, tid = threadIdx.x;
    __shared__ float red[256];
    const float* row = out + b * Cv;
    float m = -1e30f;
    for (int i = tid; i < Cv; i += 256) m = fmaxf(m, row[i]);
    red[tid] = m; __syncthreads();
#pragma unroll
    for (int st = 128; st; st >>= 1) {
        if (tid < st) red[tid] = fmaxf(red[tid], red[tid + st]);
        __syncthreads();
    }
    m = red[0]; __syncthreads();
    float s = 0.f;
    for (int i = tid; i < Cv; i += 256) s += __expf(row[i] - m);
    red[tid] = s; __syncthreads();
#pragma unroll
    for (int st = 128; st; st >>= 1) {
        if (tid < st) red[tid] += red[tid + st];
        __syncthreads();
    }
    if (tid == 0) { g_rowstat[b][0] = m; g_rowstat[b][1] = 1.f / red[0]; }
}

__global__ void softmax_norm(float* out)
{
    int idx = blockIdx.x * 256 + threadIdx.x;
    int b = idx / Cv;
    out[idx] = __expf(out[idx] - g_rowstat[b][0]) * g_rowstat[b][1];
}

// ---------------- launch -------------------------------------------------------------
extern "C" void kernel_launch(void* const* d_in, const int* in_sizes, int n_in,
                              void* d_out, int out_size)
{
    (void)in_sizes; (void)n_in; (void)out_size;
    const float* x      = (const float*)d_in[0];
    const float* mask   = (const float*)d_in[1];
    const float* eWih_f = (const float*)d_in[2];
    const float* eWhh_f = (const float*)d_in[3];
    const float* ebih_f = (const float*)d_in[4];
    const float* ebhh_f = (const float*)d_in[5];
    const float* eWih_b = (const float*)d_in[6];
    const float* eWhh_b = (const float*)d_in[7];
    const float* ebih_b = (const float*)d_in[8];
    const float* ebhh_b = (const float*)d_in[9];
    const float* dWih   = (const float*)d_in[10];
    const float* dWhh   = (const float*)d_in[11];
    const float* dbih   = (const float*)d_in[12];
    const float* dbhh   = (const float*)d_in[13];
    const float* w_a    = (const float*)d_in[14];
    const float* v_a    = (const float*)d_in[15];
    const float* u_a    = (const float*)d_in[16];
    const float* w_b    = (const float*)d_in[17];
    const float* v_b    = (const float*)d_in[18];
    float* out = (float*)d_out;

    float *p_xpre, *p_hs, *p_wahs, *p_sfin, *p_ctx;
    cudaGetSymbolAddress((void**)&p_xpre, g_xpre);
    cudaGetSymbolAddress((void**)&p_hs,   g_hs);
    cudaGetSymbolAddress((void**)&p_wahs, g_wahs);
    cudaGetSymbolAddress((void**)&p_sfin, g_sfin);
    cudaGetSymbolAddress((void**)&p_ctx,  g_ctx);

    cudaFuncSetAttribute(encoder_rec, cudaFuncAttributeMaxDynamicSharedMemorySize, 256 * 132 * 4);
    cudaFuncSetAttribute(decoder_persist, cudaFuncAttributeMaxDynamicSharedMemorySize, 128 * 388 * 4);

    // 1) xpre = x @ Wih^T + biases (both directions, one launch)
    gemm_xpre<<<dim3(8, 512, 2), 256>>>(x, eWih_f, eWih_b, ebih_f, ebhh_f, ebih_b, ebhh_b, p_xpre);

    // 2) encoder recurrence (writes g_hs and g_hsT)
    encoder_rec<<<dim3(Bn, 2), 512, 256 * 132 * 4>>>(eWhh_f, eWhh_b);

    // 3) wa_hs = h_s @ w_a^T
    gemm_nt<<<dim3(2, 512), 256>>>(p_hs, w_a, p_wahs, Sn * Bn, Hn, 2 * Hn, 0);

    // 4) fused per-batch persistent decoder (no inter-CTA sync)
    decoder_persist<<<Bn, 1024, 128 * 388 * 4>>>(mask, v_a, u_a, dWih, dWhh, dbih, dbhh);

    // 5) logits = s @ w_b^T + ctx @ v_b^T  into d_out, then softmax
    gemm_nt<<<dim3(Cv / 64, 1), 256>>>(p_sfin, w_b, out, Bn, Cv, Hn,     0);
    gemm_nt<<<dim3(Cv / 64, 1), 256>>>(p_ctx,  v_b, out, Bn, Cv, 2 * Hn, 1);
    softmax_stat<<<Bn, 256>>>(out);
    softmax_norm<<<(Bn * Cv) / 256, 256>>>(out);
}

// round 7
// speedup vs baseline: 1.7954x; 1.0344x over previous
#include <cuda_runtime.h>

#define Sn 512
#define Bn 64
#define En 256
#define Hn 128
#define G4H 512
#define Tn 128
#define Cv 32000

// ---------------- scratch (static device globals; no allocation) ----------------
__device__ float g_xpre[2][Sn][Bn][G4H];     // precomputed x@Wih^T + biases
__device__ float g_hs[Sn][Bn][2*Hn];         // encoder outputs (concat fwd|bwd)
__device__ float g_hsT[Bn][2*Hn][Sn];        // transposed: per-b, j-major, s-contiguous
__device__ float g_wahsT[Bn][Sn][Hn];        // w_a @ h_s, transposed per-b contiguous
__device__ float g_sfin[Bn][Hn];             // final decoder hidden
__device__ float g_ctx[Bn][2*Hn];            // final ctx
__device__ float g_rowstat[Bn][2];           // softmax max, 1/sum

__device__ __forceinline__ float sigf(float x) { return 1.f / (1.f + __expf(-x)); }
__device__ __forceinline__ float tanh_fast(float x) {
    float y; asm("tanh.approx.f32 %0, %1;" : "=f"(y) : "f"(x)); return y;
}
// reduce across 8-lane group (lanes differing in bits 0..2)
__device__ __forceinline__ float gred8(float v) {
    v += __shfl_xor_sync(0xFFFFFFFFu, v, 1);
    v += __shfl_xor_sync(0xFFFFFFFFu, v, 2);
    v += __shfl_xor_sync(0xFFFFFFFFu, v, 4);
    return v;
}

// ---------------- fused xpre GEMM: both directions via blockIdx.z --------------------
__global__ void gemm_xpre(const float* __restrict__ A,
                          const float* __restrict__ B0, const float* __restrict__ B1,
                          const float* __restrict__ bi0, const float* __restrict__ bh0,
                          const float* __restrict__ bi1, const float* __restrict__ bh1,
                          float* __restrict__ C)
{
    int dir = blockIdx.z;
    const float* B = dir ? B1 : B0;
    const float* bi = dir ? bi1 : bi0;
    const float* bh = dir ? bh1 : bh0;
    float* Cd = C + (size_t)dir * Sn * Bn * G4H;

    __shared__ __align__(16) float As[16][64];
    __shared__ __align__(16) float Bs[16][64];
    int tid = threadIdx.x;
    int tx = tid & 15, ty = tid >> 4;
    int n0 = blockIdx.x * 64, m0 = blockIdx.y * 64;
    float acc[4][4] = {};

    for (int k0 = 0; k0 < En; k0 += 16) {
#pragma unroll
        for (int qq = 0; qq < 4; qq++) {
            int idx = tid + qq * 256;
            int kk = idx & 15, m = idx >> 4;
            As[kk][m] = A[(m0 + m) * En + k0 + kk];
            Bs[kk][m] = B[(n0 + m) * En + k0 + kk];
        }
        __syncthreads();
#pragma unroll
        for (int kk = 0; kk < 16; kk++) {
            float4 a4 = *reinterpret_cast<const float4*>(&As[kk][ty * 4]);
            float4 b4 = *reinterpret_cast<const float4*>(&Bs[kk][tx * 4]);
            float av[4] = {a4.x, a4.y, a4.z, a4.w};
            float bv[4] = {b4.x, b4.y, b4.z, b4.w};
#pragma unroll
            for (int i = 0; i < 4; i++)
#pragma unroll
                for (int j = 0; j < 4; j++)
                    acc[i][j] += av[i] * bv[j];
        }
        __syncthreads();
    }
#pragma unroll
    for (int i = 0; i < 4; i++) {
        int row = m0 + ty * 4 + i;
#pragma unroll
        for (int j = 0; j < 4; j++) {
            int col = n0 + tx * 4 + j;
            Cd[row * G4H + col] = acc[i][j] + bi[col] + bh[col];
        }
    }
}

// ---------------- wahs GEMM, storing transposed: g_wahsT[b][s][h] --------------------
__global__ void gemm_wahsT(const float* __restrict__ A, const float* __restrict__ B)
{
    __shared__ __align__(16) float As[16][64];
    __shared__ __align__(16) float Bs[16][64];
    int tid = threadIdx.x;
    int tx = tid & 15, ty = tid >> 4;
    int n0 = blockIdx.x * 64, m0 = blockIdx.y * 64;
    float acc[4][4] = {};

    for (int k0 = 0; k0 < 2 * Hn; k0 += 16) {
#pragma unroll
        for (int qq = 0; qq < 4; qq++) {
            int idx = tid + qq * 256;
            int kk = idx & 15, m = idx >> 4;
            As[kk][m] = A[(m0 + m) * (2 * Hn) + k0 + kk];
            Bs[kk][m] = B[(n0 + m) * (2 * Hn) + k0 + kk];
        }
        __syncthreads();
#pragma unroll
        for (int kk = 0; kk < 16; kk++) {
            float4 a4 = *reinterpret_cast<const float4*>(&As[kk][ty * 4]);
            float4 b4 = *reinterpret_cast<const float4*>(&Bs[kk][tx * 4]);
            float av[4] = {a4.x, a4.y, a4.z, a4.w};
            float bv[4] = {b4.x, b4.y, b4.z, b4.w};
#pragma unroll
            for (int i = 0; i < 4; i++)
#pragma unroll
                for (int j = 0; j < 4; j++)
                    acc[i][j] += av[i] * bv[j];
        }
        __syncthreads();
    }
#pragma unroll
    for (int i = 0; i < 4; i++) {
        int row = m0 + ty * 4 + i;     // row = s*Bn + b
        int s = row >> 6, bb = row & 63;
#pragma unroll
        for (int j = 0; j < 4; j++) {
            int col = n0 + tx * 4 + j;
            g_wahsT[bb][s][col] = acc[i][j];
        }
    }
}

// ---------------- fused logits GEMM: out = sfin@w_b^T + ctx@v_b^T --------------------
__global__ void gemm_logits(const float* __restrict__ A1, const float* __restrict__ B1,
                            const float* __restrict__ A2, const float* __restrict__ B2,
                            float* __restrict__ C)
{
    __shared__ __align__(16) float As[16][64];
    __shared__ __align__(16) float Bs[16][64];
    int tid = threadIdx.x;
    int tx = tid & 15, ty = tid >> 4;
    int n0 = blockIdx.x * 64;
    float acc[4][4] = {};

    for (int k0 = 0; k0 < Hn; k0 += 16) {
#pragma unroll
        for (int qq = 0; qq < 4; qq++) {
            int idx = tid + qq * 256;
            int kk = idx & 15, m = idx >> 4;
            As[kk][m] = A1[m * Hn + k0 + kk];
            Bs[kk][m] = B1[(n0 + m) * Hn + k0 + kk];
        }
        __syncthreads();
#pragma unroll
        for (int kk = 0; kk < 16; kk++) {
            float4 a4 = *reinterpret_cast<const float4*>(&As[kk][ty * 4]);
            float4 b4 = *reinterpret_cast<const float4*>(&Bs[kk][tx * 4]);
            float av[4] = {a4.x, a4.y, a4.z, a4.w};
            float bv[4] = {b4.x, b4.y, b4.z, b4.w};
#pragma unroll
            for (int i = 0; i < 4; i++)
#pragma unroll
                for (int j = 0; j < 4; j++)
                    acc[i][j] += av[i] * bv[j];
        }
        __syncthreads();
    }
    for (int k0 = 0; k0 < 2 * Hn; k0 += 16) {
#pragma unroll
        for (int qq = 0; qq < 4; qq++) {
            int idx = tid + qq * 256;
            int kk = idx & 15, m = idx >> 4;
            As[kk][m] = A2[m * 2 * Hn + k0 + kk];
            Bs[kk][m] = B2[(n0 + m) * 2 * Hn + k0 + kk];
        }
        __syncthreads();
#pragma unroll
        for (int kk = 0; kk < 16; kk++) {
            float4 a4 = *reinterpret_cast<const float4*>(&As[kk][ty * 4]);
            float4 b4 = *reinterpret_cast<const float4*>(&Bs[kk][tx * 4]);
            float av[4] = {a4.x, a4.y, a4.z, a4.w};
            float bv[4] = {b4.x, b4.y, b4.z, b4.w};
#pragma unroll
            for (int i = 0; i < 4; i++)
#pragma unroll
                for (int j = 0; j < 4; j++)
                    acc[i][j] += av[i] * bv[j];
        }
        __syncthreads();
    }
#pragma unroll
    for (int i = 0; i < 4; i++) {
        int row = ty * 4 + i;
#pragma unroll
        for (int j = 0; j < 4; j++)
            C[row * Cv + n0 + tx * 4 + j] = acc[i][j];
    }
}

// ---------------- encoder recurrence: smem-cached half of Whh, writes hs + hsT -------
__global__ void encoder_rec(const float* __restrict__ Whh_f, const float* __restrict__ Whh_b)
{
    extern __shared__ __align__(16) float ws[];
    __shared__ __align__(16) float h_sm[Hn];
    __shared__ float c_sm[Hn];
    __shared__ float gate_sm[G4H];
    int b = blockIdx.x, dir = blockIdx.y;
    const float* __restrict__ Whh = dir ? Whh_b : Whh_f;
    int tid = threadIdx.x;  // 512

    for (int idx = tid; idx < 256 * 128; idx += 512) {
        int r = idx >> 7, c = idx & 127;
        ws[r * 132 + c] = Whh[idx];
    }
    if (tid < Hn) { h_sm[tid] = 0.f; c_sm[tid] = 0.f; }
    __syncthreads();

    const float4* __restrict__ wS = reinterpret_cast<const float4*>(ws + tid * 132);
    const float4* __restrict__ wG = reinterpret_cast<const float4*>(Whh + tid * Hn);
    const float4* h4 = reinterpret_cast<const float4*>(h_sm);
    bool use_smem = (tid < 256);

    for (int step = 0; step < Sn; step++) {
        int t = dir ? (Sn - 1 - step) : step;
        float a0 = 0.f, a1 = 0.f, a2 = 0.f, a3 = 0.f;
        if (use_smem) {
#pragma unroll
            for (int k = 0; k < 32; k += 4) {
                float4 w0 = wS[k + 0]; float4 h0 = h4[k + 0];
                float4 w1 = wS[k + 1]; float4 h1 = h4[k + 1];
                float4 w2 = wS[k + 2]; float4 h2 = h4[k + 2];
                float4 w3 = wS[k + 3]; float4 h3 = h4[k + 3];
                a0 += w0.x * h0.x + w0.y * h0.y + w0.z * h0.z + w0.w * h0.w;
                a1 += w1.x * h1.x + w1.y * h1.y + w1.z * h1.z + w1.w * h1.w;
                a2 += w2.x * h2.x + w2.y * h2.y + w2.z * h2.z + w2.w * h2.w;
                a3 += w3.x * h3.x + w3.y * h3.y + w3.z * h3.z + w3.w * h3.w;
            }
        } else {
#pragma unroll
            for (int k = 0; k < 32; k += 4) {
                float4 w0 = __ldg(&wG[k + 0]); float4 h0 = h4[k + 0];
                float4 w1 = __ldg(&wG[k + 1]); float4 h1 = h4[k + 1];
                float4 w2 = __ldg(&wG[k + 2]); float4 h2 = h4[k + 2];
                float4 w3 = __ldg(&wG[k + 3]); float4 h3 = h4[k + 3];
                a0 += w0.x * h0.x + w0.y * h0.y + w0.z * h0.z + w0.w * h0.w;
                a1 += w1.x * h1.x + w1.y * h1.y + w1.z * h1.z + w1.w * h1.w;
                a2 += w2.x * h2.x + w2.y * h2.y + w2.z * h2.z + w2.w * h2.w;
                a3 += w3.x * h3.x + w3.y * h3.y + w3.z * h3.z + w3.w * h3.w;
            }
        }
        gate_sm[tid] = g_xpre[dir][t][b][tid] + ((a0 + a1) + (a2 + a3));
        __syncthreads();
        if (tid < Hn) {
            float gi = gate_sm[tid], gf = gate_sm[tid + 128];
            float gg = gate_sm[tid + 256], go = gate_sm[tid + 384];
            float c = sigf(gf) * c_sm[tid] + sigf(gi) * tanhf(gg);
            float h = sigf(go) * tanhf(c);
            c_sm[tid] = c; h_sm[tid] = h;
            int j = dir * Hn + tid;
            g_hs[t][b][j] = h;
            g_hsT[b][j][t] = h;
        }
        __syncthreads();
    }
}

// ---------------- persistent per-batch decoder: 64 CTAs x 512 threads ----------------
// dynamic smem: 128 gate rows x 388 floats = 198656 B (Whh|Wih rows 0..127)
__global__ void __launch_bounds__(512, 1)
decoder_persist(const float* __restrict__ mask, const float* __restrict__ va,
                const float* __restrict__ ua,
                const float* __restrict__ Wih, const float* __restrict__ Whh,
                const float* __restrict__ bih, const float* __restrict__ bhh)
{
    extern __shared__ __align__(16) float wc[];         // [128][388]
    __shared__ __align__(16) float xin_sm[384];         // [s(128) | ctx(256)]
    __shared__ __align__(16) float e_sm[Sn];            // scores -> alpha
    __shared__ __align__(16) float s_sm[Hn];
    __shared__ __align__(16) float y_sm[Hn];
    __shared__ __align__(16) float vas_sm[Hn];
    __shared__ __align__(16) float u_sm[Hn];
    __shared__ __align__(16) float ctx_sm[2*Hn];
    __shared__ __align__(16) float mask_sm[Sn];
    __shared__ __align__(16) float bias_sm[G4H];
    __shared__ __align__(16) float gates_sm[G4H];
    __shared__ float red[16];
    __shared__ float red2[2];

    int b = blockIdx.x;
    int tid = threadIdx.x;                  // 512
    int w = tid >> 5, l = tid & 31;
    int g = tid >> 3, q = tid & 7;          // 64 groups of 8 lanes

    // one-time init
    for (int idx = tid; idx < 128 * 384; idx += 512) {
        int r = idx / 384, c = idx - r * 384;
        wc[r * 388 + c] = (c < 128) ? Whh[r * 128 + c] : Wih[r * 256 + (c - 128)];
    }
    bias_sm[tid] = bih[tid] + bhh[tid];
    mask_sm[tid] = mask[tid * Bn + b];
    if (tid < Hn) { u_sm[tid] = ua[tid]; s_sm[tid] = 0.f; y_sm[tid] = 0.f; }
    __syncthreads();

    const float4* va4    = reinterpret_cast<const float4*>(va);
    const float4* Whh4   = reinterpret_cast<const float4*>(Whh);
    const float4* Wih4   = reinterpret_cast<const float4*>(Wih);
    const float4* wahsT4 = reinterpret_cast<const float4*>(&g_wahsT[0][0][0]);
    const float4* hsT4   = reinterpret_cast<const float4*>(&g_hsT[0][0][0]);
    const float4* s4     = reinterpret_cast<const float4*>(s_sm);
    const float4* u4     = reinterpret_cast<const float4*>(u_sm);
    const float4* vas4   = reinterpret_cast<const float4*>(vas_sm);
    const float4* e4p    = reinterpret_cast<const float4*>(e_sm);
    const float4* xin4   = reinterpret_cast<const float4*>(xin_sm);

    for (int t = 0; t < Tn; t++) {
        // ---- vas[j] = v_a[j] . s  (2 rows per 8-lane group) ----
#pragma unroll
        for (int p = 0; p < 2; p++) {
            int j = p * 64 + g;
            float acc = 0.f;
#pragma unroll
            for (int k = 0; k < 4; k++) {
                int f = q + k * 8;
                float4 W = __ldg(&va4[j * 32 + f]);
                float4 X = s4[f];
                acc += W.x * X.x + W.y * X.y + W.z * X.z + W.w * X.w;
            }
            acc = gred8(acc);
            if (q == 0) vas_sm[j] = acc;
        }
        __syncthreads();

        // ---- scores e[s] = u . tanh(wahsT[b][s] + vas), * mask  (8 s per group) ----
        {
            float4 V[4], U[4];
#pragma unroll
            for (int k = 0; k < 4; k++) { V[k] = vas4[q + k * 8]; U[k] = u4[q + k * 8]; }
#pragma unroll
            for (int p = 0; p < 8; p++) {
                int s = p * 64 + g;
                float acc = 0.f;
#pragma unroll
                for (int k = 0; k < 4; k++) {
                    float4 A = __ldg(&wahsT4[(b * Sn + s) * 32 + q + k * 8]);
                    acc += tanh_fast(A.x + V[k].x) * U[k].x + tanh_fast(A.y + V[k].y) * U[k].y +
                           tanh_fast(A.z + V[k].z) * U[k].z + tanh_fast(A.w + V[k].w) * U[k].w;
                }
                acc = gred8(acc);
                if (q == 0) e_sm[s] = acc * mask_sm[s];
            }
        }
        __syncthreads();

        // ---- softmax over 512 (one element per thread) ----
        {
            float v = e_sm[tid];
            float m = v;
#pragma unroll
            for (int o = 16; o; o >>= 1) m = fmaxf(m, __shfl_xor_sync(0xFFFFFFFFu, m, o));
            if (l == 0) red[w] = m;
            __syncthreads();
            if (tid == 0) {
                float mm = red[0];
#pragma unroll
                for (int i = 1; i < 16; i++) mm = fmaxf(mm, red[i]);
                red2[0] = mm;
            }
            __syncthreads();
            float ex = __expf(v - red2[0]);
            float sm = ex;
#pragma unroll
            for (int o = 16; o; o >>= 1) sm += __shfl_xor_sync(0xFFFFFFFFu, sm, o);
            if (l == 0) red[w] = sm;
            __syncthreads();
            if (tid == 0) {
                float ss = red[0];
#pragma unroll
                for (int i = 1; i < 16; i++) ss += red[i];
                red2[1] = 1.f / ss;
            }
            __syncthreads();
            e_sm[tid] = ex * red2[1];   // alpha
        }
        __syncthreads();

        // ---- ctx[j] = sum_s alpha[s] * hsT[b][j][s]  (4 j per group) ----
#pragma unroll
        for (int p = 0; p < 4; p++) {
            int j = p * 64 + g;
            const float4* hp = &hsT4[(b * 2 * Hn + j) * 128];
            float acc = 0.f;
#pragma unroll
            for (int k = 0; k < 16; k++) {
                int f = q + k * 8;
                float4 H = __ldg(&hp[f]);
                float4 A = e4p[f];
                acc += H.x * A.x + H.y * A.y + H.z * A.z + H.w * A.w;
            }
            acc = gred8(acc);
            if (q == 0) {
                ctx_sm[j] = acc;
                if (t == Tn - 1) g_ctx[b][j] = acc;
            }
        }
        __syncthreads();

        // ---- build xin = [s ; ctx] ----
        if (tid < 128) xin_sm[tid] = s_sm[tid];
        else if (tid < 384) xin_sm[tid] = ctx_sm[tid - 128];
        __syncthreads();

        // ---- gates[r] = W[r] . xin + bias  (8 rows per group; p<2 from smem) ----
#pragma unroll
        for (int p = 0; p < 8; p++) {
            int r = p * 64 + g;
            float acc = 0.f;
            if (p < 2) {
                const float4* wr = reinterpret_cast<const float4*>(wc + r * 388);
#pragma unroll
                for (int k = 0; k < 12; k++) {
                    int f = q + k * 8;
                    float4 W = wr[f];
                    float4 X = xin4[f];
                    acc += W.x * X.x + W.y * X.y + W.z * X.z + W.w * X.w;
                }
            } else {
#pragma unroll
                for (int k = 0; k < 4; k++) {
                    int f = q + k * 8;
                    float4 W = __ldg(&Whh4[r * 32 + f]);
                    float4 X = xin4[f];
                    acc += W.x * X.x + W.y * X.y + W.z * X.z + W.w * X.w;
                }
#pragma unroll
                for (int k = 4; k < 12; k++) {
                    int f = q + k * 8;
                    float4 W = __ldg(&Wih4[r * 64 + f - 32]);
                    float4 X = xin4[f];
                    acc += W.x * X.x + W.y * X.y + W.z * X.z + W.w * X.w;
                }
            }
            acc = gred8(acc);
            if (q == 0) gates_sm[r] = acc + bias_sm[r];
        }
        __syncthreads();

        // ---- LSTM cell ----
        if (tid < Hn) {
            float gi = gates_sm[tid],       gf = gates_sm[tid + 128];
            float gg = gates_sm[tid + 256], go = gates_sm[tid + 384];
            float y = sigf(gf) * y_sm[tid] + sigf(gi) * tanhf(gg);
            float s = sigf(go) * tanhf(y);
            y_sm[tid] = y; s_sm[tid] = s;
            if (t == Tn - 1) g_sfin[b][tid] = s;
        }
        __syncthreads();
    }
}

// ---------------- final softmax over C=32000 -----------------------------------------
__global__ void softmax_stat(const float* __restrict__ out)
{
    int b = blockIdx.x, tid = threadIdx.x;
    __shared__ float red[256];
    const float* row = out + b * Cv;
    float m = -1e30f;
    for (int i = tid; i < Cv; i += 256) m = fmaxf(m, row[i]);
    red[tid] = m; __syncthreads();
#pragma unroll
    for (int st = 128; st; st >>= 1) {
        if (tid < st) red[tid] = fmaxf(red[tid], red[tid + st]);
        __syncthreads();
    }
    m = red[0]; __syncthreads();
    float s = 0.f;
    for (int i = tid; i < Cv; i += 256) s += __expf(row[i] - m);
    red[tid] = s; __syncthreads();
#pragma unroll
    for (int st = 128; st; st >>= 1) {
        if (tid < st) red[tid] += red[tid + st];
        __syncthreads();
    }
    if (tid == 0) { g_rowstat[b][0] = m; g_rowstat[b][1] = 1.f / red[0]; }
}

__global__ void softmax_norm(float* out)
{
    int b = blockIdx.y;
    int i = blockIdx.x * 256 + threadIdx.x;     // Cv = 125*256 exactly
    float* row = out + b * Cv;
    row[i] = __expf(row[i] - g_rowstat[b][0]) * g_rowstat[b][1];
}

// ---------------- launch -------------------------------------------------------------
extern "C" void kernel_launch(void* const* d_in, const int* in_sizes, int n_in,
                              void* d_out, int out_size)
{
    (void)in_sizes; (void)n_in; (void)out_size;
    const float* x      = (const float*)d_in[0];
    const float* mask   = (const float*)d_in[1];
    const float* eWih_f = (const float*)d_in[2];
    const float* eWhh_f = (const float*)d_in[3];
    const float* ebih_f = (const float*)d_in[4];
    const float* ebhh_f = (const float*)d_in[5];
    const float* eWih_b = (const float*)d_in[6];
    const float* eWhh_b = (const float*)d_in[7];
    const float* ebih_b = (const float*)d_in[8];
    const float* ebhh_b = (const float*)d_in[9];
    const float* dWih   = (const float*)d_in[10];
    const float* dWhh   = (const float*)d_in[11];
    const float* dbih   = (const float*)d_in[12];
    const float* dbhh   = (const float*)d_in[13];
    const float* w_a    = (const float*)d_in[14];
    const float* v_a    = (const float*)d_in[15];
    const float* u_a    = (const float*)d_in[16];
    const float* w_b    = (const float*)d_in[17];
    const float* v_b    = (const float*)d_in[18];
    float* out = (float*)d_out;

    float *p_xpre, *p_hs, *p_sfin, *p_ctx;
    cudaGetSymbolAddress((void**)&p_xpre, g_xpre);
    cudaGetSymbolAddress((void**)&p_hs,   g_hs);
    cudaGetSymbolAddress((void**)&p_sfin, g_sfin);
    cudaGetSymbolAddress((void**)&p_ctx,  g_ctx);

    cudaFuncSetAttribute(encoder_rec, cudaFuncAttributeMaxDynamicSharedMemorySize, 256 * 132 * 4);
    cudaFuncSetAttribute(decoder_persist, cudaFuncAttributeMaxDynamicSharedMemorySize, 128 * 388 * 4);

    // 1) xpre = x @ Wih^T + biases (both directions, one launch)
    gemm_xpre<<<dim3(8, 512, 2), 256>>>(x, eWih_f, eWih_b, ebih_f, ebhh_f, ebih_b, ebhh_b, p_xpre);

    // 2) encoder recurrence (writes g_hs and g_hsT)
    encoder_rec<<<dim3(Bn, 2), 512, 256 * 132 * 4>>>(eWhh_f, eWhh_b);

    // 3) wa_hs = h_s @ w_a^T, stored transposed per-b
    gemm_wahsT<<<dim3(2, 512), 256>>>(p_hs, w_a);

    // 4) fused per-batch persistent decoder (no inter-CTA sync)
    decoder_persist<<<Bn, 512, 128 * 388 * 4>>>(mask, v_a, u_a, dWih, dWhh, dbih, dbhh);

    // 5) logits (one fused GEMM) + softmax
    gemm_logits<<<dim3(Cv / 64, 1), 256>>>(p_sfin, w_b, p_ctx, v_b, out);
    softmax_stat<<<Bn, 256>>>(out);
    softmax_norm<<<dim3(Cv / 256, Bn), 256>>>(out);
}

// round 10
// speedup vs baseline: 2.0191x; 1.1246x over previous
#include <cuda_runtime.h>
#include <cstdint>

#define Sn 512
#define Bn 64
#define En 256
#define Hn 128
#define G4H 512
#define Tn 128
#define Cv 32000

// ---------------- scratch (static device globals; no allocation) ----------------
__device__ float g_xpre[2][Sn][Bn][G4H];     // precomputed x@Wih^T + biases
__device__ float g_hs[Sn][Bn][2*Hn];         // encoder outputs (concat fwd|bwd)
__device__ float g_hsT[Bn][2*Hn][Sn];        // transposed: per-b, j-major, s-contiguous
__device__ float g_wahsT[Bn][Sn][Hn];        // w_a @ h_s, transposed per-b contiguous
__device__ float g_sfin[Bn][Hn];             // final decoder hidden
__device__ float g_ctx[Bn][2*Hn];            // final ctx
__device__ float g_rowstat[Bn][2];           // softmax max, 1/sum

__device__ __forceinline__ float sigf(float x) { return 1.f / (1.f + __expf(-x)); }
__device__ __forceinline__ float tanh_fast(float x) {
    float y; asm("tanh.approx.f32 %0, %1;" : "=f"(y) : "f"(x)); return y;
}
__device__ __forceinline__ float gred8(float v) {
    v += __shfl_xor_sync(0xFFFFFFFFu, v, 1);
    v += __shfl_xor_sync(0xFFFFFFFFu, v, 2);
    v += __shfl_xor_sync(0xFFFFFFFFu, v, 4);
    return v;
}

// ---------------- cluster / DSMEM helpers -------------------------------------------
__device__ __forceinline__ uint32_t smem_u32(const void* p) {
    uint32_t a;
    asm("{ .reg .u64 t; cvta.to.shared.u64 t, %1; cvt.u32.u64 %0, t; }" : "=r"(a) : "l"(p));
    return a;
}
__device__ __forceinline__ uint32_t mapa_peer(uint32_t a, uint32_t rank) {
    uint32_t r; asm("mapa.shared::cluster.u32 %0, %1, %2;" : "=r"(r) : "r"(a), "r"(rank));
    return r;
}
__device__ __forceinline__ void st_remote_f32(uint32_t a, float v) {
    asm volatile("st.shared::cluster.f32 [%0], %1;" :: "r"(a), "f"(v) : "memory");
}
// full cluster barrier, all threads of both CTAs; arrive=release, wait=acquire
__device__ __forceinline__ void cluster_barrier() {
    asm volatile("barrier.cluster.arrive.aligned;" ::: "memory");
    asm volatile("barrier.cluster.wait.aligned;" ::: "memory");
}

// ---------------- fused xpre GEMM: both directions via blockIdx.z --------------------
__global__ void gemm_xpre(const float* __restrict__ A,
                          const float* __restrict__ B0, const float* __restrict__ B1,
                          const float* __restrict__ bi0, const float* __restrict__ bh0,
                          const float* __restrict__ bi1, const float* __restrict__ bh1,
                          float* __restrict__ C)
{
    int dir = blockIdx.z;
    const float* B = dir ? B1 : B0;
    const float* bi = dir ? bi1 : bi0;
    const float* bh = dir ? bh1 : bh0;
    float* Cd = C + (size_t)dir * Sn * Bn * G4H;

    __shared__ __align__(16) float As[16][64];
    __shared__ __align__(16) float Bs[16][64];
    int tid = threadIdx.x;
    int tx = tid & 15, ty = tid >> 4;
    int n0 = blockIdx.x * 64, m0 = blockIdx.y * 64;
    float acc[4][4] = {};

    for (int k0 = 0; k0 < En; k0 += 16) {
#pragma unroll
        for (int qq = 0; qq < 4; qq++) {
            int idx = tid + qq * 256;
            int kk = idx & 15, m = idx >> 4;
            As[kk][m] = A[(m0 + m) * En + k0 + kk];
            Bs[kk][m] = B[(n0 + m) * En + k0 + kk];
        }
        __syncthreads();
#pragma unroll
        for (int kk = 0; kk < 16; kk++) {
            float4 a4 = *reinterpret_cast<const float4*>(&As[kk][ty * 4]);
            float4 b4 = *reinterpret_cast<const float4*>(&Bs[kk][tx * 4]);
            float av[4] = {a4.x, a4.y, a4.z, a4.w};
            float bv[4] = {b4.x, b4.y, b4.z, b4.w};
#pragma unroll
            for (int i = 0; i < 4; i++)
#pragma unroll
                for (int j = 0; j < 4; j++)
                    acc[i][j] += av[i] * bv[j];
        }
        __syncthreads();
    }
#pragma unroll
    for (int i = 0; i < 4; i++) {
        int row = m0 + ty * 4 + i;
#pragma unroll
        for (int j = 0; j < 4; j++) {
            int col = n0 + tx * 4 + j;
            Cd[row * G4H + col] = acc[i][j] + bi[col] + bh[col];
        }
    }
}

// ---------------- wahs GEMM, storing transposed: g_wahsT[b][s][h] --------------------
__global__ void gemm_wahsT(const float* __restrict__ A, const float* __restrict__ B)
{
    __shared__ __align__(16) float As[16][64];
    __shared__ __align__(16) float Bs[16][64];
    int tid = threadIdx.x;
    int tx = tid & 15, ty = tid >> 4;
    int n0 = blockIdx.x * 64, m0 = blockIdx.y * 64;
    float acc[4][4] = {};

    for (int k0 = 0; k0 < 2 * Hn; k0 += 16) {
#pragma unroll
        for (int qq = 0; qq < 4; qq++) {
            int idx = tid + qq * 256;
            int kk = idx & 15, m = idx >> 4;
            As[kk][m] = A[(m0 + m) * (2 * Hn) + k0 + kk];
            Bs[kk][m] = B[(n0 + m) * (2 * Hn) + k0 + kk];
        }
        __syncthreads();
#pragma unroll
        for (int kk = 0; kk < 16; kk++) {
            float4 a4 = *reinterpret_cast<const float4*>(&As[kk][ty * 4]);
            float4 b4 = *reinterpret_cast<const float4*>(&Bs[kk][tx * 4]);
            float av[4] = {a4.x, a4.y, a4.z, a4.w};
            float bv[4] = {b4.x, b4.y, b4.z, b4.w};
#pragma unroll
            for (int i = 0; i < 4; i++)
#pragma unroll
                for (int j = 0; j < 4; j++)
                    acc[i][j] += av[i] * bv[j];
        }
        __syncthreads();
    }
#pragma unroll
    for (int i = 0; i < 4; i++) {
        int row = m0 + ty * 4 + i;     // row = s*Bn + b
        int s = row >> 6, bb = row & 63;
#pragma unroll
        for (int j = 0; j < 4; j++) {
            int col = n0 + tx * 4 + j;
            g_wahsT[bb][s][col] = acc[i][j];
        }
    }
}

// ---------------- fused logits GEMM: out = sfin@w_b^T + ctx@v_b^T --------------------
__global__ void gemm_logits(const float* __restrict__ A1, const float* __restrict__ B1,
                            const float* __restrict__ A2, const float* __restrict__ B2,
                            float* __restrict__ C)
{
    __shared__ __align__(16) float As[16][64];
    __shared__ __align__(16) float Bs[16][64];
    int tid = threadIdx.x;
    int tx = tid & 15, ty = tid >> 4;
    int n0 = blockIdx.x * 64;
    float acc[4][4] = {};

    for (int k0 = 0; k0 < Hn; k0 += 16) {
#pragma unroll
        for (int qq = 0; qq < 4; qq++) {
            int idx = tid + qq * 256;
            int kk = idx & 15, m = idx >> 4;
            As[kk][m] = A1[m * Hn + k0 + kk];
            Bs[kk][m] = B1[(n0 + m) * Hn + k0 + kk];
        }
        __syncthreads();
#pragma unroll
        for (int kk = 0; kk < 16; kk++) {
            float4 a4 = *reinterpret_cast<const float4*>(&As[kk][ty * 4]);
            float4 b4 = *reinterpret_cast<const float4*>(&Bs[kk][tx * 4]);
            float av[4] = {a4.x, a4.y, a4.z, a4.w};
            float bv[4] = {b4.x, b4.y, b4.z, b4.w};
#pragma unroll
            for (int i = 0; i < 4; i++)
#pragma unroll
                for (int j = 0; j < 4; j++)
                    acc[i][j] += av[i] * bv[j];
        }
        __syncthreads();
    }
    for (int k0 = 0; k0 < 2 * Hn; k0 += 16) {
#pragma unroll
        for (int qq = 0; qq < 4; qq++) {
            int idx = tid + qq * 256;
            int kk = idx & 15, m = idx >> 4;
            As[kk][m] = A2[m * 2 * Hn + k0 + kk];
            Bs[kk][m] = B2[(n0 + m) * 2 * Hn + k0 + kk];
        }
        __syncthreads();
#pragma unroll
        for (int kk = 0; kk < 16; kk++) {
            float4 a4 = *reinterpret_cast<const float4*>(&As[kk][ty * 4]);
            float4 b4 = *reinterpret_cast<const float4*>(&Bs[kk][tx * 4]);
            float av[4] = {a4.x, a4.y, a4.z, a4.w};
            float bv[4] = {b4.x, b4.y, b4.z, b4.w};
#pragma unroll
            for (int i = 0; i < 4; i++)
#pragma unroll
                for (int j = 0; j < 4; j++)
                    acc[i][j] += av[i] * bv[j];
        }
        __syncthreads();
    }
#pragma unroll
    for (int i = 0; i < 4; i++) {
        int row = ty * 4 + i;
#pragma unroll
        for (int j = 0; j < 4; j++)
            C[row * Cv + n0 + tx * 4 + j] = acc[i][j];
    }
}

// ---------------- encoder recurrence: smem-cached half of Whh, writes hs + hsT -------
__global__ void encoder_rec(const float* __restrict__ Whh_f, const float* __restrict__ Whh_b)
{
    extern __shared__ __align__(16) float ws[];
    __shared__ __align__(16) float h_sm[Hn];
    __shared__ float c_sm[Hn];
    __shared__ float gate_sm[G4H];
    int b = blockIdx.x, dir = blockIdx.y;
    const float* __restrict__ Whh = dir ? Whh_b : Whh_f;
    int tid = threadIdx.x;  // 512

    for (int idx = tid; idx < 256 * 128; idx += 512) {
        int r = idx >> 7, c = idx & 127;
        ws[r * 132 + c] = Whh[idx];
    }
    if (tid < Hn) { h_sm[tid] = 0.f; c_sm[tid] = 0.f; }
    __syncthreads();

    const float4* __restrict__ wS = reinterpret_cast<const float4*>(ws + tid * 132);
    const float4* __restrict__ wG = reinterpret_cast<const float4*>(Whh + tid * Hn);
    const float4* h4 = reinterpret_cast<const float4*>(h_sm);
    bool use_smem = (tid < 256);

    for (int step = 0; step < Sn; step++) {
        int t = dir ? (Sn - 1 - step) : step;
        float a0 = 0.f, a1 = 0.f, a2 = 0.f, a3 = 0.f;
        if (use_smem) {
#pragma unroll
            for (int k = 0; k < 32; k += 4) {
                float4 w0 = wS[k + 0]; float4 h0 = h4[k + 0];
                float4 w1 = wS[k + 1]; float4 h1 = h4[k + 1];
                float4 w2 = wS[k + 2]; float4 h2 = h4[k + 2];
                float4 w3 = wS[k + 3]; float4 h3 = h4[k + 3];
                a0 += w0.x * h0.x + w0.y * h0.y + w0.z * h0.z + w0.w * h0.w;
                a1 += w1.x * h1.x + w1.y * h1.y + w1.z * h1.z + w1.w * h1.w;
                a2 += w2.x * h2.x + w2.y * h2.y + w2.z * h2.z + w2.w * h2.w;
                a3 += w3.x * h3.x + w3.y * h3.y + w3.z * h3.z + w3.w * h3.w;
            }
        } else {
#pragma unroll
            for (int k = 0; k < 32; k += 4) {
                float4 w0 = __ldg(&wG[k + 0]); float4 h0 = h4[k + 0];
                float4 w1 = __ldg(&wG[k + 1]); float4 h1 = h4[k + 1];
                float4 w2 = __ldg(&wG[k + 2]); float4 h2 = h4[k + 2];
                float4 w3 = __ldg(&wG[k + 3]); float4 h3 = h4[k + 3];
                a0 += w0.x * h0.x + w0.y * h0.y + w0.z * h0.z + w0.w * h0.w;
                a1 += w1.x * h1.x + w1.y * h1.y + w1.z * h1.z + w1.w * h1.w;
                a2 += w2.x * h2.x + w2.y * h2.y + w2.z * h2.z + w2.w * h2.w;
                a3 += w3.x * h3.x + w3.y * h3.y + w3.z * h3.z + w3.w * h3.w;
            }
        }
        gate_sm[tid] = g_xpre[dir][t][b][tid] + ((a0 + a1) + (a2 + a3));
        __syncthreads();
        if (tid < Hn) {
            float gi = gate_sm[tid], gf = gate_sm[tid + 128];
            float gg = gate_sm[tid + 256], go = gate_sm[tid + 384];
            float c = sigf(gf) * c_sm[tid] + sigf(gi) * tanhf(gg);
            float h = sigf(go) * tanhf(c);
            c_sm[tid] = c; h_sm[tid] = h;
            int j = dir * Hn + tid;
            g_hs[t][b][j] = h;
            g_hsT[b][j][t] = h;
        }
        __syncthreads();
    }
}

// ---------------- cluster-pair persistent decoder: 128 CTAs (2 per batch) ------------
// CTA rank h handles: scores/ctx for s in [h*256,(h+1)*256), gates/cell for j in [h*64,(h+1)*64)
// Handshakes via full cluster barriers (all threads; release/acquire built in).
// dynamic smem: 128 cached gate rows x 388 floats = 198656 B
__global__ void __launch_bounds__(512, 1) __cluster_dims__(2, 1, 1)
decoder_persist(const float* __restrict__ mask, const float* __restrict__ va,
                const float* __restrict__ ua,
                const float* __restrict__ Wih, const float* __restrict__ Whh,
                const float* __restrict__ bih, const float* __restrict__ bhh)
{
    extern __shared__ __align__(16) float wc[];          // [128][388]
    __shared__ __align__(16) float s_sm[2][Hn];          // full hidden, dbl-buffered
    __shared__ __align__(16) float y_sm[64];             // owned cell state
    __shared__ __align__(16) float vas_sm[Hn];
    __shared__ __align__(16) float u_sm[Hn];
    __shared__ __align__(16) float e_sm[256];            // local-half exp (unnorm)
    __shared__ __align__(16) float ctxp_sm[2*Hn];        // my unnormalized partial ctx
    __shared__ __align__(16) float xin_sm[384];
    __shared__ __align__(16) float mask_sm[256];
    __shared__ __align__(16) float bias_sm[256];
    __shared__ __align__(16) float gates_sm[256];
    __shared__ __align__(16) float xch_ctx[2][2*Hn];     // peer writes partial ctx here
    __shared__ __align__(16) float xch_ms[2][2];         // peer writes (max, sum) here
    __shared__ float red[16];
    __shared__ float red2[4];

    uint32_t rank;
    asm("mov.u32 %0, %%cluster_ctarank;" : "=r"(rank));
    int h = (int)rank;
    int b = blockIdx.x >> 1;
    int tid = threadIdx.x;                  // 512
    int w = tid >> 5, l = tid & 31;
    int g = tid >> 3, q = tid & 7;          // 64 groups of 8 lanes

    uint32_t peer_xctx = mapa_peer(smem_u32(&xch_ctx[0][0]), rank ^ 1);
    uint32_t peer_xms  = mapa_peer(smem_u32(&xch_ms[0][0]),  rank ^ 1);
    uint32_t peer_s    = mapa_peer(smem_u32(&s_sm[0][0]),    rank ^ 1);

    // owned weight cache: quads i,f,g,o restricted to owned j-half
    for (int idx = tid; idx < 128 * 384; idx += 512) {
        int lr = idx / 384, c = idx - lr * 384;
        int r = (lr >> 6) * 128 + h * 64 + (lr & 63);
        wc[lr * 388 + c] = (c < 128) ? Whh[r * 128 + c] : Wih[r * 256 + (c - 128)];
    }
    if (tid < 256) {
        int r = (tid >> 6) * 128 + h * 64 + (tid & 63);
        bias_sm[tid] = bih[r] + bhh[r];
        mask_sm[tid] = mask[(h * 256 + tid) * Bn + b];
    }
    if (tid < Hn) { u_sm[tid] = ua[tid]; s_sm[0][tid] = 0.f; }
    if (tid < 64) y_sm[tid] = 0.f;
    __syncthreads();

    const float4* va4    = reinterpret_cast<const float4*>(va);
    const float4* Whh4   = reinterpret_cast<const float4*>(Whh);
    const float4* Wih4   = reinterpret_cast<const float4*>(Wih);
    const float4* wahsT4 = reinterpret_cast<const float4*>(&g_wahsT[0][0][0]);
    const float4* hsT4   = reinterpret_cast<const float4*>(&g_hsT[0][0][0]);
    const float4* u4     = reinterpret_cast<const float4*>(u_sm);
    const float4* vas4   = reinterpret_cast<const float4*>(vas_sm);
    const float4* e4p    = reinterpret_cast<const float4*>(e_sm);
    const float4* xin4   = reinterpret_cast<const float4*>(xin_sm);

    for (int t = 0; t < Tn; t++) {
        int par = t & 1;
        const float4* s4 = reinterpret_cast<const float4*>(&s_sm[par][0]);

        // ---- vas[j] = v_a[j] . s  (redundant full 128; 2 rows per group) ----
#pragma unroll
        for (int p = 0; p < 2; p++) {
            int j = p * 64 + g;
            float acc = 0.f;
#pragma unroll
            for (int k = 0; k < 4; k++) {
                int f = q + k * 8;
                float4 W = __ldg(&va4[j * 32 + f]);
                float4 X = s4[f];
                acc += W.x * X.x + W.y * X.y + W.z * X.z + W.w * X.w;
            }
            acc = gred8(acc);
            if (q == 0) vas_sm[j] = acc;
        }
        __syncthreads();

        // ---- local scores (s-half): 4 per group ----
        {
            float4 V[4], U[4];
#pragma unroll
            for (int k = 0; k < 4; k++) { V[k] = vas4[q + k * 8]; U[k] = u4[q + k * 8]; }
#pragma unroll
            for (int p = 0; p < 4; p++) {
                int sl = p * 64 + g;
                int s = h * 256 + sl;
                float acc = 0.f;
#pragma unroll
                for (int k = 0; k < 4; k++) {
                    float4 A = __ldg(&wahsT4[(b * Sn + s) * 32 + q + k * 8]);
                    acc += tanh_fast(A.x + V[k].x) * U[k].x + tanh_fast(A.y + V[k].y) * U[k].y +
                           tanh_fast(A.z + V[k].z) * U[k].z + tanh_fast(A.w + V[k].w) * U[k].w;
                }
                acc = gred8(acc);
                if (q == 0) e_sm[sl] = acc * mask_sm[sl];
            }
        }
        __syncthreads();

        // ---- local max + unnormalized exp + local sum ----
        {
            float v = (tid < 256) ? e_sm[tid] : -1e30f;
            float m = v;
#pragma unroll
            for (int o = 16; o; o >>= 1) m = fmaxf(m, __shfl_xor_sync(0xFFFFFFFFu, m, o));
            if (l == 0) red[w] = m;
            __syncthreads();
            if (tid == 0) {
                float mm = red[0];
#pragma unroll
                for (int i = 1; i < 16; i++) mm = fmaxf(mm, red[i]);
                red2[0] = mm;
            }
            __syncthreads();
            float ex = (tid < 256) ? __expf(v - red2[0]) : 0.f;
            float sm = ex;
#pragma unroll
            for (int o = 16; o; o >>= 1) sm += __shfl_xor_sync(0xFFFFFFFFu, sm, o);
            if (l == 0) red[w] = sm;
            __syncthreads();
            if (tid == 0) {
                float ss = red[0];
#pragma unroll
                for (int i = 1; i < 16; i++) ss += red[i];
                red2[1] = ss;
            }
            if (tid < 256) e_sm[tid] = ex;
        }
        __syncthreads();

        // ---- unnormalized partial ctx over my s-half (4 j per group) ----
#pragma unroll
        for (int p = 0; p < 4; p++) {
            int j = p * 64 + g;
            const float4* hp = &hsT4[(b * 2 * Hn + j) * 128 + h * 64];
            float acc = 0.f;
#pragma unroll
            for (int k = 0; k < 8; k++) {
                int f = q + k * 8;
                float4 H = __ldg(&hp[f]);
                float4 A = e4p[f];
                acc += H.x * A.x + H.y * A.y + H.z * A.z + H.w * A.w;
            }
            acc = gred8(acc);
            if (q == 0) ctxp_sm[j] = acc;
        }
        __syncthreads();

        // ---- exchange (m, sum, partial ctx) via DSMEM; full cluster barrier ----
        if (tid < 256) st_remote_f32(peer_xctx + (par * 256 + tid) * 4, ctxp_sm[tid]);
        if (tid < 2)   st_remote_f32(peer_xms + (par * 2 + tid) * 4, red2[tid]);
        cluster_barrier();

        // ---- combine softmax stats ----
        if (tid == 0) {
            float m_me = red2[0], s_me = red2[1];
            float m_pr = xch_ms[par][0], s_pr = xch_ms[par][1];
            float M = fmaxf(m_me, m_pr);
            float a = __expf(m_me - M), bb2 = __expf(m_pr - M);
            float inv = 1.f / (s_me * a + s_pr * bb2);
            red2[2] = a * inv; red2[3] = bb2 * inv;
        }
        __syncthreads();

        // ---- xin = [ s ; ctx_full ] ----
        if (tid < 128) xin_sm[tid] = s_sm[par][tid];
        else if (tid < 384) {
            int j = tid - 128;
            xin_sm[tid] = ctxp_sm[j] * red2[2] + xch_ctx[par][j] * red2[3];
        }
        __syncthreads();
        if (t == Tn - 1 && h == 0 && tid < 256) g_ctx[b][tid] = xin_sm[128 + tid];

        // ---- gates for owned rows (4 per group: quads i,f,g,o of owned j) ----
#pragma unroll
        for (int p = 0; p < 4; p++) {
            int lr = p * 64 + g;
            float acc = 0.f;
            if (p < 2) {
                const float4* wr = reinterpret_cast<const float4*>(wc + lr * 388);
#pragma unroll
                for (int k = 0; k < 12; k++) {
                    int f = q + k * 8;
                    float4 W = wr[f];
                    float4 X = xin4[f];
                    acc += W.x * X.x + W.y * X.y + W.z * X.z + W.w * X.w;
                }
            } else {
                int r = p * 128 + h * 64 + g;
#pragma unroll
                for (int k = 0; k < 4; k++) {
                    int f = q + k * 8;
                    float4 W = __ldg(&Whh4[r * 32 + f]);
                    float4 X = xin4[f];
                    acc += W.x * X.x + W.y * X.y + W.z * X.z + W.w * X.w;
                }
#pragma unroll
                for (int k = 4; k < 12; k++) {
                    int f = q + k * 8;
                    float4 W = __ldg(&Wih4[r * 64 + f - 32]);
                    float4 X = xin4[f];
                    acc += W.x * X.x + W.y * X.y + W.z * X.z + W.w * X.w;
                }
            }
            acc = gred8(acc);
            if (q == 0) gates_sm[lr] = acc + bias_sm[lr];
        }
        __syncthreads();

        // ---- cell for owned j; publish s-half to both CTAs ----
        if (tid < 64) {
            float gi = gates_sm[tid],       gf = gates_sm[64 + tid];
            float gg = gates_sm[128 + tid], go = gates_sm[192 + tid];
            float y = sigf(gf) * y_sm[tid] + sigf(gi) * tanhf(gg);
            float s = sigf(go) * tanhf(y);
            y_sm[tid] = y;
            int jg = h * 64 + tid;
            s_sm[par ^ 1][jg] = s;
            st_remote_f32(peer_s + ((par ^ 1) * 128 + jg) * 4, s);
            if (t == Tn - 1) g_sfin[b][jg] = s;
        }
        cluster_barrier();
    }
}

// ---------------- final softmax over C=32000 -----------------------------------------
__global__ void softmax_stat(const float* __restrict__ out)
{
    int b = blockIdx.x, tid = threadIdx.x;
    __shared__ float red[256];
    const float* row = out + b * Cv;
    float m = -1e30f;
    for (int i = tid; i < Cv; i += 256) m = fmaxf(m, row[i]);
    red[tid] = m; __syncthreads();
#pragma unroll
    for (int st = 128; st; st >>= 1) {
        if (tid < st) red[tid] = fmaxf(red[tid], red[tid + st]);
        __syncthreads();
    }
    m = red[0]; __syncthreads();
    float s = 0.f;
    for (int i = tid; i < Cv; i += 256) s += __expf(row[i] - m);
    red[tid] = s; __syncthreads();
#pragma unroll
    for (int st = 128; st; st >>= 1) {
        if (tid < st) red[tid] += red[tid + st];
        __syncthreads();
    }
    if (tid == 0) { g_rowstat[b][0] = m; g_rowstat[b][1] = 1.f / red[0]; }
}

__global__ void softmax_norm(float* out)
{
    int b = blockIdx.y;
    int i = blockIdx.x * 256 + threadIdx.x;     // Cv = 125*256 exactly
    float* row = out + b * Cv;
    row[i] = __expf(row[i] - g_rowstat[b][0]) * g_rowstat[b][1];
}

// ---------------- launch -------------------------------------------------------------
extern "C" void kernel_launch(void* const* d_in, const int* in_sizes, int n_in,
                              void* d_out, int out_size)
{
    (void)in_sizes; (void)n_in; (void)out_size;
    const float* x      = (const float*)d_in[0];
    const float* mask   = (const float*)d_in[1];
    const float* eWih_f = (const float*)d_in[2];
    const float* eWhh_f = (const float*)d_in[3];
    const float* ebih_f = (const float*)d_in[4];
    const float* ebhh_f = (const float*)d_in[5];
    const float* eWih_b = (const float*)d_in[6];
    const float* eWhh_b = (const float*)d_in[7];
    const float* ebih_b = (const float*)d_in[8];
    const float* ebhh_b = (const float*)d_in[9];
    const float* dWih   = (const float*)d_in[10];
    const float* dWhh   = (const float*)d_in[11];
    const float* dbih   = (const float*)d_in[12];
    const float* dbhh   = (const float*)d_in[13];
    const float* w_a    = (const float*)d_in[14];
    const float* v_a    = (const float*)d_in[15];
    const float* u_a    = (const float*)d_in[16];
    const float* w_b    = (const float*)d_in[17];
    const float* v_b    = (const float*)d_in[18];
    float* out = (float*)d_out;

    float *p_xpre, *p_hs, *p_sfin, *p_ctx;
    cudaGetSymbolAddress((void**)&p_xpre, g_xpre);
    cudaGetSymbolAddress((void**)&p_hs,   g_hs);
    cudaGetSymbolAddress((void**)&p_sfin, g_sfin);
    cudaGetSymbolAddress((void**)&p_ctx,  g_ctx);

    cudaFuncSetAttribute(encoder_rec, cudaFuncAttributeMaxDynamicSharedMemorySize, 256 * 132 * 4);
    cudaFuncSetAttribute(decoder_persist, cudaFuncAttributeMaxDynamicSharedMemorySize, 128 * 388 * 4);

    // 1) xpre = x @ Wih^T + biases (both directions, one launch)
    gemm_xpre<<<dim3(8, 512, 2), 256>>>(x, eWih_f, eWih_b, ebih_f, ebhh_f, ebih_b, ebhh_b, p_xpre);

    // 2) encoder recurrence (writes g_hs and g_hsT)
    encoder_rec<<<dim3(Bn, 2), 512, 256 * 132 * 4>>>(eWhh_f, eWhh_b);

    // 3) wa_hs = h_s @ w_a^T, stored transposed per-b
    gemm_wahsT<<<dim3(2, 512), 256>>>(p_hs, w_a);

    // 4) cluster-pair persistent decoder (2 CTAs per batch, cluster-barrier handshakes)
    decoder_persist<<<2 * Bn, 512, 128 * 388 * 4>>>(mask, v_a, u_a, dWih, dWhh, dbih, dbhh);

    // 5) logits (one fused GEMM) + softmax
    gemm_logits<<<dim3(Cv / 64, 1), 256>>>(p_sfin, w_b, p_ctx, v_b, out);
    softmax_stat<<<Bn, 256>>>(out);
    softmax_norm<<<dim3(Cv / 256, Bn), 256>>>(out);
}

// round 12
// speedup vs baseline: 2.0470x; 1.0138x over previous
#include <cuda_runtime.h>
#include <cstdint>

#define Sn 512
#define Bn 64
#define En 256
#define Hn 128
#define G4H 512
#define Tn 128
#define Cv 32000

// ---------------- scratch (static device globals; no allocation) ----------------
__device__ float g_xpre[2][Sn][Bn][G4H];     // precomputed x@Wih^T + biases
__device__ float g_hs[Sn][Bn][2*Hn];         // encoder outputs (concat fwd|bwd)
__device__ float g_hsT[Bn][2*Hn][Sn];        // transposed: per-b, j-major, s-contiguous
__device__ float g_wahsT[Bn][Sn][Hn];        // w_a @ h_s, transposed per-b contiguous
__device__ float g_sfin[Bn][Hn];             // final decoder hidden
__device__ float g_ctx[Bn][2*Hn];            // final ctx
__device__ float g_rowstat[Bn][2];           // softmax max, 1/sum

__device__ __forceinline__ float sigf(float x) { return 1.f / (1.f + __expf(-x)); }
__device__ __forceinline__ float tanh_fast(float x) {
    float y; asm("tanh.approx.f32 %0, %1;" : "=f"(y) : "f"(x)); return y;
}
__device__ __forceinline__ float gred8(float v) {
    v += __shfl_xor_sync(0xFFFFFFFFu, v, 1);
    v += __shfl_xor_sync(0xFFFFFFFFu, v, 2);
    v += __shfl_xor_sync(0xFFFFFFFFu, v, 4);
    return v;
}

// ---------------- cluster / DSMEM helpers -------------------------------------------
__device__ __forceinline__ uint32_t smem_u32(const void* p) {
    uint32_t a;
    asm("{ .reg .u64 t; cvta.to.shared.u64 t, %1; cvt.u32.u64 %0, t; }" : "=r"(a) : "l"(p));
    return a;
}
__device__ __forceinline__ uint32_t mapa_peer(uint32_t a, uint32_t rank) {
    uint32_t r; asm("mapa.shared::cluster.u32 %0, %1, %2;" : "=r"(r) : "r"(a), "r"(rank));
    return r;
}
__device__ __forceinline__ void st_remote_f32(uint32_t a, float v) {
    asm volatile("st.shared::cluster.f32 [%0], %1;" :: "r"(a), "f"(v) : "memory");
}
// full cluster barrier, all threads of both CTAs; arrive=release, wait=acquire
__device__ __forceinline__ void cluster_barrier() {
    asm volatile("barrier.cluster.arrive.aligned;" ::: "memory");
    asm volatile("barrier.cluster.wait.aligned;" ::: "memory");
}

// ---------------- fused xpre GEMM: both directions via blockIdx.z --------------------
__global__ void gemm_xpre(const float* __restrict__ A,
                          const float* __restrict__ B0, const float* __restrict__ B1,
                          const float* __restrict__ bi0, const float* __restrict__ bh0,
                          const float* __restrict__ bi1, const float* __restrict__ bh1,
                          float* __restrict__ C)
{
    int dir = blockIdx.z;
    const float* B = dir ? B1 : B0;
    const float* bi = dir ? bi1 : bi0;
    const float* bh = dir ? bh1 : bh0;
    float* Cd = C + (size_t)dir * Sn * Bn * G4H;

    __shared__ __align__(16) float As[16][64];
    __shared__ __align__(16) float Bs[16][64];
    int tid = threadIdx.x;
    int tx = tid & 15, ty = tid >> 4;
    int n0 = blockIdx.x * 64, m0 = blockIdx.y * 64;
    float acc[4][4] = {};

    for (int k0 = 0; k0 < En; k0 += 16) {
#pragma unroll
        for (int qq = 0; qq < 4; qq++) {
            int idx = tid + qq * 256;
            int kk = idx & 15, m = idx >> 4;
            As[kk][m] = A[(m0 + m) * En + k0 + kk];
            Bs[kk][m] = B[(n0 + m) * En + k0 + kk];
        }
        __syncthreads();
#pragma unroll
        for (int kk = 0; kk < 16; kk++) {
            float4 a4 = *reinterpret_cast<const float4*>(&As[kk][ty * 4]);
            float4 b4 = *reinterpret_cast<const float4*>(&Bs[kk][tx * 4]);
            float av[4] = {a4.x, a4.y, a4.z, a4.w};
            float bv[4] = {b4.x, b4.y, b4.z, b4.w};
#pragma unroll
            for (int i = 0; i < 4; i++)
#pragma unroll
                for (int j = 0; j < 4; j++)
                    acc[i][j] += av[i] * bv[j];
        }
        __syncthreads();
    }
#pragma unroll
    for (int i = 0; i < 4; i++) {
        int row = m0 + ty * 4 + i;
#pragma unroll
        for (int j = 0; j < 4; j++) {
            int col = n0 + tx * 4 + j;
            Cd[row * G4H + col] = acc[i][j] + bi[col] + bh[col];
        }
    }
}

// ---------------- wahs GEMM, storing transposed: g_wahsT[b][s][h] --------------------
__global__ void gemm_wahsT(const float* __restrict__ A, const float* __restrict__ B)
{
    __shared__ __align__(16) float As[16][64];
    __shared__ __align__(16) float Bs[16][64];
    int tid = threadIdx.x;
    int tx = tid & 15, ty = tid >> 4;
    int n0 = blockIdx.x * 64, m0 = blockIdx.y * 64;
    float acc[4][4] = {};

    for (int k0 = 0; k0 < 2 * Hn; k0 += 16) {
#pragma unroll
        for (int qq = 0; qq < 4; qq++) {
            int idx = tid + qq * 256;
            int kk = idx & 15, m = idx >> 4;
            As[kk][m] = A[(m0 + m) * (2 * Hn) + k0 + kk];
            Bs[kk][m] = B[(n0 + m) * (2 * Hn) + k0 + kk];
        }
        __syncthreads();
#pragma unroll
        for (int kk = 0; kk < 16; kk++) {
            float4 a4 = *reinterpret_cast<const float4*>(&As[kk][ty * 4]);
            float4 b4 = *reinterpret_cast<const float4*>(&Bs[kk][tx * 4]);
            float av[4] = {a4.x, a4.y, a4.z, a4.w};
            float bv[4] = {b4.x, b4.y, b4.z, b4.w};
#pragma unroll
            for (int i = 0; i < 4; i++)
#pragma unroll
                for (int j = 0; j < 4; j++)
                    acc[i][j] += av[i] * bv[j];
        }
        __syncthreads();
    }
#pragma unroll
    for (int i = 0; i < 4; i++) {
        int row = m0 + ty * 4 + i;     // row = s*Bn + b
        int s = row >> 6, bb = row & 63;
#pragma unroll
        for (int j = 0; j < 4; j++) {
            int col = n0 + tx * 4 + j;
            g_wahsT[bb][s][col] = acc[i][j];
        }
    }
}

// ---------------- fused logits GEMM: out = sfin@w_b^T + ctx@v_b^T --------------------
__global__ void gemm_logits(const float* __restrict__ A1, const float* __restrict__ B1,
                            const float* __restrict__ A2, const float* __restrict__ B2,
                            float* __restrict__ C)
{
    __shared__ __align__(16) float As[16][64];
    __shared__ __align__(16) float Bs[16][64];
    int tid = threadIdx.x;
    int tx = tid & 15, ty = tid >> 4;
    int n0 = blockIdx.x * 64;
    float acc[4][4] = {};

    for (int k0 = 0; k0 < Hn; k0 += 16) {
#pragma unroll
        for (int qq = 0; qq < 4; qq++) {
            int idx = tid + qq * 256;
            int kk = idx & 15, m = idx >> 4;
            As[kk][m] = A1[m * Hn + k0 + kk];
            Bs[kk][m] = B1[(n0 + m) * Hn + k0 + kk];
        }
        __syncthreads();
#pragma unroll
        for (int kk = 0; kk < 16; kk++) {
            float4 a4 = *reinterpret_cast<const float4*>(&As[kk][ty * 4]);
            float4 b4 = *reinterpret_cast<const float4*>(&Bs[kk][tx * 4]);
            float av[4] = {a4.x, a4.y, a4.z, a4.w};
            float bv[4] = {b4.x, b4.y, b4.z, b4.w};
#pragma unroll
            for (int i = 0; i < 4; i++)
#pragma unroll
                for (int j = 0; j < 4; j++)
                    acc[i][j] += av[i] * bv[j];
        }
        __syncthreads();
    }
    for (int k0 = 0; k0 < 2 * Hn; k0 += 16) {
#pragma unroll
        for (int qq = 0; qq < 4; qq++) {
            int idx = tid + qq * 256;
            int kk = idx & 15, m = idx >> 4;
            As[kk][m] = A2[m * 2 * Hn + k0 + kk];
            Bs[kk][m] = B2[(n0 + m) * 2 * Hn + k0 + kk];
        }
        __syncthreads();
#pragma unroll
        for (int kk = 0; kk < 16; kk++) {
            float4 a4 = *reinterpret_cast<const float4*>(&As[kk][ty * 4]);
            float4 b4 = *reinterpret_cast<const float4*>(&Bs[kk][tx * 4]);
            float av[4] = {a4.x, a4.y, a4.z, a4.w};
            float bv[4] = {b4.x, b4.y, b4.z, b4.w};
#pragma unroll
            for (int i = 0; i < 4; i++)
#pragma unroll
                for (int j = 0; j < 4; j++)
                    acc[i][j] += av[i] * bv[j];
        }
        __syncthreads();
    }
#pragma unroll
    for (int i = 0; i < 4; i++) {
        int row = ty * 4 + i;
#pragma unroll
        for (int j = 0; j < 4; j++)
            C[row * Cv + n0 + tx * 4 + j] = acc[i][j];
    }
}

// ---------------- encoder recurrence: smem-cached half of Whh, writes hs + hsT -------
__global__ void encoder_rec(const float* __restrict__ Whh_f, const float* __restrict__ Whh_b)
{
    extern __shared__ __align__(16) float ws[];
    __shared__ __align__(16) float h_sm[Hn];
    __shared__ float c_sm[Hn];
    __shared__ float gate_sm[G4H];
    int b = blockIdx.x, dir = blockIdx.y;
    const float* __restrict__ Whh = dir ? Whh_b : Whh_f;
    int tid = threadIdx.x;  // 512

    for (int idx = tid; idx < 256 * 128; idx += 512) {
        int r = idx >> 7, c = idx & 127;
        ws[r * 132 + c] = Whh[idx];
    }
    if (tid < Hn) { h_sm[tid] = 0.f; c_sm[tid] = 0.f; }
    __syncthreads();

    const float4* __restrict__ wS = reinterpret_cast<const float4*>(ws + tid * 132);
    const float4* __restrict__ wG = reinterpret_cast<const float4*>(Whh + tid * Hn);
    const float4* h4 = reinterpret_cast<const float4*>(h_sm);
    bool use_smem = (tid < 256);

    for (int step = 0; step < Sn; step++) {
        int t = dir ? (Sn - 1 - step) : step;
        float a0 = 0.f, a1 = 0.f, a2 = 0.f, a3 = 0.f;
        if (use_smem) {
#pragma unroll
            for (int k = 0; k < 32; k += 4) {
                float4 w0 = wS[k + 0]; float4 h0 = h4[k + 0];
                float4 w1 = wS[k + 1]; float4 h1 = h4[k + 1];
                float4 w2 = wS[k + 2]; float4 h2 = h4[k + 2];
                float4 w3 = wS[k + 3]; float4 h3 = h4[k + 3];
                a0 += w0.x * h0.x + w0.y * h0.y + w0.z * h0.z + w0.w * h0.w;
                a1 += w1.x * h1.x + w1.y * h1.y + w1.z * h1.z + w1.w * h1.w;
                a2 += w2.x * h2.x + w2.y * h2.y + w2.z * h2.z + w2.w * h2.w;
                a3 += w3.x * h3.x + w3.y * h3.y + w3.z * h3.z + w3.w * h3.w;
            }
        } else {
#pragma unroll
            for (int k = 0; k < 32; k += 4) {
                float4 w0 = __ldg(&wG[k + 0]); float4 h0 = h4[k + 0];
                float4 w1 = __ldg(&wG[k + 1]); float4 h1 = h4[k + 1];
                float4 w2 = __ldg(&wG[k + 2]); float4 h2 = h4[k + 2];
                float4 w3 = __ldg(&wG[k + 3]); float4 h3 = h4[k + 3];
                a0 += w0.x * h0.x + w0.y * h0.y + w0.z * h0.z + w0.w * h0.w;
                a1 += w1.x * h1.x + w1.y * h1.y + w1.z * h1.z + w1.w * h1.w;
                a2 += w2.x * h2.x + w2.y * h2.y + w2.z * h2.z + w2.w * h2.w;
                a3 += w3.x * h3.x + w3.y * h3.y + w3.z * h3.z + w3.w * h3.w;
            }
        }
        gate_sm[tid] = g_xpre[dir][t][b][tid] + ((a0 + a1) + (a2 + a3));
        __syncthreads();
        if (tid < Hn) {
            float gi = gate_sm[tid], gf = gate_sm[tid + 128];
            float gg = gate_sm[tid + 256], go = gate_sm[tid + 384];
            float c = sigf(gf) * c_sm[tid] + sigf(gi) * tanhf(gg);
            float h = sigf(go) * tanhf(c);
            c_sm[tid] = c; h_sm[tid] = h;
            int j = dir * Hn + tid;
            g_hs[t][b][j] = h;
            g_hsT[b][j][t] = h;
        }
        __syncthreads();
    }
}

// ---------------- cluster-pair persistent decoder: 128 CTAs (2 per batch) ------------
// CTA rank h: scores/ctx for s in [h*256,(h+1)*256), gates/cell for j in [h*64,(h+1)*64)
// Max-free softmax (|e| <= ||u||_1 ~ 5.1, exp safe in fp32; mathematically identical).
// 5 syncthreads + 2 cluster barriers per step.
__global__ void __launch_bounds__(512, 1) __cluster_dims__(2, 1, 1)
decoder_persist(const float* __restrict__ mask, const float* __restrict__ va,
                const float* __restrict__ ua,
                const float* __restrict__ Wih, const float* __restrict__ Whh,
                const float* __restrict__ bih, const float* __restrict__ bhh)
{
    extern __shared__ __align__(16) float wc[];          // [128][388]
    __shared__ __align__(16) float s_sm[2][Hn];          // full hidden, dbl-buffered
    __shared__ __align__(16) float y_sm[64];             // owned cell state
    __shared__ __align__(16) float vas_sm[Hn];
    __shared__ __align__(16) float u_sm[Hn];
    __shared__ __align__(16) float e_sm[256];            // local-half exp (unnorm)
    __shared__ __align__(16) float ctxp_sm[2*Hn];        // my unnormalized partial ctx
    __shared__ __align__(16) float xin_sm[384];
    __shared__ __align__(16) float mask_sm[256];
    __shared__ __align__(16) float bias_sm[256];
    __shared__ __align__(16) float gates_sm[256];
    __shared__ __align__(16) float xch_ctx[2][2*Hn];     // peer writes partial ctx here
    __shared__ __align__(16) float xch_s[2];             // peer writes its exp-sum here
    __shared__ float red[16];
    __shared__ float S_loc[2];                           // my local exp-sum, per parity

    uint32_t rank;
    asm("mov.u32 %0, %%cluster_ctarank;" : "=r"(rank));
    int h = (int)rank;
    int b = blockIdx.x >> 1;
    int tid = threadIdx.x;                  // 512
    int w = tid >> 5, l = tid & 31;
    int g = tid >> 3, q = tid & 7;          // 64 groups of 8 lanes

    uint32_t peer_xctx = mapa_peer(smem_u32(&xch_ctx[0][0]), rank ^ 1);
    uint32_t peer_xs   = mapa_peer(smem_u32(&xch_s[0]),      rank ^ 1);
    uint32_t peer_s    = mapa_peer(smem_u32(&s_sm[0][0]),    rank ^ 1);

    // owned weight cache: quads i,f,g,o restricted to owned j-half
    for (int idx = tid; idx < 128 * 384; idx += 512) {
        int lr = idx / 384, c = idx - lr * 384;
        int r = (lr >> 6) * 128 + h * 64 + (lr & 63);
        wc[lr * 388 + c] = (c < 128) ? Whh[r * 128 + c] : Wih[r * 256 + (c - 128)];
    }
    if (tid < 256) {
        int r = (tid >> 6) * 128 + h * 64 + (tid & 63);
        bias_sm[tid] = bih[r] + bhh[r];
        mask_sm[tid] = mask[(h * 256 + tid) * Bn + b];
    }
    if (tid < Hn) { u_sm[tid] = ua[tid]; s_sm[0][tid] = 0.f; }
    if (tid < 64) y_sm[tid] = 0.f;
    __syncthreads();

    const float4* va4    = reinterpret_cast<const float4*>(va);
    const float4* Whh4   = reinterpret_cast<const float4*>(Whh);
    const float4* Wih4   = reinterpret_cast<const float4*>(Wih);
    const float4* wahsT4 = reinterpret_cast<const float4*>(&g_wahsT[0][0][0]);
    const float4* hsT4   = reinterpret_cast<const float4*>(&g_hsT[0][0][0]);
    const float4* u4     = reinterpret_cast<const float4*>(u_sm);
    const float4* vas4   = reinterpret_cast<const float4*>(vas_sm);
    const float4* e4p    = reinterpret_cast<const float4*>(e_sm);
    const float4* xin4   = reinterpret_cast<const float4*>(xin_sm);

    for (int t = 0; t < Tn; t++) {
        int par = t & 1;
        const float4* s4 = reinterpret_cast<const float4*>(&s_sm[par][0]);

        // ---- vas[j] = v_a[j] . s  (redundant full 128; 2 rows per group) ----
#pragma unroll
        for (int p = 0; p < 2; p++) {
            int j = p * 64 + g;
            float acc = 0.f;
#pragma unroll
            for (int k = 0; k < 4; k++) {
                int f = q + k * 8;
                float4 W = __ldg(&va4[j * 32 + f]);
                float4 X = s4[f];
                acc += W.x * X.x + W.y * X.y + W.z * X.z + W.w * X.w;
            }
            acc = gred8(acc);
            if (q == 0) vas_sm[j] = acc;
        }
        __syncthreads();                                        // sync 1

        // ---- scores + exp (max-free) + per-warp sum  (4 s per group) ----
        {
            float4 V[4], U[4];
#pragma unroll
            for (int k = 0; k < 4; k++) { V[k] = vas4[q + k * 8]; U[k] = u4[q + k * 8]; }
            float stacc = 0.f;
#pragma unroll
            for (int p = 0; p < 4; p++) {
                int sl = p * 64 + g;
                int s = h * 256 + sl;
                float acc = 0.f;
#pragma unroll
                for (int k = 0; k < 4; k++) {
                    float4 A = __ldg(&wahsT4[(b * Sn + s) * 32 + q + k * 8]);
                    acc += tanh_fast(A.x + V[k].x) * U[k].x + tanh_fast(A.y + V[k].y) * U[k].y +
                           tanh_fast(A.z + V[k].z) * U[k].z + tanh_fast(A.w + V[k].w) * U[k].w;
                }
                acc = gred8(acc);                 // all 8 lanes hold group total
                float ex = __expf(acc * mask_sm[sl]);
                if (q == 0) e_sm[sl] = ex;
                stacc += ex;
            }
            // warp sum: 4 groups/warp, each group's value replicated on its 8 lanes
            stacc += __shfl_xor_sync(0xFFFFFFFFu, stacc, 8);
            stacc += __shfl_xor_sync(0xFFFFFFFFu, stacc, 16);
            if (l == 0) red[w] = stacc;
        }
        __syncthreads();                                        // sync 2

        // ---- unnormalized partial ctx over my s-half (4 j per group);
        //      tid0 finishes the exp-sum first ----
        if (tid == 0) {
            float ss = red[0];
#pragma unroll
            for (int i = 1; i < 16; i++) ss += red[i];
            S_loc[par] = ss;
        }
#pragma unroll
        for (int p = 0; p < 4; p++) {
            int j = p * 64 + g;
            const float4* hp = &hsT4[(b * 2 * Hn + j) * 128 + h * 64];
            float acc = 0.f;
#pragma unroll
            for (int k = 0; k < 8; k++) {
                int f = q + k * 8;
                float4 H = __ldg(&hp[f]);
                float4 A = e4p[f];
                acc += H.x * A.x + H.y * A.y + H.z * A.z + H.w * A.w;
            }
            acc = gred8(acc);
            if (q == 0) ctxp_sm[j] = acc;
        }
        __syncthreads();                                        // sync 3

        // ---- exchange (sum, partial ctx) via DSMEM; cluster barrier ----
        if (tid < 256) st_remote_f32(peer_xctx + (par * 256 + tid) * 4, ctxp_sm[tid]);
        if (tid == 0)  st_remote_f32(peer_xs + par * 4, S_loc[par]);
        cluster_barrier();                                      // cluster 1

        // ---- xin = [ s ; (ctxp_me + ctxp_peer) / (S_me + S_peer) ] ----
        if (tid < 128) xin_sm[tid] = s_sm[par][tid];
        else if (tid < 384) {
            int j = tid - 128;
            float inv = 1.f / (S_loc[par] + xch_s[par]);
            xin_sm[tid] = (ctxp_sm[j] + xch_ctx[par][j]) * inv;
        }
        __syncthreads();                                        // sync 4
        if (t == Tn - 1 && h == 0 && tid < 256) g_ctx[b][tid] = xin_sm[128 + tid];

        // ---- gates for owned rows (4 per group: quads i,f,g,o of owned j) ----
#pragma unroll
        for (int p = 0; p < 4; p++) {
            int lr = p * 64 + g;
            float acc = 0.f;
            if (p < 2) {
                const float4* wr = reinterpret_cast<const float4*>(wc + lr * 388);
#pragma unroll
                for (int k = 0; k < 12; k++) {
                    int f = q + k * 8;
                    float4 W = wr[f];
                    float4 X = xin4[f];
                    acc += W.x * X.x + W.y * X.y + W.z * X.z + W.w * X.w;
                }
            } else {
                int r = p * 128 + h * 64 + g;
#pragma unroll
                for (int k = 0; k < 4; k++) {
                    int f = q + k * 8;
                    float4 W = __ldg(&Whh4[r * 32 + f]);
                    float4 X = xin4[f];
                    acc += W.x * X.x + W.y * X.y + W.z * X.z + W.w * X.w;
                }
#pragma unroll
                for (int k = 4; k < 12; k++) {
                    int f = q + k * 8;
                    float4 W = __ldg(&Wih4[r * 64 + f - 32]);
                    float4 X = xin4[f];
                    acc += W.x * X.x + W.y * X.y + W.z * X.z + W.w * X.w;
                }
            }
            acc = gred8(acc);
            if (q == 0) gates_sm[lr] = acc + bias_sm[lr];
        }
        __syncthreads();                                        // sync 5

        // ---- cell for owned j; publish s-half to both CTAs ----
        if (tid < 64) {
            float gi = gates_sm[tid],       gf = gates_sm[64 + tid];
            float gg = gates_sm[128 + tid], go = gates_sm[192 + tid];
            float y = sigf(gf) * y_sm[tid] + sigf(gi) * tanhf(gg);
            float s = sigf(go) * tanhf(y);
            y_sm[tid] = y;
            int jg = h * 64 + tid;
            s_sm[par ^ 1][jg] = s;
            st_remote_f32(peer_s + ((par ^ 1) * 128 + jg) * 4, s);
            if (t == Tn - 1) g_sfin[b][jg] = s;
        }
        cluster_barrier();                                      // cluster 2
    }
}

// ---------------- final softmax over C=32000 -----------------------------------------
__global__ void softmax_stat(const float* __restrict__ out)
{
    int b = blockIdx.x, tid = threadIdx.x;
    __shared__ float red[256];
    const float* row = out + b * Cv;
    float m = -1e30f;
    for (int i = tid; i < Cv; i += 256) m = fmaxf(m, row[i]);
    red[tid] = m; __syncthreads();
#pragma unroll
    for (int st = 128; st; st >>= 1) {
        if (tid < st) red[tid] = fmaxf(red[tid], red[tid + st]);
        __syncthreads();
    }
    m = red[0]; __syncthreads();
    float s = 0.f;
    for (int i = tid; i < Cv; i += 256) s += __expf(row[i] - m);
    red[tid] = s; __syncthreads();
#pragma unroll
    for (int st = 128; st; st >>= 1) {
        if (tid < st) red[tid] += red[tid + st];
        __syncthreads();
    }
    if (tid == 0) { g_rowstat[b][0] = m; g_rowstat[b][1] = 1.f / red[0]; }
}

__global__ void softmax_norm(float* out)
{
    int b = blockIdx.y;
    int i = blockIdx.x * 256 + threadIdx.x;     // Cv = 125*256 exactly
    float* row = out + b * Cv;
    row[i] = __expf(row[i] - g_rowstat[b][0]) * g_rowstat[b][1];
}

// ---------------- launch -------------------------------------------------------------
extern "C" void kernel_launch(void* const* d_in, const int* in_sizes, int n_in,
                              void* d_out, int out_size)
{
    (void)in_sizes; (void)n_in; (void)out_size;
    const float* x      = (const float*)d_in[0];
    const float* mask   = (const float*)d_in[1];
    const float* eWih_f = (const float*)d_in[2];
    const float* eWhh_f = (const float*)d_in[3];
    const float* ebih_f = (const float*)d_in[4];
    const float* ebhh_f = (const float*)d_in[5];
    const float* eWih_b = (const float*)d_in[6];
    const float* eWhh_b = (const float*)d_in[7];
    const float* ebih_b = (const float*)d_in[8];
    const float* ebhh_b = (const float*)d_in[9];
    const float* dWih   = (const float*)d_in[10];
    const float* dWhh   = (const float*)d_in[11];
    const float* dbih   = (const float*)d_in[12];
    const float* dbhh   = (const float*)d_in[13];
    const float* w_a    = (const float*)d_in[14];
    const float* v_a    = (const float*)d_in[15];
    const float* u_a    = (const float*)d_in[16];
    const float* w_b    = (const float*)d_in[17];
    const float* v_b    = (const float*)d_in[18];
    float* out = (float*)d_out;

    float *p_xpre, *p_hs, *p_sfin, *p_ctx;
    cudaGetSymbolAddress((void**)&p_xpre, g_xpre);
    cudaGetSymbolAddress((void**)&p_hs,   g_hs);
    cudaGetSymbolAddress((void**)&p_sfin, g_sfin);
    cudaGetSymbolAddress((void**)&p_ctx,  g_ctx);

    cudaFuncSetAttribute(encoder_rec, cudaFuncAttributeMaxDynamicSharedMemorySize, 256 * 132 * 4);
    cudaFuncSetAttribute(decoder_persist, cudaFuncAttributeMaxDynamicSharedMemorySize, 128 * 388 * 4);

    // 1) xpre = x @ Wih^T + biases (both directions, one launch)
    gemm_xpre<<<dim3(8, 512, 2), 256>>>(x, eWih_f, eWih_b, ebih_f, ebhh_f, ebih_b, ebhh_b, p_xpre);

    // 2) encoder recurrence (writes g_hs and g_hsT)
    encoder_rec<<<dim3(Bn, 2), 512, 256 * 132 * 4>>>(eWhh_f, eWhh_b);

    // 3) wa_hs = h_s @ w_a^T, stored transposed per-b
    gemm_wahsT<<<dim3(2, 512), 256>>>(p_hs, w_a);

    // 4) cluster-pair persistent decoder (2 CTAs per batch, cluster-barrier handshakes)
    decoder_persist<<<2 * Bn, 512, 128 * 388 * 4>>>(mask, v_a, u_a, dWih, dWhh, dbih, dbhh);

    // 5) logits (one fused GEMM) + softmax
    gemm_logits<<<dim3(Cv / 64, 1), 256>>>(p_sfin, w_b, p_ctx, v_b, out);
    softmax_stat<<<Bn, 256>>>(out);
    softmax_norm<<<dim3(Cv / 256, Bn), 256>>>(out);
}

// round 13
// speedup vs baseline: 2.3100x; 1.1285x over previous
#include <cuda_runtime.h>
#include <cstdint>

#define Sn 512
#define Bn 64
#define En 256
#define Hn 128
#define G4H 512
#define Tn 128
#define Cv 32000

// ---------------- scratch (static device globals; no allocation) ----------------
__device__ float g_xpre[2][Sn][Bn][G4H];     // precomputed x@Wih^T + biases
__device__ float g_hs[Sn][Bn][2*Hn];         // encoder outputs (concat fwd|bwd)
__device__ float g_hsT[Bn][2*Hn][Sn];        // transposed: per-b, j-major, s-contiguous
__device__ float g_wahsT[Bn][Sn][Hn];        // w_a @ h_s, transposed per-b contiguous
__device__ float g_sfin[Bn][Hn];             // final decoder hidden
__device__ float g_ctx[Bn][2*Hn];            // final ctx
__device__ float g_rowstat[Bn][2];           // softmax max, 1/sum

__device__ __forceinline__ float sigf(float x) { return 1.f / (1.f + __expf(-x)); }
__device__ __forceinline__ float tanh_fast(float x) {
    float y; asm("tanh.approx.f32 %0, %1;" : "=f"(y) : "f"(x)); return y;
}
__device__ __forceinline__ float gred8(float v) {
    v += __shfl_xor_sync(0xFFFFFFFFu, v, 1);
    v += __shfl_xor_sync(0xFFFFFFFFu, v, 2);
    v += __shfl_xor_sync(0xFFFFFFFFu, v, 4);
    return v;
}

// ---------------- cluster / DSMEM helpers -------------------------------------------
__device__ __forceinline__ uint32_t smem_u32(const void* p) {
    uint32_t a;
    asm("{ .reg .u64 t; cvta.to.shared.u64 t, %1; cvt.u32.u64 %0, t; }" : "=r"(a) : "l"(p));
    return a;
}
__device__ __forceinline__ uint32_t mapa_peer(uint32_t a, uint32_t rank) {
    uint32_t r; asm("mapa.shared::cluster.u32 %0, %1, %2;" : "=r"(r) : "r"(a), "r"(rank));
    return r;
}
__device__ __forceinline__ void st_remote_f32(uint32_t a, float v) {
    asm volatile("st.shared::cluster.f32 [%0], %1;" :: "r"(a), "f"(v) : "memory");
}
__device__ __forceinline__ void cluster_barrier() {
    asm volatile("barrier.cluster.arrive.aligned;" ::: "memory");
    asm volatile("barrier.cluster.wait.aligned;" ::: "memory");
}

// ================= fast SGEMM core: 128x128 tile, BK=8, 8x8 microtile ================
// C[M,N] = A[M,K] @ B[N,K]^T, strided fragments (rows ty*4, 64+ty*4; cols tx*4, 64+tx*4)
// smem padded to 132 to kill scatter-store bank conflicts.

#define SG_PAD 132

// ---- variant 1: xpre (both dirs via blockIdx.z, bias epilogue, C row stride G4H) ----
__global__ void __launch_bounds__(256, 2) sgemm_xpre(
    const float* __restrict__ A,
    const float* __restrict__ B0, const float* __restrict__ B1,
    const float* __restrict__ bi0, const float* __restrict__ bh0,
    const float* __restrict__ bi1, const float* __restrict__ bh1,
    float* __restrict__ Cbase)
{
    int dir = blockIdx.z;
    const float* __restrict__ B  = dir ? B1 : B0;
    const float* __restrict__ bi = dir ? bi1 : bi0;
    const float* __restrict__ bh = dir ? bh1 : bh0;
    float* __restrict__ C = Cbase + (size_t)dir * Sn * Bn * G4H;
    const int K = En;

    __shared__ __align__(16) float As[2][8][SG_PAD];
    __shared__ __align__(16) float Bs[2][8][SG_PAD];

    int tid = threadIdx.x;
    int tx = tid & 15, ty = tid >> 4;
    int m0 = blockIdx.y * 128, n0 = blockIdx.x * 128;
    int lrow = tid >> 1, lk = (tid & 1) * 4;

    const float* Aload = A + (size_t)(m0 + lrow) * K + lk;
    const float* Bload = B + (size_t)(n0 + lrow) * K + lk;

    float acc[8][8] = {};
    float4 ra = *reinterpret_cast<const float4*>(Aload);
    float4 rb = *reinterpret_cast<const float4*>(Bload);
    As[0][lk+0][lrow]=ra.x; As[0][lk+1][lrow]=ra.y; As[0][lk+2][lrow]=ra.z; As[0][lk+3][lrow]=ra.w;
    Bs[0][lk+0][lrow]=rb.x; Bs[0][lk+1][lrow]=rb.y; Bs[0][lk+2][lrow]=rb.z; Bs[0][lk+3][lrow]=rb.w;
    __syncthreads();

    int nkb = K >> 3, buf = 0;
    for (int kb = 0; kb < nkb; kb++) {
        if (kb + 1 < nkb) {
            ra = *reinterpret_cast<const float4*>(Aload + (kb + 1) * 8);
            rb = *reinterpret_cast<const float4*>(Bload + (kb + 1) * 8);
        }
#pragma unroll
        for (int k = 0; k < 8; k++) {
            float4 a0 = *reinterpret_cast<const float4*>(&As[buf][k][ty * 4]);
            float4 a1 = *reinterpret_cast<const float4*>(&As[buf][k][ty * 4 + 64]);
            float4 b0 = *reinterpret_cast<const float4*>(&Bs[buf][k][tx * 4]);
            float4 b1 = *reinterpret_cast<const float4*>(&Bs[buf][k][tx * 4 + 64]);
            float av[8] = {a0.x,a0.y,a0.z,a0.w,a1.x,a1.y,a1.z,a1.w};
            float bv[8] = {b0.x,b0.y,b0.z,b0.w,b1.x,b1.y,b1.z,b1.w};
#pragma unroll
            for (int i = 0; i < 8; i++)
#pragma unroll
                for (int j = 0; j < 8; j++)
                    acc[i][j] += av[i] * bv[j];
        }
        if (kb + 1 < nkb) {
            int nb = buf ^ 1;
            As[nb][lk+0][lrow]=ra.x; As[nb][lk+1][lrow]=ra.y; As[nb][lk+2][lrow]=ra.z; As[nb][lk+3][lrow]=ra.w;
            Bs[nb][lk+0][lrow]=rb.x; Bs[nb][lk+1][lrow]=rb.y; Bs[nb][lk+2][lrow]=rb.z; Bs[nb][lk+3][lrow]=rb.w;
        }
        __syncthreads();
        buf ^= 1;
    }
#pragma unroll
    for (int i = 0; i < 8; i++) {
        int row = m0 + ((i < 4) ? (ty * 4 + i) : (64 + ty * 4 + i - 4));
#pragma unroll
        for (int jh = 0; jh < 2; jh++) {
            int col = n0 + tx * 4 + jh * 64;
            float4 v;
            v.x = acc[i][jh*4+0] + bi[col+0] + bh[col+0];
            v.y = acc[i][jh*4+1] + bi[col+1] + bh[col+1];
            v.z = acc[i][jh*4+2] + bi[col+2] + bh[col+2];
            v.w = acc[i][jh*4+3] + bi[col+3] + bh[col+3];
            *reinterpret_cast<float4*>(&C[(size_t)row * G4H + col]) = v;
        }
    }
}

// ---- variant 2: wahs with transposed store into g_wahsT[b][s][h] (N=128, K=256) -----
__global__ void __launch_bounds__(256, 2) sgemm_wahsT(
    const float* __restrict__ A, const float* __restrict__ B)
{
    const int K = 2 * Hn;

    __shared__ __align__(16) float As[2][8][SG_PAD];
    __shared__ __align__(16) float Bs[2][8][SG_PAD];

    int tid = threadIdx.x;
    int tx = tid & 15, ty = tid >> 4;
    int m0 = blockIdx.y * 128;
    int lrow = tid >> 1, lk = (tid & 1) * 4;

    const float* Aload = A + (size_t)(m0 + lrow) * K + lk;
    const float* Bload = B + (size_t)lrow * K + lk;     // n0 = 0 (N=128)

    float acc[8][8] = {};
    float4 ra = *reinterpret_cast<const float4*>(Aload);
    float4 rb = *reinterpret_cast<const float4*>(Bload);
    As[0][lk+0][lrow]=ra.x; As[0][lk+1][lrow]=ra.y; As[0][lk+2][lrow]=ra.z; As[0][lk+3][lrow]=ra.w;
    Bs[0][lk+0][lrow]=rb.x; Bs[0][lk+1][lrow]=rb.y; Bs[0][lk+2][lrow]=rb.z; Bs[0][lk+3][lrow]=rb.w;
    __syncthreads();

    int nkb = K >> 3, buf = 0;
    for (int kb = 0; kb < nkb; kb++) {
        if (kb + 1 < nkb) {
            ra = *reinterpret_cast<const float4*>(Aload + (kb + 1) * 8);
            rb = *reinterpret_cast<const float4*>(Bload + (kb + 1) * 8);
        }
#pragma unroll
        for (int k = 0; k < 8; k++) {
            float4 a0 = *reinterpret_cast<const float4*>(&As[buf][k][ty * 4]);
            float4 a1 = *reinterpret_cast<const float4*>(&As[buf][k][ty * 4 + 64]);
            float4 b0 = *reinterpret_cast<const float4*>(&Bs[buf][k][tx * 4]);
            float4 b1 = *reinterpret_cast<const float4*>(&Bs[buf][k][tx * 4 + 64]);
            float av[8] = {a0.x,a0.y,a0.z,a0.w,a1.x,a1.y,a1.z,a1.w};
            float bv[8] = {b0.x,b0.y,b0.z,b0.w,b1.x,b1.y,b1.z,b1.w};
#pragma unroll
            for (int i = 0; i < 8; i++)
#pragma unroll
                for (int j = 0; j < 8; j++)
                    acc[i][j] += av[i] * bv[j];
        }
        if (kb + 1 < nkb) {
            int nb = buf ^ 1;
            As[nb][lk+0][lrow]=ra.x; As[nb][lk+1][lrow]=ra.y; As[nb][lk+2][lrow]=ra.z; As[nb][lk+3][lrow]=ra.w;
            Bs[nb][lk+0][lrow]=rb.x; Bs[nb][lk+1][lrow]=rb.y; Bs[nb][lk+2][lrow]=rb.z; Bs[nb][lk+3][lrow]=rb.w;
        }
        __syncthreads();
        buf ^= 1;
    }
#pragma unroll
    for (int i = 0; i < 8; i++) {
        int row = m0 + ((i < 4) ? (ty * 4 + i) : (64 + ty * 4 + i - 4));
        int s = row >> 6, bb = row & 63;    // row = s*Bn + b
#pragma unroll
        for (int jh = 0; jh < 2; jh++) {
            int col = tx * 4 + jh * 64;
            float4 v;
            v.x = acc[i][jh*4+0]; v.y = acc[i][jh*4+1];
            v.z = acc[i][jh*4+2]; v.w = acc[i][jh*4+3];
            *reinterpret_cast<float4*>(&g_wahsT[bb][s][col]) = v;
        }
    }
}

// ---------------- fused logits GEMM: out = sfin@w_b^T + ctx@v_b^T --------------------
__global__ void gemm_logits(const float* __restrict__ A1, const float* __restrict__ B1,
                            const float* __restrict__ A2, const float* __restrict__ B2,
                            float* __restrict__ C)
{
    __shared__ __align__(16) float As[16][64];
    __shared__ __align__(16) float Bs[16][64];
    int tid = threadIdx.x;
    int tx = tid & 15, ty = tid >> 4;
    int n0 = blockIdx.x * 64;
    float acc[4][4] = {};

    for (int k0 = 0; k0 < Hn; k0 += 16) {
#pragma unroll
        for (int qq = 0; qq < 4; qq++) {
            int idx = tid + qq * 256;
            int kk = idx & 15, m = idx >> 4;
            As[kk][m] = A1[m * Hn + k0 + kk];
            Bs[kk][m] = B1[(n0 + m) * Hn + k0 + kk];
        }
        __syncthreads();
#pragma unroll
        for (int kk = 0; kk < 16; kk++) {
            float4 a4 = *reinterpret_cast<const float4*>(&As[kk][ty * 4]);
            float4 b4 = *reinterpret_cast<const float4*>(&Bs[kk][tx * 4]);
            float av[4] = {a4.x, a4.y, a4.z, a4.w};
            float bv[4] = {b4.x, b4.y, b4.z, b4.w};
#pragma unroll
            for (int i = 0; i < 4; i++)
#pragma unroll
                for (int j = 0; j < 4; j++)
                    acc[i][j] += av[i] * bv[j];
        }
        __syncthreads();
    }
    for (int k0 = 0; k0 < 2 * Hn; k0 += 16) {
#pragma unroll
        for (int qq = 0; qq < 4; qq++) {
            int idx = tid + qq * 256;
            int kk = idx & 15, m = idx >> 4;
            As[kk][m] = A2[m * 2 * Hn + k0 + kk];
            Bs[kk][m] = B2[(n0 + m) * 2 * Hn + k0 + kk];
        }
        __syncthreads();
#pragma unroll
        for (int kk = 0; kk < 16; kk++) {
            float4 a4 = *reinterpret_cast<const float4*>(&As[kk][ty * 4]);
            float4 b4 = *reinterpret_cast<const float4*>(&Bs[kk][tx * 4]);
            float av[4] = {a4.x, a4.y, a4.z, a4.w};
            float bv[4] = {b4.x, b4.y, b4.z, b4.w};
#pragma unroll
            for (int i = 0; i < 4; i++)
#pragma unroll
                for (int j = 0; j < 4; j++)
                    acc[i][j] += av[i] * bv[j];
        }
        __syncthreads();
    }
#pragma unroll
    for (int i = 0; i < 4; i++) {
        int row = ty * 4 + i;
#pragma unroll
        for (int j = 0; j < 4; j++)
            C[row * Cv + n0 + tx * 4 + j] = acc[i][j];
    }
}

// ---------------- encoder recurrence: smem-cached half of Whh, writes hs + hsT -------
__global__ void encoder_rec(const float* __restrict__ Whh_f, const float* __restrict__ Whh_b)
{
    extern __shared__ __align__(16) float ws[];
    __shared__ __align__(16) float h_sm[Hn];
    __shared__ float c_sm[Hn];
    __shared__ float gate_sm[G4H];
    int b = blockIdx.x, dir = blockIdx.y;
    const float* __restrict__ Whh = dir ? Whh_b : Whh_f;
    int tid = threadIdx.x;  // 512

    for (int idx = tid; idx < 256 * 128; idx += 512) {
        int r = idx >> 7, c = idx & 127;
        ws[r * 132 + c] = Whh[idx];
    }
    if (tid < Hn) { h_sm[tid] = 0.f; c_sm[tid] = 0.f; }
    __syncthreads();

    const float4* __restrict__ wS = reinterpret_cast<const float4*>(ws + tid * 132);
    const float4* __restrict__ wG = reinterpret_cast<const float4*>(Whh + tid * Hn);
    const float4* h4 = reinterpret_cast<const float4*>(h_sm);
    bool use_smem = (tid < 256);

    for (int step = 0; step < Sn; step++) {
        int t = dir ? (Sn - 1 - step) : step;
        float a0 = 0.f, a1 = 0.f, a2 = 0.f, a3 = 0.f;
        if (use_smem) {
#pragma unroll
            for (int k = 0; k < 32; k += 4) {
                float4 w0 = wS[k + 0]; float4 h0 = h4[k + 0];
                float4 w1 = wS[k + 1]; float4 h1 = h4[k + 1];
                float4 w2 = wS[k + 2]; float4 h2 = h4[k + 2];
                float4 w3 = wS[k + 3]; float4 h3 = h4[k + 3];
                a0 += w0.x * h0.x + w0.y * h0.y + w0.z * h0.z + w0.w * h0.w;
                a1 += w1.x * h1.x + w1.y * h1.y + w1.z * h1.z + w1.w * h1.w;
                a2 += w2.x * h2.x + w2.y * h2.y + w2.z * h2.z + w2.w * h2.w;
                a3 += w3.x * h3.x + w3.y * h3.y + w3.z * h3.z + w3.w * h3.w;
            }
        } else {
#pragma unroll
            for (int k = 0; k < 32; k += 4) {
                float4 w0 = __ldg(&wG[k + 0]); float4 h0 = h4[k + 0];
                float4 w1 = __ldg(&wG[k + 1]); float4 h1 = h4[k + 1];
                float4 w2 = __ldg(&wG[k + 2]); float4 h2 = h4[k + 2];
                float4 w3 = __ldg(&wG[k + 3]); float4 h3 = h4[k + 3];
                a0 += w0.x * h0.x + w0.y * h0.y + w0.z * h0.z + w0.w * h0.w;
                a1 += w1.x * h1.x + w1.y * h1.y + w1.z * h1.z + w1.w * h1.w;
                a2 += w2.x * h2.x + w2.y * h2.y + w2.z * h2.z + w2.w * h2.w;
                a3 += w3.x * h3.x + w3.y * h3.y + w3.z * h3.z + w3.w * h3.w;
            }
        }
        gate_sm[tid] = g_xpre[dir][t][b][tid] + ((a0 + a1) + (a2 + a3));
        __syncthreads();
        if (tid < Hn) {
            float gi = gate_sm[tid], gf = gate_sm[tid + 128];
            float gg = gate_sm[tid + 256], go = gate_sm[tid + 384];
            float c = sigf(gf) * c_sm[tid] + sigf(gi) * tanhf(gg);
            float h = sigf(go) * tanhf(c);
            c_sm[tid] = c; h_sm[tid] = h;
            int j = dir * Hn + tid;
            g_hs[t][b][j] = h;
            g_hsT[b][j][t] = h;
        }
        __syncthreads();
    }
}

// ---------------- cluster-pair persistent decoder: 128 CTAs (2 per batch) ------------
__global__ void __launch_bounds__(512, 1) __cluster_dims__(2, 1, 1)
decoder_persist(const float* __restrict__ mask, const float* __restrict__ va,
                const float* __restrict__ ua,
                const float* __restrict__ Wih, const float* __restrict__ Whh,
                const float* __restrict__ bih, const float* __restrict__ bhh)
{
    extern __shared__ __align__(16) float wc[];          // [128][388]
    __shared__ __align__(16) float s_sm[2][Hn];
    __shared__ __align__(16) float y_sm[64];
    __shared__ __align__(16) float vas_sm[Hn];
    __shared__ __align__(16) float u_sm[Hn];
    __shared__ __align__(16) float e_sm[256];
    __shared__ __align__(16) float ctxp_sm[2*Hn];
    __shared__ __align__(16) float xin_sm[384];
    __shared__ __align__(16) float mask_sm[256];
    __shared__ __align__(16) float bias_sm[256];
    __shared__ __align__(16) float gates_sm[256];
    __shared__ __align__(16) float xch_ctx[2][2*Hn];
    __shared__ __align__(16) float xch_s[2];
    __shared__ float red[16];
    __shared__ float S_loc[2];

    uint32_t rank;
    asm("mov.u32 %0, %%cluster_ctarank;" : "=r"(rank));
    int h = (int)rank;
    int b = blockIdx.x >> 1;
    int tid = threadIdx.x;                  // 512
    int w = tid >> 5, l = tid & 31;
    int g = tid >> 3, q = tid & 7;

    uint32_t peer_xctx = mapa_peer(smem_u32(&xch_ctx[0][0]), rank ^ 1);
    uint32_t peer_xs   = mapa_peer(smem_u32(&xch_s[0]),      rank ^ 1);
    uint32_t peer_s    = mapa_peer(smem_u32(&s_sm[0][0]),    rank ^ 1);

    for (int idx = tid; idx < 128 * 384; idx += 512) {
        int lr = idx / 384, c = idx - lr * 384;
        int r = (lr >> 6) * 128 + h * 64 + (lr & 63);
        wc[lr * 388 + c] = (c < 128) ? Whh[r * 128 + c] : Wih[r * 256 + (c - 128)];
    }
    if (tid < 256) {
        int r = (tid >> 6) * 128 + h * 64 + (tid & 63);
        bias_sm[tid] = bih[r] + bhh[r];
        mask_sm[tid] = mask[(h * 256 + tid) * Bn + b];
    }
    if (tid < Hn) { u_sm[tid] = ua[tid]; s_sm[0][tid] = 0.f; }
    if (tid < 64) y_sm[tid] = 0.f;
    __syncthreads();

    const float4* va4    = reinterpret_cast<const float4*>(va);
    const float4* Whh4   = reinterpret_cast<const float4*>(Whh);
    const float4* Wih4   = reinterpret_cast<const float4*>(Wih);
    const float4* wahsT4 = reinterpret_cast<const float4*>(&g_wahsT[0][0][0]);
    const float4* hsT4   = reinterpret_cast<const float4*>(&g_hsT[0][0][0]);
    const float4* u4     = reinterpret_cast<const float4*>(u_sm);
    const float4* vas4   = reinterpret_cast<const float4*>(vas_sm);
    const float4* e4p    = reinterpret_cast<const float4*>(e_sm);
    const float4* xin4   = reinterpret_cast<const float4*>(xin_sm);

    for (int t = 0; t < Tn; t++) {
        int par = t & 1;
        const float4* s4 = reinterpret_cast<const float4*>(&s_sm[par][0]);

#pragma unroll
        for (int p = 0; p < 2; p++) {
            int j = p * 64 + g;
            float acc = 0.f;
#pragma unroll
            for (int k = 0; k < 4; k++) {
                int f = q + k * 8;
                float4 W = __ldg(&va4[j * 32 + f]);
                float4 X = s4[f];
                acc += W.x * X.x + W.y * X.y + W.z * X.z + W.w * X.w;
            }
            acc = gred8(acc);
            if (q == 0) vas_sm[j] = acc;
        }
        __syncthreads();

        {
            float4 V[4], U[4];
#pragma unroll
            for (int k = 0; k < 4; k++) { V[k] = vas4[q + k * 8]; U[k] = u4[q + k * 8]; }
            float stacc = 0.f;
#pragma unroll
            for (int p = 0; p < 4; p++) {
                int sl = p * 64 + g;
                int s = h * 256 + sl;
                float acc = 0.f;
#pragma unroll
                for (int k = 0; k < 4; k++) {
                    float4 A = __ldg(&wahsT4[(b * Sn + s) * 32 + q + k * 8]);
                    acc += tanh_fast(A.x + V[k].x) * U[k].x + tanh_fast(A.y + V[k].y) * U[k].y +
                           tanh_fast(A.z + V[k].z) * U[k].z + tanh_fast(A.w + V[k].w) * U[k].w;
                }
                acc = gred8(acc);
                float ex = __expf(acc * mask_sm[sl]);
                if (q == 0) e_sm[sl] = ex;
                stacc += ex;
            }
            stacc += __shfl_xor_sync(0xFFFFFFFFu, stacc, 8);
            stacc += __shfl_xor_sync(0xFFFFFFFFu, stacc, 16);
            if (l == 0) red[w] = stacc;
        }
        __syncthreads();

        if (tid == 0) {
            float ss = red[0];
#pragma unroll
            for (int i = 1; i < 16; i++) ss += red[i];
            S_loc[par] = ss;
        }
#pragma unroll
        for (int p = 0; p < 4; p++) {
            int j = p * 64 + g;
            const float4* hp = &hsT4[(b * 2 * Hn + j) * 128 + h * 64];
            float acc = 0.f;
#pragma unroll
            for (int k = 0; k < 8; k++) {
                int f = q + k * 8;
                float4 H = __ldg(&hp[f]);
                float4 A = e4p[f];
                acc += H.x * A.x + H.y * A.y + H.z * A.z + H.w * A.w;
            }
            acc = gred8(acc);
            if (q == 0) ctxp_sm[j] = acc;
        }
        __syncthreads();

        if (tid < 256) st_remote_f32(peer_xctx + (par * 256 + tid) * 4, ctxp_sm[tid]);
        if (tid == 0)  st_remote_f32(peer_xs + par * 4, S_loc[par]);
        cluster_barrier();

        if (tid < 128) xin_sm[tid] = s_sm[par][tid];
        else if (tid < 384) {
            int j = tid - 128;
            float inv = 1.f / (S_loc[par] + xch_s[par]);
            xin_sm[tid] = (ctxp_sm[j] + xch_ctx[par][j]) * inv;
        }
        __syncthreads();
        if (t == Tn - 1 && h == 0 && tid < 256) g_ctx[b][tid] = xin_sm[128 + tid];

#pragma unroll
        for (int p = 0; p < 4; p++) {
            int lr = p * 64 + g;
            float acc = 0.f;
            if (p < 2) {
                const float4* wr = reinterpret_cast<const float4*>(wc + lr * 388);
#pragma unroll
                for (int k = 0; k < 12; k++) {
                    int f = q + k * 8;
                    float4 W = wr[f];
                    float4 X = xin4[f];
                    acc += W.x * X.x + W.y * X.y + W.z * X.z + W.w * X.w;
                }
            } else {
                int r = p * 128 + h * 64 + g;
#pragma unroll
                for (int k = 0; k < 4; k++) {
                    int f = q + k * 8;
                    float4 W = __ldg(&Whh4[r * 32 + f]);
                    float4 X = xin4[f];
                    acc += W.x * X.x + W.y * X.y + W.z * X.z + W.w * X.w;
                }
#pragma unroll
                for (int k = 4; k < 12; k++) {
                    int f = q + k * 8;
                    float4 W = __ldg(&Wih4[r * 64 + f - 32]);
                    float4 X = xin4[f];
                    acc += W.x * X.x + W.y * X.y + W.z * X.z + W.w * X.w;
                }
            }
            acc = gred8(acc);
            if (q == 0) gates_sm[lr] = acc + bias_sm[lr];
        }
        __syncthreads();

        if (tid < 64) {
            float gi = gates_sm[tid],       gf = gates_sm[64 + tid];
            float gg = gates_sm[128 + tid], go = gates_sm[192 + tid];
            float y = sigf(gf) * y_sm[tid] + sigf(gi) * tanhf(gg);
            float s = sigf(go) * tanhf(y);
            y_sm[tid] = y;
            int jg = h * 64 + tid;
            s_sm[par ^ 1][jg] = s;
            st_remote_f32(peer_s + ((par ^ 1) * 128 + jg) * 4, s);
            if (t == Tn - 1) g_sfin[b][jg] = s;
        }
        cluster_barrier();
    }
}

// ---------------- final softmax over C=32000 -----------------------------------------
__global__ void softmax_stat(const float* __restrict__ out)
{
    int b = blockIdx.x, tid = threadIdx.x;
    __shared__ float red[256];
    const float* row = out + b * Cv;
    float m = -1e30f;
    for (int i = tid; i < Cv; i += 256) m = fmaxf(m, row[i]);
    red[tid] = m; __syncthreads();
#pragma unroll
    for (int st = 128; st; st >>= 1) {
        if (tid < st) red[tid] = fmaxf(red[tid], red[tid + st]);
        __syncthreads();
    }
    m = red[0]; __syncthreads();
    float s = 0.f;
    for (int i = tid; i < Cv; i += 256) s += __expf(row[i] - m);
    red[tid] = s; __syncthreads();
#pragma unroll
    for (int st = 128; st; st >>= 1) {
        if (tid < st) red[tid] += red[tid + st];
        __syncthreads();
    }
    if (tid == 0) { g_rowstat[b][0] = m; g_rowstat[b][1] = 1.f / red[0]; }
}

__global__ void softmax_norm(float* out)
{
    int b = blockIdx.y;
    int i = blockIdx.x * 256 + threadIdx.x;
    float* row = out + b * Cv;
    row[i] = __expf(row[i] - g_rowstat[b][0]) * g_rowstat[b][1];
}

// ---------------- launch -------------------------------------------------------------
extern "C" void kernel_launch(void* const* d_in, const int* in_sizes, int n_in,
                              void* d_out, int out_size)
{
    (void)in_sizes; (void)n_in; (void)out_size;
    const float* x      = (const float*)d_in[0];
    const float* mask   = (const float*)d_in[1];
    const float* eWih_f = (const float*)d_in[2];
    const float* eWhh_f = (const float*)d_in[3];
    const float* ebih_f = (const float*)d_in[4];
    const float* ebhh_f = (const float*)d_in[5];
    const float* eWih_b = (const float*)d_in[6];
    const float* eWhh_b = (const float*)d_in[7];
    const float* ebih_b = (const float*)d_in[8];
    const float* ebhh_b = (const float*)d_in[9];
    const float* dWih   = (const float*)d_in[10];
    const float* dWhh   = (const float*)d_in[11];
    const float* dbih   = (const float*)d_in[12];
    const float* dbhh   = (const float*)d_in[13];
    const float* w_a    = (const float*)d_in[14];
    const float* v_a    = (const float*)d_in[15];
    const float* u_a    = (const float*)d_in[16];
    const float* w_b    = (const float*)d_in[17];
    const float* v_b    = (const float*)d_in[18];
    float* out = (float*)d_out;

    float *p_xpre, *p_hs, *p_sfin, *p_ctx;
    cudaGetSymbolAddress((void**)&p_xpre, g_xpre);
    cudaGetSymbolAddress((void**)&p_hs,   g_hs);
    cudaGetSymbolAddress((void**)&p_sfin, g_sfin);
    cudaGetSymbolAddress((void**)&p_ctx,  g_ctx);

    cudaFuncSetAttribute(encoder_rec, cudaFuncAttributeMaxDynamicSharedMemorySize, 256 * 132 * 4);
    cudaFuncSetAttribute(decoder_persist, cudaFuncAttributeMaxDynamicSharedMemorySize, 128 * 388 * 4);

    // 1) xpre = x @ Wih^T + biases (both directions; fast 128x128x8 SGEMM)
    sgemm_xpre<<<dim3(G4H / 128, Sn * Bn / 128, 2), 256>>>(
        x, eWih_f, eWih_b, ebih_f, ebhh_f, ebih_b, ebhh_b, p_xpre);

    // 2) encoder recurrence (writes g_hs and g_hsT)
    encoder_rec<<<dim3(Bn, 2), 512, 256 * 132 * 4>>>(eWhh_f, eWhh_b);

    // 3) wa_hs = h_s @ w_a^T, stored transposed per-b (fast SGEMM)
    sgemm_wahsT<<<dim3(1, Sn * Bn / 128), 256>>>(p_hs, w_a);

    // 4) cluster-pair persistent decoder (2 CTAs per batch, cluster-barrier handshakes)
    decoder_persist<<<2 * Bn, 512, 128 * 388 * 4>>>(mask, v_a, u_a, dWih, dWhh, dbih, dbhh);

    // 5) logits (one fused GEMM) + softmax
    gemm_logits<<<dim3(Cv / 64, 1), 256>>>(p_sfin, w_b, p_ctx, v_b, out);
    softmax_stat<<<Bn, 256>>>(out);
    softmax_norm<<<dim3(Cv / 256, Bn), 256>>>(out);
}

// round 14
// speedup vs baseline: 3.8398x; 1.6623x over previous
#include <cuda_runtime.h>
#include <cstdint>

#define Sn 512
#define Bn 64
#define En 256
#define Hn 128
#define G4H 512
#define Tn 128
#define Cv 32000
#define ENC_CACHED 384   // Whh rows cached in encoder smem

// ---------------- scratch (static device globals; no allocation) ----------------
__device__ float g_xpre[2][Sn][Bn][G4H];     // precomputed x@Wih^T + biases
__device__ float g_hs[Sn][Bn][2*Hn];         // encoder outputs (concat fwd|bwd)
__device__ float g_hsT[Bn][2*Hn][Sn];        // transposed: per-b, j-major, s-contiguous
__device__ float g_wahsT[Bn][Sn][Hn];        // w_a @ h_s, transposed per-b contiguous
__device__ float g_sfin[Bn][Hn];             // final decoder hidden
__device__ float g_ctx[Bn][2*Hn];            // final ctx
__device__ float g_rowstat[Bn][2];           // softmax max, 1/sum

__device__ __forceinline__ float sigf(float x) { return 1.f / (1.f + __expf(-x)); }
__device__ __forceinline__ float tanh_fast(float x) {
    float y; asm("tanh.approx.f32 %0, %1;" : "=f"(y) : "f"(x)); return y;
}
__device__ __forceinline__ float gred8(float v) {
    v += __shfl_xor_sync(0xFFFFFFFFu, v, 1);
    v += __shfl_xor_sync(0xFFFFFFFFu, v, 2);
    v += __shfl_xor_sync(0xFFFFFFFFu, v, 4);
    return v;
}

// ---------------- cluster / DSMEM helpers -------------------------------------------
__device__ __forceinline__ uint32_t smem_u32(const void* p) {
    uint32_t a;
    asm("{ .reg .u64 t; cvta.to.shared.u64 t, %1; cvt.u32.u64 %0, t; }" : "=r"(a) : "l"(p));
    return a;
}
__device__ __forceinline__ uint32_t mapa_peer(uint32_t a, uint32_t rank) {
    uint32_t r; asm("mapa.shared::cluster.u32 %0, %1, %2;" : "=r"(r) : "r"(a), "r"(rank));
    return r;
}
__device__ __forceinline__ void st_remote_f32(uint32_t a, float v) {
    asm volatile("st.shared::cluster.f32 [%0], %1;" :: "r"(a), "f"(v) : "memory");
}
__device__ __forceinline__ void cluster_barrier() {
    asm volatile("barrier.cluster.arrive.aligned;" ::: "memory");
    asm volatile("barrier.cluster.wait.aligned;" ::: "memory");
}

// ================= fast SGEMM core: 128x128 tile, BK=8, 8x8 microtile ================
#define SG_PAD 132

__global__ void __launch_bounds__(256, 2) sgemm_xpre(
    const float* __restrict__ A,
    const float* __restrict__ B0, const float* __restrict__ B1,
    const float* __restrict__ bi0, const float* __restrict__ bh0,
    const float* __restrict__ bi1, const float* __restrict__ bh1,
    float* __restrict__ Cbase)
{
    int dir = blockIdx.z;
    const float* __restrict__ B  = dir ? B1 : B0;
    const float* __restrict__ bi = dir ? bi1 : bi0;
    const float* __restrict__ bh = dir ? bh1 : bh0;
    float* __restrict__ C = Cbase + (size_t)dir * Sn * Bn * G4H;
    const int K = En;

    __shared__ __align__(16) float As[2][8][SG_PAD];
    __shared__ __align__(16) float Bs[2][8][SG_PAD];

    int tid = threadIdx.x;
    int tx = tid & 15, ty = tid >> 4;
    int m0 = blockIdx.y * 128, n0 = blockIdx.x * 128;
    int lrow = tid >> 1, lk = (tid & 1) * 4;

    const float* Aload = A + (size_t)(m0 + lrow) * K + lk;
    const float* Bload = B + (size_t)(n0 + lrow) * K + lk;

    float acc[8][8] = {};
    float4 ra = *reinterpret_cast<const float4*>(Aload);
    float4 rb = *reinterpret_cast<const float4*>(Bload);
    As[0][lk+0][lrow]=ra.x; As[0][lk+1][lrow]=ra.y; As[0][lk+2][lrow]=ra.z; As[0][lk+3][lrow]=ra.w;
    Bs[0][lk+0][lrow]=rb.x; Bs[0][lk+1][lrow]=rb.y; Bs[0][lk+2][lrow]=rb.z; Bs[0][lk+3][lrow]=rb.w;
    __syncthreads();

    int nkb = K >> 3, buf = 0;
    for (int kb = 0; kb < nkb; kb++) {
        if (kb + 1 < nkb) {
            ra = *reinterpret_cast<const float4*>(Aload + (kb + 1) * 8);
            rb = *reinterpret_cast<const float4*>(Bload + (kb + 1) * 8);
        }
#pragma unroll
        for (int k = 0; k < 8; k++) {
            float4 a0 = *reinterpret_cast<const float4*>(&As[buf][k][ty * 4]);
            float4 a1 = *reinterpret_cast<const float4*>(&As[buf][k][ty * 4 + 64]);
            float4 b0 = *reinterpret_cast<const float4*>(&Bs[buf][k][tx * 4]);
            float4 b1 = *reinterpret_cast<const float4*>(&Bs[buf][k][tx * 4 + 64]);
            float av[8] = {a0.x,a0.y,a0.z,a0.w,a1.x,a1.y,a1.z,a1.w};
            float bv[8] = {b0.x,b0.y,b0.z,b0.w,b1.x,b1.y,b1.z,b1.w};
#pragma unroll
            for (int i = 0; i < 8; i++)
#pragma unroll
                for (int j = 0; j < 8; j++)
                    acc[i][j] += av[i] * bv[j];
        }
        if (kb + 1 < nkb) {
            int nb = buf ^ 1;
            As[nb][lk+0][lrow]=ra.x; As[nb][lk+1][lrow]=ra.y; As[nb][lk+2][lrow]=ra.z; As[nb][lk+3][lrow]=ra.w;
            Bs[nb][lk+0][lrow]=rb.x; Bs[nb][lk+1][lrow]=rb.y; Bs[nb][lk+2][lrow]=rb.z; Bs[nb][lk+3][lrow]=rb.w;
        }
        __syncthreads();
        buf ^= 1;
    }
#pragma unroll
    for (int i = 0; i < 8; i++) {
        int row = m0 + ((i < 4) ? (ty * 4 + i) : (64 + ty * 4 + i - 4));
#pragma unroll
        for (int jh = 0; jh < 2; jh++) {
            int col = n0 + tx * 4 + jh * 64;
            float4 v;
            v.x = acc[i][jh*4+0] + bi[col+0] + bh[col+0];
            v.y = acc[i][jh*4+1] + bi[col+1] + bh[col+1];
            v.z = acc[i][jh*4+2] + bi[col+2] + bh[col+2];
            v.w = acc[i][jh*4+3] + bi[col+3] + bh[col+3];
            *reinterpret_cast<float4*>(&C[(size_t)row * G4H + col]) = v;
        }
    }
}

__global__ void __launch_bounds__(256, 2) sgemm_wahsT(
    const float* __restrict__ A, const float* __restrict__ B)
{
    const int K = 2 * Hn;

    __shared__ __align__(16) float As[2][8][SG_PAD];
    __shared__ __align__(16) float Bs[2][8][SG_PAD];

    int tid = threadIdx.x;
    int tx = tid & 15, ty = tid >> 4;
    int m0 = blockIdx.y * 128;
    int lrow = tid >> 1, lk = (tid & 1) * 4;

    const float* Aload = A + (size_t)(m0 + lrow) * K + lk;
    const float* Bload = B + (size_t)lrow * K + lk;

    float acc[8][8] = {};
    float4 ra = *reinterpret_cast<const float4*>(Aload);
    float4 rb = *reinterpret_cast<const float4*>(Bload);
    As[0][lk+0][lrow]=ra.x; As[0][lk+1][lrow]=ra.y; As[0][lk+2][lrow]=ra.z; As[0][lk+3][lrow]=ra.w;
    Bs[0][lk+0][lrow]=rb.x; Bs[0][lk+1][lrow]=rb.y; Bs[0][lk+2][lrow]=rb.z; Bs[0][lk+3][lrow]=rb.w;
    __syncthreads();

    int nkb = K >> 3, buf = 0;
    for (int kb = 0; kb < nkb; kb++) {
        if (kb + 1 < nkb) {
            ra = *reinterpret_cast<const float4*>(Aload + (kb + 1) * 8);
            rb = *reinterpret_cast<const float4*>(Bload + (kb + 1) * 8);
        }
#pragma unroll
        for (int k = 0; k < 8; k++) {
            float4 a0 = *reinterpret_cast<const float4*>(&As[buf][k][ty * 4]);
            float4 a1 = *reinterpret_cast<const float4*>(&As[buf][k][ty * 4 + 64]);
            float4 b0 = *reinterpret_cast<const float4*>(&Bs[buf][k][tx * 4]);
            float4 b1 = *reinterpret_cast<const float4*>(&Bs[buf][k][tx * 4 + 64]);
            float av[8] = {a0.x,a0.y,a0.z,a0.w,a1.x,a1.y,a1.z,a1.w};
            float bv[8] = {b0.x,b0.y,b0.z,b0.w,b1.x,b1.y,b1.z,b1.w};
#pragma unroll
            for (int i = 0; i < 8; i++)
#pragma unroll
                for (int j = 0; j < 8; j++)
                    acc[i][j] += av[i] * bv[j];
        }
        if (kb + 1 < nkb) {
            int nb = buf ^ 1;
            As[nb][lk+0][lrow]=ra.x; As[nb][lk+1][lrow]=ra.y; As[nb][lk+2][lrow]=ra.z; As[nb][lk+3][lrow]=ra.w;
            Bs[nb][lk+0][lrow]=rb.x; Bs[nb][lk+1][lrow]=rb.y; Bs[nb][lk+2][lrow]=rb.z; Bs[nb][lk+3][lrow]=rb.w;
        }
        __syncthreads();
        buf ^= 1;
    }
#pragma unroll
    for (int i = 0; i < 8; i++) {
        int row = m0 + ((i < 4) ? (ty * 4 + i) : (64 + ty * 4 + i - 4));
        int s = row >> 6, bb = row & 63;
#pragma unroll
        for (int jh = 0; jh < 2; jh++) {
            int col = tx * 4 + jh * 64;
            float4 v;
            v.x = acc[i][jh*4+0]; v.y = acc[i][jh*4+1];
            v.z = acc[i][jh*4+2]; v.w = acc[i][jh*4+3];
            *reinterpret_cast<float4*>(&g_wahsT[bb][s][col]) = v;
        }
    }
}

// ---------------- fused logits GEMM: out = sfin@w_b^T + ctx@v_b^T --------------------
__global__ void gemm_logits(const float* __restrict__ A1, const float* __restrict__ B1,
                            const float* __restrict__ A2, const float* __restrict__ B2,
                            float* __restrict__ C)
{
    __shared__ __align__(16) float As[16][64];
    __shared__ __align__(16) float Bs[16][64];
    int tid = threadIdx.x;
    int tx = tid & 15, ty = tid >> 4;
    int n0 = blockIdx.x * 64;
    float acc[4][4] = {};

    for (int k0 = 0; k0 < Hn; k0 += 16) {
#pragma unroll
        for (int qq = 0; qq < 4; qq++) {
            int idx = tid + qq * 256;
            int kk = idx & 15, m = idx >> 4;
            As[kk][m] = A1[m * Hn + k0 + kk];
            Bs[kk][m] = B1[(n0 + m) * Hn + k0 + kk];
        }
        __syncthreads();
#pragma unroll
        for (int kk = 0; kk < 16; kk++) {
            float4 a4 = *reinterpret_cast<const float4*>(&As[kk][ty * 4]);
            float4 b4 = *reinterpret_cast<const float4*>(&Bs[kk][tx * 4]);
            float av[4] = {a4.x, a4.y, a4.z, a4.w};
            float bv[4] = {b4.x, b4.y, b4.z, b4.w};
#pragma unroll
            for (int i = 0; i < 4; i++)
#pragma unroll
                for (int j = 0; j < 4; j++)
                    acc[i][j] += av[i] * bv[j];
        }
        __syncthreads();
    }
    for (int k0 = 0; k0 < 2 * Hn; k0 += 16) {
#pragma unroll
        for (int qq = 0; qq < 4; qq++) {
            int idx = tid + qq * 256;
            int kk = idx & 15, m = idx >> 4;
            As[kk][m] = A2[m * 2 * Hn + k0 + kk];
            Bs[kk][m] = B2[(n0 + m) * 2 * Hn + k0 + kk];
        }
        __syncthreads();
#pragma unroll
        for (int kk = 0; kk < 16; kk++) {
            float4 a4 = *reinterpret_cast<const float4*>(&As[kk][ty * 4]);
            float4 b4 = *reinterpret_cast<const float4*>(&Bs[kk][tx * 4]);
            float av[4] = {a4.x, a4.y, a4.z, a4.w};
            float bv[4] = {b4.x, b4.y, b4.z, b4.w};
#pragma unroll
            for (int i = 0; i < 4; i++)
#pragma unroll
                for (int j = 0; j < 4; j++)
                    acc[i][j] += av[i] * bv[j];
        }
        __syncthreads();
    }
#pragma unroll
    for (int i = 0; i < 4; i++) {
        int row = ty * 4 + i;
#pragma unroll
        for (int j = 0; j < 4; j++)
            C[row * Cv + n0 + tx * 4 + j] = acc[i][j];
    }
}

// ---------------- encoder recurrence: 8-lane-group GEMV (coalesced), 384-row cache ---
// 512 threads = 64 groups; group g computes gate rows p*64+g, p=0..7.
// dynamic smem: ENC_CACHED * 132 * 4 = 202752 B
__global__ void __launch_bounds__(512, 1)
encoder_rec(const float* __restrict__ Whh_f, const float* __restrict__ Whh_b)
{
    extern __shared__ __align__(16) float ws[];
    __shared__ __align__(16) float h_sm[Hn];
    __shared__ float c_sm[Hn];
    __shared__ float gate_sm[G4H];
    int b = blockIdx.x, dir = blockIdx.y;
    const float* __restrict__ Whh = dir ? Whh_b : Whh_f;
    int tid = threadIdx.x;              // 512
    int g = tid >> 3, q = tid & 7;      // 64 groups of 8 lanes

    for (int idx = tid; idx < ENC_CACHED * 128; idx += 512) {
        int r = idx >> 7, c = idx & 127;
        ws[r * 132 + c] = Whh[idx];
    }
    if (tid < Hn) { h_sm[tid] = 0.f; c_sm[tid] = 0.f; }
    __syncthreads();

    const float4* h4 = reinterpret_cast<const float4*>(h_sm);
    const float4* Whh4 = reinterpret_cast<const float4*>(Whh);

    for (int step = 0; step < Sn; step++) {
        int t = dir ? (Sn - 1 - step) : step;
        // h fragment in registers, reused for all 8 owned rows
        float4 H0 = h4[q], H1 = h4[q + 8], H2 = h4[q + 16], H3 = h4[q + 24];
#pragma unroll
        for (int p = 0; p < 8; p++) {
            int r = p * 64 + g;
            float acc;
            if (r < ENC_CACHED) {
                const float4* wr = reinterpret_cast<const float4*>(ws + r * 132);
                float4 W0 = wr[q], W1 = wr[q + 8], W2 = wr[q + 16], W3 = wr[q + 24];
                acc = W0.x*H0.x + W0.y*H0.y + W0.z*H0.z + W0.w*H0.w
                    + W1.x*H1.x + W1.y*H1.y + W1.z*H1.z + W1.w*H1.w
                    + W2.x*H2.x + W2.y*H2.y + W2.z*H2.z + W2.w*H2.w
                    + W3.x*H3.x + W3.y*H3.y + W3.z*H3.z + W3.w*H3.w;
            } else {
                const float4* wr = &Whh4[r * 32];
                float4 W0 = __ldg(&wr[q]),      W1 = __ldg(&wr[q + 8]);
                float4 W2 = __ldg(&wr[q + 16]), W3 = __ldg(&wr[q + 24]);
                acc = W0.x*H0.x + W0.y*H0.y + W0.z*H0.z + W0.w*H0.w
                    + W1.x*H1.x + W1.y*H1.y + W1.z*H1.z + W1.w*H1.w
                    + W2.x*H2.x + W2.y*H2.y + W2.z*H2.z + W2.w*H2.w
                    + W3.x*H3.x + W3.y*H3.y + W3.z*H3.z + W3.w*H3.w;
            }
            acc = gred8(acc);
            if (q == 0) gate_sm[r] = acc + g_xpre[dir][t][b][r];
        }
        __syncthreads();
        if (tid < Hn) {
            float gi = gate_sm[tid], gf = gate_sm[tid + 128];
            float gg = gate_sm[tid + 256], go = gate_sm[tid + 384];
            float c = sigf(gf) * c_sm[tid] + sigf(gi) * tanhf(gg);
            float h = sigf(go) * tanhf(c);
            c_sm[tid] = c; h_sm[tid] = h;
            int j = dir * Hn + tid;
            g_hs[t][b][j] = h;
            g_hsT[b][j][t] = h;
        }
        __syncthreads();
    }
}

// ---------------- cluster-pair persistent decoder: 128 CTAs (2 per batch) ------------
__global__ void __launch_bounds__(512, 1) __cluster_dims__(2, 1, 1)
decoder_persist(const float* __restrict__ mask, const float* __restrict__ va,
                const float* __restrict__ ua,
                const float* __restrict__ Wih, const float* __restrict__ Whh,
                const float* __restrict__ bih, const float* __restrict__ bhh)
{
    extern __shared__ __align__(16) float wc[];          // [128][388]
    __shared__ __align__(16) float s_sm[2][Hn];
    __shared__ __align__(16) float y_sm[64];
    __shared__ __align__(16) float vas_sm[Hn];
    __shared__ __align__(16) float u_sm[Hn];
    __shared__ __align__(16) float e_sm[256];
    __shared__ __align__(16) float ctxp_sm[2*Hn];
    __shared__ __align__(16) float xin_sm[384];
    __shared__ __align__(16) float mask_sm[256];
    __shared__ __align__(16) float bias_sm[256];
    __shared__ __align__(16) float gates_sm[256];
    __shared__ __align__(16) float xch_ctx[2][2*Hn];
    __shared__ __align__(16) float xch_s[2];
    __shared__ float red[16];
    __shared__ float S_loc[2];

    uint32_t rank;
    asm("mov.u32 %0, %%cluster_ctarank;" : "=r"(rank));
    int h = (int)rank;
    int b = blockIdx.x >> 1;
    int tid = threadIdx.x;                  // 512
    int w = tid >> 5, l = tid & 31;
    int g = tid >> 3, q = tid & 7;

    uint32_t peer_xctx = mapa_peer(smem_u32(&xch_ctx[0][0]), rank ^ 1);
    uint32_t peer_xs   = mapa_peer(smem_u32(&xch_s[0]),      rank ^ 1);
    uint32_t peer_s    = mapa_peer(smem_u32(&s_sm[0][0]),    rank ^ 1);

    for (int idx = tid; idx < 128 * 384; idx += 512) {
        int lr = idx / 384, c = idx - lr * 384;
        int r = (lr >> 6) * 128 + h * 64 + (lr & 63);
        wc[lr * 388 + c] = (c < 128) ? Whh[r * 128 + c] : Wih[r * 256 + (c - 128)];
    }
    if (tid < 256) {
        int r = (tid >> 6) * 128 + h * 64 + (tid & 63);
        bias_sm[tid] = bih[r] + bhh[r];
        mask_sm[tid] = mask[(h * 256 + tid) * Bn + b];
    }
    if (tid < Hn) { u_sm[tid] = ua[tid]; s_sm[0][tid] = 0.f; }
    if (tid < 64) y_sm[tid] = 0.f;
    __syncthreads();

    const float4* va4    = reinterpret_cast<const float4*>(va);
    const float4* Whh4   = reinterpret_cast<const float4*>(Whh);
    const float4* Wih4   = reinterpret_cast<const float4*>(Wih);
    const float4* wahsT4 = reinterpret_cast<const float4*>(&g_wahsT[0][0][0]);
    const float4* hsT4   = reinterpret_cast<const float4*>(&g_hsT[0][0][0]);
    const float4* u4     = reinterpret_cast<const float4*>(u_sm);
    const float4* vas4   = reinterpret_cast<const float4*>(vas_sm);
    const float4* e4p    = reinterpret_cast<const float4*>(e_sm);
    const float4* xin4   = reinterpret_cast<const float4*>(xin_sm);

    for (int t = 0; t < Tn; t++) {
        int par = t & 1;
        const float4* s4 = reinterpret_cast<const float4*>(&s_sm[par][0]);

#pragma unroll
        for (int p = 0; p < 2; p++) {
            int j = p * 64 + g;
            float acc = 0.f;
#pragma unroll
            for (int k = 0; k < 4; k++) {
                int f = q + k * 8;
                float4 W = __ldg(&va4[j * 32 + f]);
                float4 X = s4[f];
                acc += W.x * X.x + W.y * X.y + W.z * X.z + W.w * X.w;
            }
            acc = gred8(acc);
            if (q == 0) vas_sm[j] = acc;
        }
        __syncthreads();

        {
            float4 V[4], U[4];
#pragma unroll
            for (int k = 0; k < 4; k++) { V[k] = vas4[q + k * 8]; U[k] = u4[q + k * 8]; }
            float stacc = 0.f;
#pragma unroll
            for (int p = 0; p < 4; p++) {
                int sl = p * 64 + g;
                int s = h * 256 + sl;
                float acc = 0.f;
#pragma unroll
                for (int k = 0; k < 4; k++) {
                    float4 A = __ldg(&wahsT4[(b * Sn + s) * 32 + q + k * 8]);
                    acc += tanh_fast(A.x + V[k].x) * U[k].x + tanh_fast(A.y + V[k].y) * U[k].y +
                           tanh_fast(A.z + V[k].z) * U[k].z + tanh_fast(A.w + V[k].w) * U[k].w;
                }
                acc = gred8(acc);
                float ex = __expf(acc * mask_sm[sl]);
                if (q == 0) e_sm[sl] = ex;
                stacc += ex;
            }
            stacc += __shfl_xor_sync(0xFFFFFFFFu, stacc, 8);
            stacc += __shfl_xor_sync(0xFFFFFFFFu, stacc, 16);
            if (l == 0) red[w] = stacc;
        }
        __syncthreads();

        if (tid == 0) {
            float ss = red[0];
#pragma unroll
            for (int i = 1; i < 16; i++) ss += red[i];
            S_loc[par] = ss;
        }
#pragma unroll
        for (int p = 0; p < 4; p++) {
            int j = p * 64 + g;
            const float4* hp = &hsT4[(b * 2 * Hn + j) * 128 + h * 64];
            float acc = 0.f;
#pragma unroll
            for (int k = 0; k < 8; k++) {
                int f = q + k * 8;
                float4 H = __ldg(&hp[f]);
                float4 A = e4p[f];
                acc += H.x * A.x + H.y * A.y + H.z * A.z + H.w * A.w;
            }
            acc = gred8(acc);
            if (q == 0) ctxp_sm[j] = acc;
        }
        __syncthreads();

        if (tid < 256) st_remote_f32(peer_xctx + (par * 256 + tid) * 4, ctxp_sm[tid]);
        if (tid == 0)  st_remote_f32(peer_xs + par * 4, S_loc[par]);
        cluster_barrier();

        if (tid < 128) xin_sm[tid] = s_sm[par][tid];
        else if (tid < 384) {
            int j = tid - 128;
            float inv = 1.f / (S_loc[par] + xch_s[par]);
            xin_sm[tid] = (ctxp_sm[j] + xch_ctx[par][j]) * inv;
        }
        __syncthreads();
        if (t == Tn - 1 && h == 0 && tid < 256) g_ctx[b][tid] = xin_sm[128 + tid];

#pragma unroll
        for (int p = 0; p < 4; p++) {
            int lr = p * 64 + g;
            float acc = 0.f;
            if (p < 2) {
                const float4* wr = reinterpret_cast<const float4*>(wc + lr * 388);
#pragma unroll
                for (int k = 0; k < 12; k++) {
                    int f = q + k * 8;
                    float4 W = wr[f];
                    float4 X = xin4[f];
                    acc += W.x * X.x + W.y * X.y + W.z * X.z + W.w * X.w;
                }
            } else {
                int r = p * 128 + h * 64 + g;
#pragma unroll
                for (int k = 0; k < 4; k++) {
                    int f = q + k * 8;
                    float4 W = __ldg(&Whh4[r * 32 + f]);
                    float4 X = xin4[f];
                    acc += W.x * X.x + W.y * X.y + W.z * X.z + W.w * X.w;
                }
#pragma unroll
                for (int k = 4; k < 12; k++) {
                    int f = q + k * 8;
                    float4 W = __ldg(&Wih4[r * 64 + f - 32]);
                    float4 X = xin4[f];
                    acc += W.x * X.x + W.y * X.y + W.z * X.z + W.w * X.w;
                }
            }
            acc = gred8(acc);
            if (q == 0) gates_sm[lr] = acc + bias_sm[lr];
        }
        __syncthreads();

        if (tid < 64) {
            float gi = gates_sm[tid],       gf = gates_sm[64 + tid];
            float gg = gates_sm[128 + tid], go = gates_sm[192 + tid];
            float y = sigf(gf) * y_sm[tid] + sigf(gi) * tanhf(gg);
            float s = sigf(go) * tanhf(y);
            y_sm[tid] = y;
            int jg = h * 64 + tid;
            s_sm[par ^ 1][jg] = s;
            st_remote_f32(peer_s + ((par ^ 1) * 128 + jg) * 4, s);
            if (t == Tn - 1) g_sfin[b][jg] = s;
        }
        cluster_barrier();
    }
}

// ---------------- final softmax over C=32000 -----------------------------------------
__global__ void softmax_stat(const float* __restrict__ out)
{
    int b = blockIdx.x, tid = threadIdx.x;
    __shared__ float red[256];
    const float* row = out + b * Cv;
    float m = -1e30f;
    for (int i = tid; i < Cv; i += 256) m = fmaxf(m, row[i]);
    red[tid] = m; __syncthreads();
#pragma unroll
    for (int st = 128; st; st >>= 1) {
        if (tid < st) red[tid] = fmaxf(red[tid], red[tid + st]);
        __syncthreads();
    }
    m = red[0]; __syncthreads();
    float s = 0.f;
    for (int i = tid; i < Cv; i += 256) s += __expf(row[i] - m);
    red[tid] = s; __syncthreads();
#pragma unroll
    for (int st = 128; st; st >>= 1) {
        if (tid < st) red[tid] += red[tid + st];
        __syncthreads();
    }
    if (tid == 0) { g_rowstat[b][0] = m; g_rowstat[b][1] = 1.f / red[0]; }
}

__global__ void softmax_norm(float* out)
{
    int b = blockIdx.y;
    int i = blockIdx.x * 256 + threadIdx.x;
    float* row = out + b * Cv;
    row[i] = __expf(row[i] - g_rowstat[b][0]) * g_rowstat[b][1];
}

// ---------------- launch -------------------------------------------------------------
extern "C" void kernel_launch(void* const* d_in, const int* in_sizes, int n_in,
                              void* d_out, int out_size)
{
    (void)in_sizes; (void)n_in; (void)out_size;
    const float* x      = (const float*)d_in[0];
    const float* mask   = (const float*)d_in[1];
    const float* eWih_f = (const float*)d_in[2];
    const float* eWhh_f = (const float*)d_in[3];
    const float* ebih_f = (const float*)d_in[4];
    const float* ebhh_f = (const float*)d_in[5];
    const float* eWih_b = (const float*)d_in[6];
    const float* eWhh_b = (const float*)d_in[7];
    const float* ebih_b = (const float*)d_in[8];
    const float* ebhh_b = (const float*)d_in[9];
    const float* dWih   = (const float*)d_in[10];
    const float* dWhh   = (const float*)d_in[11];
    const float* dbih   = (const float*)d_in[12];
    const float* dbhh   = (const float*)d_in[13];
    const float* w_a    = (const float*)d_in[14];
    const float* v_a    = (const float*)d_in[15];
    const float* u_a    = (const float*)d_in[16];
    const float* w_b    = (const float*)d_in[17];
    const float* v_b    = (const float*)d_in[18];
    float* out = (float*)d_out;

    float *p_xpre, *p_hs, *p_sfin, *p_ctx;
    cudaGetSymbolAddress((void**)&p_xpre, g_xpre);
    cudaGetSymbolAddress((void**)&p_hs,   g_hs);
    cudaGetSymbolAddress((void**)&p_sfin, g_sfin);
    cudaGetSymbolAddress((void**)&p_ctx,  g_ctx);

    cudaFuncSetAttribute(encoder_rec, cudaFuncAttributeMaxDynamicSharedMemorySize, ENC_CACHED * 132 * 4);
    cudaFuncSetAttribute(decoder_persist, cudaFuncAttributeMaxDynamicSharedMemorySize, 128 * 388 * 4);

    // 1) xpre = x @ Wih^T + biases (both directions; fast 128x128x8 SGEMM)
    sgemm_xpre<<<dim3(G4H / 128, Sn * Bn / 128, 2), 256>>>(
        x, eWih_f, eWih_b, ebih_f, ebhh_f, ebih_b, ebhh_b, p_xpre);

    // 2) encoder recurrence (coalesced group-GEMV, 384-row smem cache)
    encoder_rec<<<dim3(Bn, 2), 512, ENC_CACHED * 132 * 4>>>(eWhh_f, eWhh_b);

    // 3) wa_hs = h_s @ w_a^T, stored transposed per-b (fast SGEMM)
    sgemm_wahsT<<<dim3(1, Sn * Bn / 128), 256>>>(p_hs, w_a);

    // 4) cluster-pair persistent decoder (2 CTAs per batch, cluster-barrier handshakes)
    decoder_persist<<<2 * Bn, 512, 128 * 388 * 4>>>(mask, v_a, u_a, dWih, dWhh, dbih, dbhh);

    // 5) logits (one fused GEMM) + softmax
    gemm_logits<<<dim3(Cv / 64, 1), 256>>>(p_sfin, w_b, p_ctx, v_b, out);
    softmax_stat<<<Bn, 256>>>(out);
    softmax_norm<<<dim3(Cv / 256, Bn), 256>>>(out);
}

// round 15
// speedup vs baseline: 4.1480x; 1.0803x over previous
#include <cuda_runtime.h>
#include <cuda_bf16.h>
#include <cstdint>

#define Sn 512
#define Bn 64
#define En 256
#define Hn 128
#define G4H 512
#define Tn 128
#define Cv 32000
#define ENC_CACHED 384

#define WC_STRIDE 400    // bf16 elems per cached weight row (384 + pad)
#define WA_STRIDE 144    // bf16 elems per cached wahs row (128 + pad)
#define VA_STRIDE 144
#define DEC_DYN_SMEM (128*WC_STRIDE*2 + 256*WA_STRIDE*2 + 128*VA_STRIDE*2)   // 212992

// ---------------- scratch (static device globals; no allocation) ----------------
__device__ float g_xpre[2][Sn][Bn][G4H];
__device__ float g_hs[Sn][Bn][2*Hn];
__device__ float g_hsT[Bn][2*Hn][Sn];              // fp32 (ctx path keeps full precision)
__device__ __nv_bfloat16 g_wahsT_bf[Bn][Sn][Hn];   // bf16 attention precompute
__device__ __nv_bfloat16 g_Wbf[G4H][384];          // bf16 decoder weights [Whh|Wih]
__device__ float g_sfin[Bn][Hn];
__device__ float g_ctx[Bn][2*Hn];
__device__ float g_rowstat[Bn][2];

__device__ __forceinline__ float sigf(float x) { return 1.f / (1.f + __expf(-x)); }
__device__ __forceinline__ float tanh_fast(float x) {
    float y; asm("tanh.approx.f32 %0, %1;" : "=f"(y) : "f"(x)); return y;
}
__device__ __forceinline__ float gred8(float v) {
    v += __shfl_xor_sync(0xFFFFFFFFu, v, 1);
    v += __shfl_xor_sync(0xFFFFFFFFu, v, 2);
    v += __shfl_xor_sync(0xFFFFFFFFu, v, 4);
    return v;
}
// dot of 8 bf16 (in uint4) with 8 fp32 (two float4)
__device__ __forceinline__ float dot8(uint4 w, float4 x0, float4 x1) {
    float2 f0 = __bfloat1622float2(*reinterpret_cast<__nv_bfloat162*>(&w.x));
    float2 f1 = __bfloat1622float2(*reinterpret_cast<__nv_bfloat162*>(&w.y));
    float2 f2 = __bfloat1622float2(*reinterpret_cast<__nv_bfloat162*>(&w.z));
    float2 f3 = __bfloat1622float2(*reinterpret_cast<__nv_bfloat162*>(&w.w));
    return f0.x*x0.x + f0.y*x0.y + f1.x*x0.z + f1.y*x0.w
         + f2.x*x1.x + f2.y*x1.y + f3.x*x1.z + f3.y*x1.w;
}
__device__ __forceinline__ float tdot8(uint4 w, float4 v0, float4 v1, float4 u0, float4 u1) {
    float2 f0 = __bfloat1622float2(*reinterpret_cast<__nv_bfloat162*>(&w.x));
    float2 f1 = __bfloat1622float2(*reinterpret_cast<__nv_bfloat162*>(&w.y));
    float2 f2 = __bfloat1622float2(*reinterpret_cast<__nv_bfloat162*>(&w.z));
    float2 f3 = __bfloat1622float2(*reinterpret_cast<__nv_bfloat162*>(&w.w));
    return tanh_fast(f0.x+v0.x)*u0.x + tanh_fast(f0.y+v0.y)*u0.y
         + tanh_fast(f1.x+v0.z)*u0.z + tanh_fast(f1.y+v0.w)*u0.w
         + tanh_fast(f2.x+v1.x)*u1.x + tanh_fast(f2.y+v1.y)*u1.y
         + tanh_fast(f3.x+v1.z)*u1.z + tanh_fast(f3.y+v1.w)*u1.w;
}

// ---------------- cluster / DSMEM helpers -------------------------------------------
__device__ __forceinline__ uint32_t smem_u32(const void* p) {
    uint32_t a;
    asm("{ .reg .u64 t; cvta.to.shared.u64 t, %1; cvt.u32.u64 %0, t; }" : "=r"(a) : "l"(p));
    return a;
}
__device__ __forceinline__ uint32_t mapa_peer(uint32_t a, uint32_t rank) {
    uint32_t r; asm("mapa.shared::cluster.u32 %0, %1, %2;" : "=r"(r) : "r"(a), "r"(rank));
    return r;
}
__device__ __forceinline__ void st_remote_f32(uint32_t a, float v) {
    asm volatile("st.shared::cluster.f32 [%0], %1;" :: "r"(a), "f"(v) : "memory");
}
__device__ __forceinline__ void cluster_barrier() {
    asm volatile("barrier.cluster.arrive.aligned;" ::: "memory");
    asm volatile("barrier.cluster.wait.aligned;" ::: "memory");
}

// ---------------- prep: convert decoder weights to bf16 ------------------------------
__global__ void prep_bf16(const float* __restrict__ Wih, const float* __restrict__ Whh)
{
    int i = blockIdx.x * 256 + threadIdx.x;
    if (i < G4H * 384) {
        int r = i / 384, c = i - r * 384;
        float v = (c < 128) ? Whh[r * 128 + c] : Wih[r * 256 + (c - 128)];
        g_Wbf[r][c] = __float2bfloat16(v);
    }
}

// ================= fast SGEMM core: 128x128 tile, BK=8, 8x8 microtile ================
#define SG_PAD 132

__global__ void __launch_bounds__(256, 2) sgemm_xpre(
    const float* __restrict__ A,
    const float* __restrict__ B0, const float* __restrict__ B1,
    const float* __restrict__ bi0, const float* __restrict__ bh0,
    const float* __restrict__ bi1, const float* __restrict__ bh1,
    float* __restrict__ Cbase)
{
    int dir = blockIdx.z;
    const float* __restrict__ B  = dir ? B1 : B0;
    const float* __restrict__ bi = dir ? bi1 : bi0;
    const float* __restrict__ bh = dir ? bh1 : bh0;
    float* __restrict__ C = Cbase + (size_t)dir * Sn * Bn * G4H;
    const int K = En;

    __shared__ __align__(16) float As[2][8][SG_PAD];
    __shared__ __align__(16) float Bs[2][8][SG_PAD];

    int tid = threadIdx.x;
    int tx = tid & 15, ty = tid >> 4;
    int m0 = blockIdx.y * 128, n0 = blockIdx.x * 128;
    int lrow = tid >> 1, lk = (tid & 1) * 4;

    const float* Aload = A + (size_t)(m0 + lrow) * K + lk;
    const float* Bload = B + (size_t)(n0 + lrow) * K + lk;

    float acc[8][8] = {};
    float4 ra = *reinterpret_cast<const float4*>(Aload);
    float4 rb = *reinterpret_cast<const float4*>(Bload);
    As[0][lk+0][lrow]=ra.x; As[0][lk+1][lrow]=ra.y; As[0][lk+2][lrow]=ra.z; As[0][lk+3][lrow]=ra.w;
    Bs[0][lk+0][lrow]=rb.x; Bs[0][lk+1][lrow]=rb.y; Bs[0][lk+2][lrow]=rb.z; Bs[0][lk+3][lrow]=rb.w;
    __syncthreads();

    int nkb = K >> 3, buf = 0;
    for (int kb = 0; kb < nkb; kb++) {
        if (kb + 1 < nkb) {
            ra = *reinterpret_cast<const float4*>(Aload + (kb + 1) * 8);
            rb = *reinterpret_cast<const float4*>(Bload + (kb + 1) * 8);
        }
#pragma unroll
        for (int k = 0; k < 8; k++) {
            float4 a0 = *reinterpret_cast<const float4*>(&As[buf][k][ty * 4]);
            float4 a1 = *reinterpret_cast<const float4*>(&As[buf][k][ty * 4 + 64]);
            float4 b0 = *reinterpret_cast<const float4*>(&Bs[buf][k][tx * 4]);
            float4 b1 = *reinterpret_cast<const float4*>(&Bs[buf][k][tx * 4 + 64]);
            float av[8] = {a0.x,a0.y,a0.z,a0.w,a1.x,a1.y,a1.z,a1.w};
            float bv[8] = {b0.x,b0.y,b0.z,b0.w,b1.x,b1.y,b1.z,b1.w};
#pragma unroll
            for (int i = 0; i < 8; i++)
#pragma unroll
                for (int j = 0; j < 8; j++)
                    acc[i][j] += av[i] * bv[j];
        }
        if (kb + 1 < nkb) {
            int nb = buf ^ 1;
            As[nb][lk+0][lrow]=ra.x; As[nb][lk+1][lrow]=ra.y; As[nb][lk+2][lrow]=ra.z; As[nb][lk+3][lrow]=ra.w;
            Bs[nb][lk+0][lrow]=rb.x; Bs[nb][lk+1][lrow]=rb.y; Bs[nb][lk+2][lrow]=rb.z; Bs[nb][lk+3][lrow]=rb.w;
        }
        __syncthreads();
        buf ^= 1;
    }
#pragma unroll
    for (int i = 0; i < 8; i++) {
        int row = m0 + ((i < 4) ? (ty * 4 + i) : (64 + ty * 4 + i - 4));
#pragma unroll
        for (int jh = 0; jh < 2; jh++) {
            int col = n0 + tx * 4 + jh * 64;
            float4 v;
            v.x = acc[i][jh*4+0] + bi[col+0] + bh[col+0];
            v.y = acc[i][jh*4+1] + bi[col+1] + bh[col+1];
            v.z = acc[i][jh*4+2] + bi[col+2] + bh[col+2];
            v.w = acc[i][jh*4+3] + bi[col+3] + bh[col+3];
            *reinterpret_cast<float4*>(&C[(size_t)row * G4H + col]) = v;
        }
    }
}

// wahs -> bf16 transposed store
__global__ void __launch_bounds__(256, 2) sgemm_wahsT(
    const float* __restrict__ A, const float* __restrict__ B)
{
    const int K = 2 * Hn;

    __shared__ __align__(16) float As[2][8][SG_PAD];
    __shared__ __align__(16) float Bs[2][8][SG_PAD];

    int tid = threadIdx.x;
    int tx = tid & 15, ty = tid >> 4;
    int m0 = blockIdx.y * 128;
    int lrow = tid >> 1, lk = (tid & 1) * 4;

    const float* Aload = A + (size_t)(m0 + lrow) * K + lk;
    const float* Bload = B + (size_t)lrow * K + lk;

    float acc[8][8] = {};
    float4 ra = *reinterpret_cast<const float4*>(Aload);
    float4 rb = *reinterpret_cast<const float4*>(Bload);
    As[0][lk+0][lrow]=ra.x; As[0][lk+1][lrow]=ra.y; As[0][lk+2][lrow]=ra.z; As[0][lk+3][lrow]=ra.w;
    Bs[0][lk+0][lrow]=rb.x; Bs[0][lk+1][lrow]=rb.y; Bs[0][lk+2][lrow]=rb.z; Bs[0][lk+3][lrow]=rb.w;
    __syncthreads();

    int nkb = K >> 3, buf = 0;
    for (int kb = 0; kb < nkb; kb++) {
        if (kb + 1 < nkb) {
            ra = *reinterpret_cast<const float4*>(Aload + (kb + 1) * 8);
            rb = *reinterpret_cast<const float4*>(Bload + (kb + 1) * 8);
        }
#pragma unroll
        for (int k = 0; k < 8; k++) {
            float4 a0 = *reinterpret_cast<const float4*>(&As[buf][k][ty * 4]);
            float4 a1 = *reinterpret_cast<const float4*>(&As[buf][k][ty * 4 + 64]);
            float4 b0 = *reinterpret_cast<const float4*>(&Bs[buf][k][tx * 4]);
            float4 b1 = *reinterpret_cast<const float4*>(&Bs[buf][k][tx * 4 + 64]);
            float av[8] = {a0.x,a0.y,a0.z,a0.w,a1.x,a1.y,a1.z,a1.w};
            float bv[8] = {b0.x,b0.y,b0.z,b0.w,b1.x,b1.y,b1.z,b1.w};
#pragma unroll
            for (int i = 0; i < 8; i++)
#pragma unroll
                for (int j = 0; j < 8; j++)
                    acc[i][j] += av[i] * bv[j];
        }
        if (kb + 1 < nkb) {
            int nb = buf ^ 1;
            As[nb][lk+0][lrow]=ra.x; As[nb][lk+1][lrow]=ra.y; As[nb][lk+2][lrow]=ra.z; As[nb][lk+3][lrow]=ra.w;
            Bs[nb][lk+0][lrow]=rb.x; Bs[nb][lk+1][lrow]=rb.y; Bs[nb][lk+2][lrow]=rb.z; Bs[nb][lk+3][lrow]=rb.w;
        }
        __syncthreads();
        buf ^= 1;
    }
#pragma unroll
    for (int i = 0; i < 8; i++) {
        int row = m0 + ((i < 4) ? (ty * 4 + i) : (64 + ty * 4 + i - 4));
        int s = row >> 6, bb = row & 63;
#pragma unroll
        for (int jh = 0; jh < 2; jh++) {
            int col = tx * 4 + jh * 64;
#pragma unroll
            for (int e = 0; e < 4; e++)
                g_wahsT_bf[bb][s][col + e] = __float2bfloat16(acc[i][jh*4+e]);
        }
    }
}

// ---------------- fused logits GEMM ---------------------------------------------------
__global__ void gemm_logits(const float* __restrict__ A1, const float* __restrict__ B1,
                            const float* __restrict__ A2, const float* __restrict__ B2,
                            float* __restrict__ C)
{
    __shared__ __align__(16) float As[16][64];
    __shared__ __align__(16) float Bs[16][64];
    int tid = threadIdx.x;
    int tx = tid & 15, ty = tid >> 4;
    int n0 = blockIdx.x * 64;
    float acc[4][4] = {};

    for (int k0 = 0; k0 < Hn; k0 += 16) {
#pragma unroll
        for (int qq = 0; qq < 4; qq++) {
            int idx = tid + qq * 256;
            int kk = idx & 15, m = idx >> 4;
            As[kk][m] = A1[m * Hn + k0 + kk];
            Bs[kk][m] = B1[(n0 + m) * Hn + k0 + kk];
        }
        __syncthreads();
#pragma unroll
        for (int kk = 0; kk < 16; kk++) {
            float4 a4 = *reinterpret_cast<const float4*>(&As[kk][ty * 4]);
            float4 b4 = *reinterpret_cast<const float4*>(&Bs[kk][tx * 4]);
            float av[4] = {a4.x, a4.y, a4.z, a4.w};
            float bv[4] = {b4.x, b4.y, b4.z, b4.w};
#pragma unroll
            for (int i = 0; i < 4; i++)
#pragma unroll
                for (int j = 0; j < 4; j++)
                    acc[i][j] += av[i] * bv[j];
        }
        __syncthreads();
    }
    for (int k0 = 0; k0 < 2 * Hn; k0 += 16) {
#pragma unroll
        for (int qq = 0; qq < 4; qq++) {
            int idx = tid + qq * 256;
            int kk = idx & 15, m = idx >> 4;
            As[kk][m] = A2[m * 2 * Hn + k0 + kk];
            Bs[kk][m] = B2[(n0 + m) * 2 * Hn + k0 + kk];
        }
        __syncthreads();
#pragma unroll
        for (int kk = 0; kk < 16; kk++) {
            float4 a4 = *reinterpret_cast<const float4*>(&As[kk][ty * 4]);
            float4 b4 = *reinterpret_cast<const float4*>(&Bs[kk][tx * 4]);
            float av[4] = {a4.x, a4.y, a4.z, a4.w};
            float bv[4] = {b4.x, b4.y, b4.z, b4.w};
#pragma unroll
            for (int i = 0; i < 4; i++)
#pragma unroll
                for (int j = 0; j < 4; j++)
                    acc[i][j] += av[i] * bv[j];
        }
        __syncthreads();
    }
#pragma unroll
    for (int i = 0; i < 4; i++) {
        int row = ty * 4 + i;
#pragma unroll
        for (int j = 0; j < 4; j++)
            C[row * Cv + n0 + tx * 4 + j] = acc[i][j];
    }
}

// ---------------- encoder recurrence (R14 winner, unchanged) -------------------------
__global__ void __launch_bounds__(512, 1)
encoder_rec(const float* __restrict__ Whh_f, const float* __restrict__ Whh_b)
{
    extern __shared__ __align__(16) float ws[];
    __shared__ __align__(16) float h_sm[Hn];
    __shared__ float c_sm[Hn];
    __shared__ float gate_sm[G4H];
    int b = blockIdx.x, dir = blockIdx.y;
    const float* __restrict__ Whh = dir ? Whh_b : Whh_f;
    int tid = threadIdx.x;
    int g = tid >> 3, q = tid & 7;

    for (int idx = tid; idx < ENC_CACHED * 128; idx += 512) {
        int r = idx >> 7, c = idx & 127;
        ws[r * 132 + c] = Whh[idx];
    }
    if (tid < Hn) { h_sm[tid] = 0.f; c_sm[tid] = 0.f; }
    __syncthreads();

    const float4* h4 = reinterpret_cast<const float4*>(h_sm);
    const float4* Whh4 = reinterpret_cast<const float4*>(Whh);

    for (int step = 0; step < Sn; step++) {
        int t = dir ? (Sn - 1 - step) : step;
        float4 H0 = h4[q], H1 = h4[q + 8], H2 = h4[q + 16], H3 = h4[q + 24];
#pragma unroll
        for (int p = 0; p < 8; p++) {
            int r = p * 64 + g;
            float acc;
            if (r < ENC_CACHED) {
                const float4* wr = reinterpret_cast<const float4*>(ws + r * 132);
                float4 W0 = wr[q], W1 = wr[q + 8], W2 = wr[q + 16], W3 = wr[q + 24];
                acc = W0.x*H0.x + W0.y*H0.y + W0.z*H0.z + W0.w*H0.w
                    + W1.x*H1.x + W1.y*H1.y + W1.z*H1.z + W1.w*H1.w
                    + W2.x*H2.x + W2.y*H2.y + W2.z*H2.z + W2.w*H2.w
                    + W3.x*H3.x + W3.y*H3.y + W3.z*H3.z + W3.w*H3.w;
            } else {
                const float4* wr = &Whh4[r * 32];
                float4 W0 = __ldg(&wr[q]),      W1 = __ldg(&wr[q + 8]);
                float4 W2 = __ldg(&wr[q + 16]), W3 = __ldg(&wr[q + 24]);
                acc = W0.x*H0.x + W0.y*H0.y + W0.z*H0.z + W0.w*H0.w
                    + W1.x*H1.x + W1.y*H1.y + W1.z*H1.z + W1.w*H1.w
                    + W2.x*H2.x + W2.y*H2.y + W2.z*H2.z + W2.w*H2.w
                    + W3.x*H3.x + W3.y*H3.y + W3.z*H3.z + W3.w*H3.w;
            }
            acc = gred8(acc);
            if (q == 0) gate_sm[r] = acc + g_xpre[dir][t][b][r];
        }
        __syncthreads();
        if (tid < Hn) {
            float gi = gate_sm[tid], gf = gate_sm[tid + 128];
            float gg = gate_sm[tid + 256], go = gate_sm[tid + 384];
            float c = sigf(gf) * c_sm[tid] + sigf(gi) * tanhf(gg);
            float h = sigf(go) * tanhf(c);
            c_sm[tid] = c; h_sm[tid] = h;
            int j = dir * Hn + tid;
            g_hs[t][b][j] = h;
            g_hsT[b][j][t] = h;
        }
        __syncthreads();
    }
}

// ---------------- cluster-pair persistent decoder, smem-resident bf16 constants ------
__global__ void __launch_bounds__(512, 1) __cluster_dims__(2, 1, 1)
decoder_persist(const float* __restrict__ mask, const float* __restrict__ va,
                const float* __restrict__ ua,
                const float* __restrict__ bih, const float* __restrict__ bhh)
{
    extern __shared__ __align__(16) __nv_bfloat16 dyn[];
    __nv_bfloat16* wc   = dyn;                                   // [128][WC_STRIDE]
    __nv_bfloat16* wa   = dyn + 128 * WC_STRIDE;                 // [256][WA_STRIDE]
    __nv_bfloat16* vasm = dyn + 128 * WC_STRIDE + 256 * WA_STRIDE; // [128][VA_STRIDE]

    __shared__ __align__(16) float s_sm[2][Hn];
    __shared__ __align__(16) float y_sm[64];
    __shared__ __align__(16) float vas_sm[Hn];
    __shared__ __align__(16) float u_sm[Hn];
    __shared__ __align__(16) float e_sm[256];
    __shared__ __align__(16) float ctxp_sm[2*Hn];
    __shared__ __align__(16) float xin_sm[384];
    __shared__ __align__(16) float mask_sm[256];
    __shared__ __align__(16) float bias_sm[256];
    __shared__ __align__(16) float gates_sm[256];
    __shared__ __align__(16) float xch_ctx[2][2*Hn];
    __shared__ __align__(16) float xch_s[2];
    __shared__ float red[16];
    __shared__ float S_loc[2];

    uint32_t rank;
    asm("mov.u32 %0, %%cluster_ctarank;" : "=r"(rank));
    int h = (int)rank;
    int b = blockIdx.x >> 1;
    int tid = threadIdx.x;
    int w = tid >> 5, l = tid & 31;
    int g = tid >> 3, q = tid & 7;

    uint32_t peer_xctx = mapa_peer(smem_u32(&xch_ctx[0][0]), rank ^ 1);
    uint32_t peer_xs   = mapa_peer(smem_u32(&xch_s[0]),      rank ^ 1);
    uint32_t peer_s    = mapa_peer(smem_u32(&s_sm[0][0]),    rank ^ 1);

    // one-time smem fills
    for (int idx = tid; idx < 128 * 384; idx += 512) {
        int lr = idx / 384, c = idx - lr * 384;
        int r = (lr >> 6) * 128 + h * 64 + (lr & 63);
        wc[lr * WC_STRIDE + c] = g_Wbf[r][c];
    }
    for (int idx = tid; idx < 256 * 128; idx += 512) {
        int sl = idx >> 7, c = idx & 127;
        wa[sl * WA_STRIDE + c] = g_wahsT_bf[b][h * 256 + sl][c];
    }
    for (int idx = tid; idx < 128 * 128; idx += 512) {
        int r = idx >> 7, c = idx & 127;
        vasm[r * VA_STRIDE + c] = __float2bfloat16(va[idx]);
    }
    if (tid < 256) {
        int r = (tid >> 6) * 128 + h * 64 + (tid & 63);
        bias_sm[tid] = bih[r] + bhh[r];
        mask_sm[tid] = mask[(h * 256 + tid) * Bn + b];
    }
    if (tid < Hn) { u_sm[tid] = ua[tid]; s_sm[0][tid] = 0.f; }
    if (tid < 64) y_sm[tid] = 0.f;
    __syncthreads();

    const float4* hsT4 = reinterpret_cast<const float4*>(&g_hsT[0][0][0]);
    const float4* u4   = reinterpret_cast<const float4*>(u_sm);
    const float4* vas4 = reinterpret_cast<const float4*>(vas_sm);
    const float4* e4p  = reinterpret_cast<const float4*>(e_sm);
    const float4* xin4 = reinterpret_cast<const float4*>(xin_sm);

    for (int t = 0; t < Tn; t++) {
        int par = t & 1;
        const float4* s4 = reinterpret_cast<const float4*>(&s_sm[par][0]);

        // ---- vas: 2 rows per group, va from bf16 smem ----
        {
            float4 S0 = s4[2*q], S1 = s4[2*q+1], S2 = s4[2*q+16], S3 = s4[2*q+17];
#pragma unroll
            for (int p = 0; p < 2; p++) {
                int j = p * 64 + g;
                const uint4* wr = reinterpret_cast<const uint4*>(vasm + j * VA_STRIDE);
                float acc = dot8(wr[q], S0, S1) + dot8(wr[q + 8], S2, S3);
                acc = gred8(acc);
                if (q == 0) vas_sm[j] = acc;
            }
        }
        __syncthreads();                                        // sync 1

        // ---- scores + exp + warp sums, wahs from bf16 smem ----
        {
            float4 V0 = vas4[2*q], V1 = vas4[2*q+1], V2 = vas4[2*q+16], V3 = vas4[2*q+17];
            float4 U0 = u4[2*q],   U1 = u4[2*q+1],   U2 = u4[2*q+16],   U3 = u4[2*q+17];
            float stacc = 0.f;
#pragma unroll
            for (int p = 0; p < 4; p++) {
                int sl = p * 64 + g;
                const uint4* ar = reinterpret_cast<const uint4*>(wa + sl * WA_STRIDE);
                float acc = tdot8(ar[q], V0, V1, U0, U1) + tdot8(ar[q + 8], V2, V3, U2, U3);
                acc = gred8(acc);
                float ex = __expf(acc * mask_sm[sl]);
                if (q == 0) e_sm[sl] = ex;
                stacc += ex;
            }
            stacc += __shfl_xor_sync(0xFFFFFFFFu, stacc, 8);
            stacc += __shfl_xor_sync(0xFFFFFFFFu, stacc, 16);
            if (l == 0) red[w] = stacc;
        }
        __syncthreads();                                        // sync 2

        // ---- partial ctx (hsT fp32 from L2; alpha frags preloaded) ----
        if (tid == 0) {
            float ss = red[0];
#pragma unroll
            for (int i = 1; i < 16; i++) ss += red[i];
            S_loc[par] = ss;
        }
        {
            float4 Af[8];
#pragma unroll
            for (int k = 0; k < 8; k++) Af[k] = e4p[q + k * 8];
#pragma unroll
            for (int p = 0; p < 4; p++) {
                int j = p * 64 + g;
                const float4* hp = &hsT4[(b * 2 * Hn + j) * 128 + h * 64];
                float acc = 0.f;
#pragma unroll
                for (int k = 0; k < 8; k++) {
                    float4 H = __ldg(&hp[q + k * 8]);
                    acc += H.x * Af[k].x + H.y * Af[k].y + H.z * Af[k].z + H.w * Af[k].w;
                }
                acc = gred8(acc);
                if (q == 0) ctxp_sm[j] = acc;
            }
        }
        __syncthreads();                                        // sync 3

        // ---- exchange ----
        if (tid < 256) st_remote_f32(peer_xctx + (par * 256 + tid) * 4, ctxp_sm[tid]);
        if (tid == 0)  st_remote_f32(peer_xs + par * 4, S_loc[par]);
        cluster_barrier();                                      // cluster 1

        // ---- xin ----
        if (tid < 128) xin_sm[tid] = s_sm[par][tid];
        else if (tid < 384) {
            int j = tid - 128;
            float inv = 1.f / (S_loc[par] + xch_s[par]);
            xin_sm[tid] = (ctxp_sm[j] + xch_ctx[par][j]) * inv;
        }
        __syncthreads();                                        // sync 4
        if (t == Tn - 1 && h == 0 && tid < 256) g_ctx[b][tid] = xin_sm[128 + tid];

        // ---- gates: i,f from smem bf16; g,o streamed bf16 from L2 ----
        {
            float4 X[12];
#pragma unroll
            for (int o2 = 0; o2 < 6; o2++) {
                X[2*o2]   = xin4[2 * (q + 8 * o2)];
                X[2*o2+1] = xin4[2 * (q + 8 * o2) + 1];
            }
#pragma unroll
            for (int p = 0; p < 4; p++) {
                int lr = p * 64 + g;
                float acc = 0.f;
                if (p < 2) {
                    const uint4* wr = reinterpret_cast<const uint4*>(wc + lr * WC_STRIDE);
#pragma unroll
                    for (int o2 = 0; o2 < 6; o2++)
                        acc += dot8(wr[q + 8 * o2], X[2*o2], X[2*o2+1]);
                } else {
                    int r = p * 128 + h * 64 + g;
                    const uint4* wr = reinterpret_cast<const uint4*>(&g_Wbf[r][0]);
#pragma unroll
                    for (int o2 = 0; o2 < 6; o2++)
                        acc += dot8(__ldg(&wr[q + 8 * o2]), X[2*o2], X[2*o2+1]);
                }
                acc = gred8(acc);
                if (q == 0) gates_sm[lr] = acc + bias_sm[lr];
            }
        }
        __syncthreads();                                        // sync 5

        // ---- cell; publish s-half ----
        if (tid < 64) {
            float gi = gates_sm[tid],       gf = gates_sm[64 + tid];
            float gg = gates_sm[128 + tid], go = gates_sm[192 + tid];
            float y = sigf(gf) * y_sm[tid] + sigf(gi) * tanhf(gg);
            float s = sigf(go) * tanhf(y);
            y_sm[tid] = y;
            int jg = h * 64 + tid;
            s_sm[par ^ 1][jg] = s;
            st_remote_f32(peer_s + ((par ^ 1) * 128 + jg) * 4, s);
            if (t == Tn - 1) g_sfin[b][jg] = s;
        }
        cluster_barrier();                                      // cluster 2
    }
}

// ---------------- final softmax over C=32000 -----------------------------------------
__global__ void softmax_stat(const float* __restrict__ out)
{
    int b = blockIdx.x, tid = threadIdx.x;
    __shared__ float red[256];
    const float* row = out + b * Cv;
    float m = -1e30f;
    for (int i = tid; i < Cv; i += 256) m = fmaxf(m, row[i]);
    red[tid] = m; __syncthreads();
#pragma unroll
    for (int st = 128; st; st >>= 1) {
        if (tid < st) red[tid] = fmaxf(red[tid], red[tid + st]);
        __syncthreads();
    }
    m = red[0]; __syncthreads();
    float s = 0.f;
    for (int i = tid; i < Cv; i += 256) s += __expf(row[i] - m);
    red[tid] = s; __syncthreads();
#pragma unroll
    for (int st = 128; st; st >>= 1) {
        if (tid < st) red[tid] += red[tid + st];
        __syncthreads();
    }
    if (tid == 0) { g_rowstat[b][0] = m; g_rowstat[b][1] = 1.f / red[0]; }
}

__global__ void softmax_norm(float* out)
{
    int b = blockIdx.y;
    int i = blockIdx.x * 256 + threadIdx.x;
    float* row = out + b * Cv;
    row[i] = __expf(row[i] - g_rowstat[b][0]) * g_rowstat[b][1];
}

// ---------------- launch -------------------------------------------------------------
extern "C" void kernel_launch(void* const* d_in, const int* in_sizes, int n_in,
                              void* d_out, int out_size)
{
    (void)in_sizes; (void)n_in; (void)out_size;
    const float* x      = (const float*)d_in[0];
    const float* mask   = (const float*)d_in[1];
    const float* eWih_f = (const float*)d_in[2];
    const float* eWhh_f = (const float*)d_in[3];
    const float* ebih_f = (const float*)d_in[4];
    const float* ebhh_f = (const float*)d_in[5];
    const float* eWih_b = (const float*)d_in[6];
    const float* eWhh_b = (const float*)d_in[7];
    const float* ebih_b = (const float*)d_in[8];
    const float* ebhh_b = (const float*)d_in[9];
    const float* dWih   = (const float*)d_in[10];
    const float* dWhh   = (const float*)d_in[11];
    const float* dbih   = (const float*)d_in[12];
    const float* dbhh   = (const float*)d_in[13];
    const float* w_a    = (const float*)d_in[14];
    const float* v_a    = (const float*)d_in[15];
    const float* u_a    = (const float*)d_in[16];
    const float* w_b    = (const float*)d_in[17];
    const float* v_b    = (const float*)d_in[18];
    float* out = (float*)d_out;

    float *p_xpre, *p_hs, *p_sfin, *p_ctx;
    cudaGetSymbolAddress((void**)&p_xpre, g_xpre);
    cudaGetSymbolAddress((void**)&p_hs,   g_hs);
    cudaGetSymbolAddress((void**)&p_sfin, g_sfin);
    cudaGetSymbolAddress((void**)&p_ctx,  g_ctx);

    cudaFuncSetAttribute(encoder_rec, cudaFuncAttributeMaxDynamicSharedMemorySize, ENC_CACHED * 132 * 4);
    cudaFuncSetAttribute(decoder_persist, cudaFuncAttributeMaxDynamicSharedMemorySize, DEC_DYN_SMEM);

    // 0) bf16 weight prep (independent)
    prep_bf16<<<768, 256>>>(dWih, dWhh);

    // 1) xpre = x @ Wih^T + biases
    sgemm_xpre<<<dim3(G4H / 128, Sn * Bn / 128, 2), 256>>>(
        x, eWih_f, eWih_b, ebih_f, ebhh_f, ebih_b, ebhh_b, p_xpre);

    // 2) encoder recurrence
    encoder_rec<<<dim3(Bn, 2), 512, ENC_CACHED * 132 * 4>>>(eWhh_f, eWhh_b);

    // 3) wa_hs -> bf16 transposed
    sgemm_wahsT<<<dim3(1, Sn * Bn / 128), 256>>>(p_hs, w_a);

    // 4) cluster-pair decoder, smem-resident bf16 constants
    decoder_persist<<<2 * Bn, 512, DEC_DYN_SMEM>>>(mask, v_a, u_a, dbih, dbhh);

    // 5) logits + softmax
    gemm_logits<<<dim3(Cv / 64, 1), 256>>>(p_sfin, w_b, p_ctx, v_b, out);
    softmax_stat<<<Bn, 256>>>(out);
    softmax_norm<<<dim3(Cv / 256, Bn), 256>>>(out);
}